// round 11
// baseline (speedup 1.0000x reference)
#include <cuda_runtime.h>
#include <cuda_fp16.h>
#include <math.h>
#include <stdint.h>

#define N_NODES 50000
#define N_EDGES 800000

// ---------------- scratch (device globals; no dynamic allocation) -------------
__device__ __half g_hh[(size_t)N_NODES * 726];
__device__ float  g_res[(size_t)N_NODES * 512];
__device__ float  g_xb [(size_t)N_NODES * 512];
__device__ __half g_x16 [(size_t)N_NODES * 128];
__device__ __half g_b16 [(size_t)N_NODES * 512];
__device__ __half g_a216[(size_t)N_NODES * 512];
__device__ __half g_w16[851968];
__device__ float  g_esd[(size_t)N_NODES * 12];   // interleaved es/ed per node
__device__ __half g_ws1[128 * 64];               // composed score weights
__device__ __half g_ws2[512 * 64];
__device__ __half g_ws3[512 * 64];
__device__ float  g_w[(size_t)N_EDGES * 6];
__device__ int   g_cnt[N_NODES + 1];
__device__ int   g_off[N_NODES + 1];
__device__ int   g_cur[N_NODES];
__device__ int   g_csr[N_EDGES];

#define W1_OFF 0
#define R1_OFF 65536
#define W2_OFF 131072
#define W3_OFF 393216
#define R3_OFF 786432

// ------------------------- fp32 -> fp16 conversion ----------------------------
__global__ void k_cvt(const float* __restrict__ x,  const float* __restrict__ W1,
                      const float* __restrict__ R1, const float* __restrict__ W2,
                      const float* __restrict__ W3, const float* __restrict__ R3) {
    size_t i = (size_t)blockIdx.x * blockDim.x + threadIdx.x;
    const size_t NX = (size_t)N_NODES * 128;
    if (i < NX) { g_x16[i] = __float2half_rn(x[i]); return; }
    size_t j = i - NX;
    if (j < 65536) { g_w16[W1_OFF + j] = __float2half_rn(W1[j]); return; }
    j -= 65536;
    if (j < 65536) { g_w16[R1_OFF + j] = __float2half_rn(R1[j]); return; }
    j -= 65536;
    if (j < 262144) { g_w16[W2_OFF + j] = __float2half_rn(W2[j]); return; }
    j -= 262144;
    if (j < 393216) {
        int r = (int)(j / 768), c = (int)(j % 768);
        g_w16[W3_OFF + j] = (c < 726) ? __float2half_rn(W3[r * 726 + c]) : __float2half_rn(0.f);
        return;
    }
    j -= 393216;
    if (j < 65536) {
        int r = (int)(j >> 7), c = (int)(j & 127);
        g_w16[R3_OFF + j] = (c < 121) ? __float2half_rn(R3[r * 121 + c]) : __float2half_rn(0.f);
    }
}
#define CVT_TOTAL ((size_t)N_NODES * 128 + 851968)

// --------------- compose attention vectors into score weights -----------------
__global__ void k_combine(const float* __restrict__ W1, const float* __restrict__ a1s,
                          const float* __restrict__ a1d,
                          const float* __restrict__ W2, const float* __restrict__ a2s,
                          const float* __restrict__ a2d,
                          const float* __restrict__ W3, const float* __restrict__ a3s,
                          const float* __restrict__ a3d) {
    int gid = blockIdx.x * blockDim.x + threadIdx.x;
    if (gid < 128 * 64) {
        int k = gid >> 6, col = gid & 63, h = col >> 1;
        float v = 0.f;
        if (col < 8) {
            const float* a = (col & 1) ? a1d : a1s;
            for (int u = 0; u < 128; u++) v += W1[k * 512 + h * 128 + u] * a[h * 128 + u];
        }
        g_ws1[k * 64 + col] = __float2half_rn(v);
        return;
    }
    gid -= 128 * 64;
    if (gid < 512 * 64) {
        int k = gid >> 6, col = gid & 63, h = col >> 1;
        float v = 0.f;
        if (col < 8) {
            const float* a = (col & 1) ? a2d : a2s;
            for (int u = 0; u < 128; u++) v += W2[k * 512 + h * 128 + u] * a[h * 128 + u];
        }
        g_ws2[k * 64 + col] = __float2half_rn(v);
        return;
    }
    gid -= 512 * 64;
    if (gid < 512 * 64) {
        int k = gid >> 6, col = gid & 63, h = col >> 1;
        float v = 0.f;
        if (col < 12) {
            const float* a = (col & 1) ? a3d : a3s;
            for (int u = 0; u < 121; u++) v += W3[k * 726 + h * 121 + u] * a[h * 121 + u];
        }
        g_ws3[k * 64 + col] = __float2half_rn(v);
    }
}
#define COMBINE_TOTAL (128 * 64 + 512 * 64 + 512 * 64)

// ------------------------------- CSR build -----------------------------------
__global__ void k_zero_cnt() {
    int i = blockIdx.x * blockDim.x + threadIdx.x;
    if (i <= N_NODES) g_cnt[i] = 0;
}
__global__ void k_count(const int* __restrict__ edges) {
    int e = blockIdx.x * blockDim.x + threadIdx.x;
    if (e < N_EDGES) atomicAdd(&g_cnt[edges[2 * e + 1]], 1);
}
__global__ void k_scan() {
    __shared__ int sh[1024];
    __shared__ int carry_s;
    int tid = threadIdx.x;
    if (tid == 0) { carry_s = 0; g_off[0] = 0; g_cur[0] = 0; }
    __syncthreads();
    for (int base = 0; base < N_NODES; base += 1024) {
        int i = base + tid;
        int v = (i < N_NODES) ? g_cnt[i] : 0;
        sh[tid] = v;
        __syncthreads();
        for (int d = 1; d < 1024; d <<= 1) {
            int t = (tid >= d) ? sh[tid - d] : 0;
            __syncthreads();
            sh[tid] += t;
            __syncthreads();
        }
        if (i < N_NODES) {
            int val = carry_s + sh[tid];
            g_off[i + 1] = val;
            if (i + 1 < N_NODES) g_cur[i + 1] = val;
        }
        __syncthreads();
        if (tid == 0) carry_s += sh[1023];
        __syncthreads();
    }
}
__global__ void k_scatter(const int* __restrict__ edges) {
    int e = blockIdx.x * blockDim.x + threadIdx.x;
    if (e < N_EDGES) {
        int dst = edges[2 * e + 1];
        int p = atomicAdd(&g_cur[dst], 1);
        g_csr[p] = edges[2 * e];
    }
}

// ------------------------------ FP16 TC GEMM, BK=64 ---------------------------
// C[M,N] = A[M,K]@B[K,N]; BM=128, BN=64, BK=64; 8 warps 4x2, warp tile 32x32.
// A tile rows are 128B (ch^=row&7 swizzle); double buffered dynamic smem 48KB.
#define BM 128
#define BN 64
#define BK 64
#define A_TILE_HALFS (BM * BK)   // 8192 halves = 16KB
#define B_TILE_HALFS (BK * BN)   // 4096 halves = 8KB
#define GEMM_SMEM_BYTES ((2 * A_TILE_HALFS + 2 * B_TILE_HALFS) * 2)  // 49152

__device__ __forceinline__ void cph16(uint32_t s, const void* g, bool p) {
    asm volatile("cp.async.cg.shared.global [%0], [%1], 16, %2;" ::"r"(s), "l"(g), "r"(p ? 16 : 0));
}
__device__ __forceinline__ void cp_commit() { asm volatile("cp.async.commit_group;"); }
__device__ __forceinline__ void ldmA(uint32_t a[4], uint32_t addr) {
    asm volatile("ldmatrix.sync.aligned.m8n8.x4.shared.b16 {%0,%1,%2,%3}, [%4];"
                 : "=r"(a[0]), "=r"(a[1]), "=r"(a[2]), "=r"(a[3]) : "r"(addr));
}
__device__ __forceinline__ void ldmBT(uint32_t b[4], uint32_t addr) {
    asm volatile("ldmatrix.sync.aligned.m8n8.x4.trans.shared.b16 {%0,%1,%2,%3}, [%4];"
                 : "=r"(b[0]), "=r"(b[1]), "=r"(b[2]), "=r"(b[3]) : "r"(addr));
}
__device__ __forceinline__ void mma16816(float c[4], const uint32_t a[4], uint32_t b0, uint32_t b1) {
    asm volatile("mma.sync.aligned.m16n8k16.row.col.f32.f16.f16.f32 "
                 "{%0,%1,%2,%3}, {%4,%5,%6,%7}, {%8,%9}, {%0,%1,%2,%3};"
                 : "+f"(c[0]), "+f"(c[1]), "+f"(c[2]), "+f"(c[3])
                 : "r"(a[0]), "r"(a[1]), "r"(a[2]), "r"(a[3]), "r"(b0), "r"(b1));
}

template <bool HALF_OUT>
__global__ __launch_bounds__(256, 4) void k_gemm_h(const __half* __restrict__ A,
                                                   const __half* __restrict__ B,
                                                   void* __restrict__ Cout,
                                                   int M, int N, int Np, int K) {
    extern __shared__ __align__(16) __half smem[];
    __half* As = smem;                       // 2 buffers of [128][64]
    __half* Bs = smem + 2 * A_TILE_HALFS;    // 2 buffers of [64][64]
    const int tid = threadIdx.x, lane = tid & 31, wid = tid >> 5;
    const int wm = wid & 3, wn = wid >> 2;
    const int g = lane >> 2, c = lane & 3;
    const int mBase = blockIdx.y * BM, nBase = blockIdx.x * BN;
    const uint32_t sA = (uint32_t)__cvta_generic_to_shared(As);
    const uint32_t sB = (uint32_t)__cvta_generic_to_shared(Bs);

    float acc[2][4][4];
    #pragma unroll
    for (int mt = 0; mt < 2; mt++)
        #pragma unroll
        for (int nt = 0; nt < 4; nt++)
            #pragma unroll
            for (int i = 0; i < 4; i++) acc[mt][nt][i] = 0.f;

    // loaders: rows are 128B = 8 chunks of 16B; swizzle ch ^= (row & 7)
    const int ar = tid >> 3, ac = tid & 7;   // A: rows ar, ar+32, ar+64, ar+96
    const int br = tid >> 3, bc = tid & 7;   // B: rows br, br+32

    auto loadTile = [&](int k0, int buf) {
        uint32_t aB = sA + (uint32_t)(buf * A_TILE_HALFS * 2);
        #pragma unroll
        for (int rr = 0; rr < 4; rr++) {
            int row = ar + rr * 32;
            int gm = mBase + row;
            int sw = ac ^ (row & 7);
            cph16(aB + (uint32_t)(row * 128 + sw * 16),
                  A + (size_t)gm * K + k0 + ac * 8, gm < M);
        }
        uint32_t bB = sB + (uint32_t)(buf * B_TILE_HALFS * 2);
        #pragma unroll
        for (int rr = 0; rr < 2; rr++) {
            int row = br + rr * 32;
            int sw = bc ^ (row & 7);
            cph16(bB + (uint32_t)(row * 128 + sw * 16),
                  B + (size_t)(k0 + row) * Np + nBase + bc * 8, true);
        }
    };

    // ldmatrix byte offsets for kk = 0..3
    uint32_t aoff[2][4], boff[2][4];
    #pragma unroll
    for (int mt = 0; mt < 2; mt++)
        #pragma unroll
        for (int kk = 0; kk < 4; kk++) {
            int row = wm * 32 + mt * 16 + (lane & 15);
            int ch = kk * 2 + (lane >> 4);
            int sw = ch ^ (row & 7);
            aoff[mt][kk] = (uint32_t)(row * 128 + sw * 16);
        }
    #pragma unroll
    for (int ng = 0; ng < 2; ng++)
        #pragma unroll
        for (int kk = 0; kk < 4; kk++) {
            int row = kk * 16 + (lane & 15);
            int ch = wn * 4 + ng * 2 + (lane >> 4);
            int sw = ch ^ (row & 7);
            boff[ng][kk] = (uint32_t)(row * 128 + sw * 16);
        }

    const int ntiles = K / BK;
    loadTile(0, 0);
    cp_commit();

    for (int t = 0; t < ntiles; t++) {
        int buf = t & 1;
        if (t + 1 < ntiles) {
            loadTile((t + 1) * BK, (t + 1) & 1);
            cp_commit();
            asm volatile("cp.async.wait_group 1;");
        } else {
            asm volatile("cp.async.wait_group 0;");
        }
        __syncthreads();

        uint32_t aB = sA + (uint32_t)(buf * A_TILE_HALFS * 2);
        uint32_t bB = sB + (uint32_t)(buf * B_TILE_HALFS * 2);
        #pragma unroll
        for (int kk = 0; kk < 4; kk++) {
            uint32_t a0[4], a1[4], b0[4], b1[4];
            ldmA(a0, aB + aoff[0][kk]);
            ldmA(a1, aB + aoff[1][kk]);
            ldmBT(b0, bB + boff[0][kk]);
            ldmBT(b1, bB + boff[1][kk]);
            mma16816(acc[0][0], a0, b0[0], b0[1]);
            mma16816(acc[0][1], a0, b0[2], b0[3]);
            mma16816(acc[0][2], a0, b1[0], b1[1]);
            mma16816(acc[0][3], a0, b1[2], b1[3]);
            mma16816(acc[1][0], a1, b0[0], b0[1]);
            mma16816(acc[1][1], a1, b0[2], b0[3]);
            mma16816(acc[1][2], a1, b1[0], b1[1]);
            mma16816(acc[1][3], a1, b1[2], b1[3]);
        }
        __syncthreads();
    }

    #pragma unroll
    for (int mt = 0; mt < 2; mt++) {
        int r0 = mBase + wm * 32 + mt * 16 + g;
        int r1 = r0 + 8;
        #pragma unroll
        for (int nt = 0; nt < 4; nt++) {
            int col = nBase + wn * 32 + nt * 8 + 2 * c;
            if (HALF_OUT) {
                __half2* C2 = (__half2*)Cout;
                if (r0 < M && col < N)
                    C2[((size_t)r0 * N + col) >> 1] = __floats2half2_rn(acc[mt][nt][0], acc[mt][nt][1]);
                if (r1 < M && col < N)
                    C2[((size_t)r1 * N + col) >> 1] = __floats2half2_rn(acc[mt][nt][2], acc[mt][nt][3]);
            } else {
                float* C = (float*)Cout;
                if (r0 < M) {
                    if (col < N)     C[(size_t)r0 * N + col]     = acc[mt][nt][0];
                    if (col + 1 < N) C[(size_t)r0 * N + col + 1] = acc[mt][nt][1];
                }
                if (r1 < M) {
                    if (col < N)     C[(size_t)r1 * N + col]     = acc[mt][nt][2];
                    if (col + 1 < N) C[(size_t)r1 * N + col + 1] = acc[mt][nt][3];
                }
            }
        }
    }
}

// --------------- softmax weights: all heads, one gather (R8-proven) ------------
#define WCAP 512
template <int H>
__global__ __launch_bounds__(128) void k_weights(const float* __restrict__ esd) {
    __shared__ int   sidx[WCAP];
    __shared__ float se[H][WCAP];
    __shared__ float red[4 * H];
    __shared__ float s_mh[H], s_inv[H];
    int n = blockIdx.x;
    int tid = threadIdx.x;
    int lane = tid & 31, wid = tid >> 5;
    int beg = g_off[n], deg = g_off[n + 1] - beg;
    if (deg == 0) return;
    const float4* e4 = (const float4*)esd;

    float edv[H];
    #pragma unroll
    for (int q = 0; q < H / 2; q++) {
        float4 d = e4[n * (H / 2) + q];
        edv[2 * q] = d.y; edv[2 * q + 1] = d.w;
    }

    if (deg <= WCAP) {
        float mx[H];
        #pragma unroll
        for (int hh = 0; hh < H; hh++) mx[hh] = -1e30f;
        for (int i = tid; i < deg; i += 128) {
            int s = g_csr[beg + i];
            sidx[i] = s;
            float ev[H];
            #pragma unroll
            for (int q = 0; q < H / 2; q++) {
                float4 v = e4[s * (H / 2) + q];
                ev[2 * q] = v.x; ev[2 * q + 1] = v.z;
            }
            #pragma unroll
            for (int hh = 0; hh < H; hh++) {
                float e = ev[hh] + edv[hh];
                e = (e > 0.f) ? e : 0.2f * e;
                se[hh][i] = e;
                mx[hh] = fmaxf(mx[hh], e);
            }
        }
        #pragma unroll
        for (int hh = 0; hh < H; hh++) {
            #pragma unroll
            for (int o = 16; o > 0; o >>= 1)
                mx[hh] = fmaxf(mx[hh], __shfl_xor_sync(0xffffffffu, mx[hh], o));
        }
        if (lane == 0)
            #pragma unroll
            for (int hh = 0; hh < H; hh++) red[wid * H + hh] = mx[hh];
        __syncthreads();
        if (tid < H)
            s_mh[tid] = fmaxf(fmaxf(red[tid], red[H + tid]),
                              fmaxf(red[2 * H + tid], red[3 * H + tid]));
        __syncthreads();
        float m[H], sum[H];
        #pragma unroll
        for (int hh = 0; hh < H; hh++) { m[hh] = s_mh[hh]; sum[hh] = 0.f; }
        for (int i = tid; i < deg; i += 128) {
            #pragma unroll
            for (int hh = 0; hh < H; hh++) {
                float p = expf(se[hh][i] - m[hh]);
                se[hh][i] = p;
                sum[hh] += p;
            }
        }
        #pragma unroll
        for (int hh = 0; hh < H; hh++) {
            #pragma unroll
            for (int o = 16; o > 0; o >>= 1)
                sum[hh] += __shfl_xor_sync(0xffffffffu, sum[hh], o);
        }
        if (lane == 0)
            #pragma unroll
            for (int hh = 0; hh < H; hh++) red[wid * H + hh] = sum[hh];
        __syncthreads();
        if (tid < H)
            s_inv[tid] = 1.0f / fmaxf(red[tid] + red[H + tid] + red[2 * H + tid] + red[3 * H + tid], 1e-9f);
        __syncthreads();
        float inv[H];
        #pragma unroll
        for (int hh = 0; hh < H; hh++) inv[hh] = s_inv[hh];
        for (int i = tid; i < deg; i += 128) {
            if (H == 4) {
                float4 w;
                w.x = se[0][i] * inv[0]; w.y = se[1][i] * inv[1];
                w.z = se[2][i] * inv[2]; w.w = se[3][i] * inv[3];
                *(float4*)(&g_w[(size_t)(beg + i) * 4]) = w;
            } else {
                #pragma unroll
                for (int q = 0; q < H / 2; q++) {
                    float2 w;
                    w.x = se[2 * q][i] * inv[2 * q];
                    w.y = se[2 * q + 1][i] * inv[2 * q + 1];
                    *(float2*)(&g_w[(size_t)(beg + i) * H + 2 * q]) = w;
                }
            }
        }
    } else {
        __shared__ float warpred[4];
        __shared__ float s_m1, s_i1;
        for (int hh = 0; hh < H; hh++) {
            float ev = edv[hh];
            float mxx = -1e30f;
            for (int i = tid; i < deg; i += 128) {
                float e = esd[g_csr[beg + i] * 2 * H + 2 * hh] + ev;
                e = (e > 0.f) ? e : 0.2f * e;
                mxx = fmaxf(mxx, e);
            }
            #pragma unroll
            for (int o = 16; o > 0; o >>= 1) mxx = fmaxf(mxx, __shfl_xor_sync(0xffffffffu, mxx, o));
            if (lane == 0) warpred[wid] = mxx;
            __syncthreads();
            if (tid == 0)
                s_m1 = fmaxf(fmaxf(warpred[0], warpred[1]), fmaxf(warpred[2], warpred[3]));
            __syncthreads();
            float m = s_m1;
            float sum = 0.f;
            for (int i = tid; i < deg; i += 128) {
                float e = esd[g_csr[beg + i] * 2 * H + 2 * hh] + ev;
                e = (e > 0.f) ? e : 0.2f * e;
                sum += expf(e - m);
            }
            #pragma unroll
            for (int o = 16; o > 0; o >>= 1) sum += __shfl_xor_sync(0xffffffffu, sum, o);
            if (lane == 0) warpred[wid] = sum;
            __syncthreads();
            if (tid == 0)
                s_i1 = 1.0f / fmaxf(warpred[0] + warpred[1] + warpred[2] + warpred[3], 1e-9f);
            __syncthreads();
            float inv = s_i1;
            for (int i = tid; i < deg; i += 128) {
                float e = esd[g_csr[beg + i] * 2 * H + 2 * hh] + ev;
                e = (e > 0.f) ? e : 0.2f * e;
                g_w[(size_t)(beg + i) * H + hh] = expf(e - m) * inv;
            }
            __syncthreads();
        }
    }
}

// ---------------- weighted aggregation, layers 1/2 (R8-proven) ----------------
__global__ __launch_bounds__(256) void k_agg512(const __half* __restrict__ h,
                                                const float* __restrict__ res,
                                                float* __restrict__ outf,
                                                __half* __restrict__ out16) {
    int n = blockIdx.x;
    int tid = threadIdx.x;
    int hh = tid >> 6;
    int beg = g_off[n], deg = g_off[n + 1] - beg;
    const __half2* h2 = (const __half2*)h;
    float ax = 0.f, ay = 0.f;
    int i = 0;
    for (; i + 4 <= deg; i += 4) {
        int s0 = g_csr[beg + i],     s1 = g_csr[beg + i + 1];
        int s2 = g_csr[beg + i + 2], s3 = g_csr[beg + i + 3];
        float w0 = g_w[(size_t)(beg + i) * 4 + hh];
        float w1 = g_w[(size_t)(beg + i + 1) * 4 + hh];
        float w2 = g_w[(size_t)(beg + i + 2) * 4 + hh];
        float w3 = g_w[(size_t)(beg + i + 3) * 4 + hh];
        float2 v0 = __half22float2(__ldg(h2 + (size_t)s0 * 256 + tid));
        float2 v1 = __half22float2(__ldg(h2 + (size_t)s1 * 256 + tid));
        float2 v2 = __half22float2(__ldg(h2 + (size_t)s2 * 256 + tid));
        float2 v3 = __half22float2(__ldg(h2 + (size_t)s3 * 256 + tid));
        ax += w0 * v0.x + w1 * v1.x + w2 * v2.x + w3 * v3.x;
        ay += w0 * v0.y + w1 * v1.y + w2 * v2.y + w3 * v3.y;
    }
    for (; i < deg; i++) {
        int s = g_csr[beg + i];
        float w = g_w[(size_t)(beg + i) * 4 + hh];
        float2 v = __half22float2(__ldg(h2 + (size_t)s * 256 + tid));
        ax += w * v.x;
        ay += w * v.y;
    }
    float2 r = ((const float2*)res)[(size_t)n * 256 + tid];
    float vx = ax + r.x, vy = ay + r.y;
    vx = (vx > 0.f) ? vx : (expf(vx) - 1.f);
    vy = (vy > 0.f) ? vy : (expf(vy) - 1.f);
    if (outf) ((float2*)outf)[(size_t)n * 256 + tid] = make_float2(vx, vy);
    ((__half2*)out16)[(size_t)n * 256 + tid] = __floats2half2_rn(vx, vy);
}

// ---------------- weighted aggregation, layer 3 (R8-proven) -------------------
__global__ __launch_bounds__(384) void k_agg726(const __half* __restrict__ h,
                                                const float* __restrict__ res,
                                                float* __restrict__ out) {
    __shared__ float sh[726];
    int n = blockIdx.x;
    int tid = threadIdx.x;
    int beg = g_off[n], deg = g_off[n + 1] - beg;
    const __half2* h2 = (const __half2*)h;
    if (tid < 363) {
        int hA = (2 * tid) / 121;
        int hB = (2 * tid + 1) / 121;
        float ax = 0.f, ay = 0.f;
        int i = 0;
        for (; i + 4 <= deg; i += 4) {
            int s0 = g_csr[beg + i],     s1 = g_csr[beg + i + 1];
            int s2 = g_csr[beg + i + 2], s3 = g_csr[beg + i + 3];
            const float* wb0 = &g_w[(size_t)(beg + i) * 6];
            const float* wb1 = &g_w[(size_t)(beg + i + 1) * 6];
            const float* wb2 = &g_w[(size_t)(beg + i + 2) * 6];
            const float* wb3 = &g_w[(size_t)(beg + i + 3) * 6];
            float2 v0 = __half22float2(__ldg(h2 + (size_t)s0 * 363 + tid));
            float2 v1 = __half22float2(__ldg(h2 + (size_t)s1 * 363 + tid));
            float2 v2 = __half22float2(__ldg(h2 + (size_t)s2 * 363 + tid));
            float2 v3 = __half22float2(__ldg(h2 + (size_t)s3 * 363 + tid));
            ax += wb0[hA] * v0.x + wb1[hA] * v1.x + wb2[hA] * v2.x + wb3[hA] * v3.x;
            ay += wb0[hB] * v0.y + wb1[hB] * v1.y + wb2[hB] * v2.y + wb3[hB] * v3.y;
        }
        for (; i < deg; i++) {
            int s = g_csr[beg + i];
            const float* wb = &g_w[(size_t)(beg + i) * 6];
            float2 v = __half22float2(__ldg(h2 + (size_t)s * 363 + tid));
            ax += wb[hA] * v.x;
            ay += wb[hB] * v.y;
        }
        sh[2 * tid]     = ax;
        sh[2 * tid + 1] = ay;
    }
    __syncthreads();
    if (tid < 121) {
        float s = 0.f;
        #pragma unroll
        for (int hh = 0; hh < 6; hh++) s += sh[tid + hh * 121];
        out[(size_t)n * 121 + tid] = s * (1.f / 6.f) + res[(size_t)n * 121 + tid];
    }
}

// ------------------------------- launcher ------------------------------------
template <bool HALF_OUT>
static void launch_gemm(const __half* A, const __half* B, void* C, int M, int N, int Np, int K) {
    dim3 grid(Np / BN, (M + BM - 1) / BM);
    cudaFuncSetAttribute(k_gemm_h<HALF_OUT>, cudaFuncAttributeMaxDynamicSharedMemorySize, GEMM_SMEM_BYTES);
    k_gemm_h<HALF_OUT><<<grid, 256, GEMM_SMEM_BYTES>>>(A, B, C, M, N, Np, K);
}

extern "C" void kernel_launch(void* const* d_in, const int* in_sizes, int n_in,
                              void* d_out, int out_size) {
    const float* x    = (const float*)d_in[0];
    const int*   edges= (const int*)d_in[1];
    const float* W1   = (const float*)d_in[2];
    const float* a1s  = (const float*)d_in[3];
    const float* a1d  = (const float*)d_in[4];
    const float* R1   = (const float*)d_in[5];
    const float* W2   = (const float*)d_in[6];
    const float* a2s  = (const float*)d_in[7];
    const float* a2d  = (const float*)d_in[8];
    const float* W3   = (const float*)d_in[9];
    const float* a3s  = (const float*)d_in[10];
    const float* a3d  = (const float*)d_in[11];
    const float* R3   = (const float*)d_in[12];
    float* out = (float*)d_out;

    __half *hh, *x16, *b16, *a216, *w16, *ws1, *ws2, *ws3;
    float *res, *xb, *esd;
    cudaGetSymbolAddress((void**)&hh,   g_hh);
    cudaGetSymbolAddress((void**)&res,  g_res);
    cudaGetSymbolAddress((void**)&xb,   g_xb);
    cudaGetSymbolAddress((void**)&x16,  g_x16);
    cudaGetSymbolAddress((void**)&b16,  g_b16);
    cudaGetSymbolAddress((void**)&a216, g_a216);
    cudaGetSymbolAddress((void**)&w16,  g_w16);
    cudaGetSymbolAddress((void**)&ws1,  g_ws1);
    cudaGetSymbolAddress((void**)&ws2,  g_ws2);
    cudaGetSymbolAddress((void**)&ws3,  g_ws3);
    cudaGetSymbolAddress((void**)&esd,  g_esd);

    k_cvt<<<(int)((CVT_TOTAL + 255) / 256), 256>>>(x, W1, R1, W2, W3, R3);
    k_zero_cnt<<<(N_NODES + 256) / 256, 256>>>();
    k_count<<<(N_EDGES + 255) / 256, 256>>>(edges);
    launch_gemm<true >(x16, w16 + W1_OFF, hh, N_NODES, 512, 512, 128);   // profiled slot
    k_combine<<<(COMBINE_TOTAL + 255) / 256, 256>>>(W1, a1s, a1d, W2, a2s, a2d, W3, a3s, a3d);
    k_scan<<<1, 1024>>>();
    k_scatter<<<(N_EDGES + 255) / 256, 256>>>(edges);

    // ---- layer 1: H=4, U=128, concat, residual x@R1, ELU
    launch_gemm<false>(x16, w16 + R1_OFF, res, N_NODES, 512, 512, 128);
    launch_gemm<false>(x16, ws1, esd, N_NODES, 8, 64, 128);
    k_weights<4><<<N_NODES, 128>>>(esd);
    k_agg512<<<N_NODES, 256>>>(hh, res, xb, b16);

    // ---- layer 2: H=4, U=128, concat, residual = x1, ELU
    launch_gemm<true >(b16, w16 + W2_OFF, hh, N_NODES, 512, 512, 512);
    launch_gemm<false>(b16, ws2, esd, N_NODES, 8, 64, 512);
    k_weights<4><<<N_NODES, 128>>>(esd);
    k_agg512<<<N_NODES, 256>>>(hh, xb, nullptr, a216);

    // ---- layer 3: H=6, U=121, avg merge, residual x2@R3, identity
    launch_gemm<true >(a216, w16 + W3_OFF, hh, N_NODES, 726, 768, 512);
    launch_gemm<false>(a216, w16 + R3_OFF, res, N_NODES, 121, 128, 512);
    launch_gemm<false>(a216, ws3, esd, N_NODES, 12, 64, 512);
    k_weights<6><<<N_NODES, 128>>>(esd);
    k_agg726<<<N_NODES, 384>>>(hh, res, out);
}

// round 12
// speedup vs baseline: 1.4230x; 1.4230x over previous
#include <cuda_runtime.h>
#include <cuda_fp16.h>
#include <math.h>
#include <stdint.h>

#define N_NODES 50000
#define N_EDGES 800000

// ---------------- scratch (device globals; no dynamic allocation) -------------
__device__ __half g_hh[(size_t)N_NODES * 726];
__device__ float  g_res[(size_t)N_NODES * 512];
__device__ float  g_xb [(size_t)N_NODES * 512];
__device__ __half g_x16 [(size_t)N_NODES * 128];
__device__ __half g_b16 [(size_t)N_NODES * 512];
__device__ __half g_a216[(size_t)N_NODES * 512];
__device__ __half g_w16[851968];
__device__ float  g_esd[(size_t)N_NODES * 12];   // interleaved es/ed per node
__device__ __half g_ws1[128 * 64];               // composed score weights
__device__ __half g_ws2[512 * 64];
__device__ __half g_ws3[512 * 64];
__device__ float  g_w[(size_t)N_EDGES * 6];
__device__ int   g_cnt[N_NODES + 1];
__device__ int   g_off[N_NODES + 1];
__device__ int   g_cur[N_NODES];
__device__ int   g_csr[N_EDGES];

#define W1_OFF 0
#define R1_OFF 65536
#define W2_OFF 131072
#define W3_OFF 393216
#define R3_OFF 786432

// ------------------------- fp32 -> fp16 conversion ----------------------------
__global__ void k_cvt(const float* __restrict__ x,  const float* __restrict__ W1,
                      const float* __restrict__ R1, const float* __restrict__ W2,
                      const float* __restrict__ W3, const float* __restrict__ R3) {
    size_t i = (size_t)blockIdx.x * blockDim.x + threadIdx.x;
    const size_t NX = (size_t)N_NODES * 128;
    if (i < NX) { g_x16[i] = __float2half_rn(x[i]); return; }
    size_t j = i - NX;
    if (j < 65536) { g_w16[W1_OFF + j] = __float2half_rn(W1[j]); return; }
    j -= 65536;
    if (j < 65536) { g_w16[R1_OFF + j] = __float2half_rn(R1[j]); return; }
    j -= 65536;
    if (j < 262144) { g_w16[W2_OFF + j] = __float2half_rn(W2[j]); return; }
    j -= 262144;
    if (j < 393216) {
        int r = (int)(j / 768), c = (int)(j % 768);
        g_w16[W3_OFF + j] = (c < 726) ? __float2half_rn(W3[r * 726 + c]) : __float2half_rn(0.f);
        return;
    }
    j -= 393216;
    if (j < 65536) {
        int r = (int)(j >> 7), c = (int)(j & 127);
        g_w16[R3_OFF + j] = (c < 121) ? __float2half_rn(R3[r * 121 + c]) : __float2half_rn(0.f);
    }
}
#define CVT_TOTAL ((size_t)N_NODES * 128 + 851968)

// --------------- compose attention vectors into score weights -----------------
__global__ void k_combine(const float* __restrict__ W1, const float* __restrict__ a1s,
                          const float* __restrict__ a1d,
                          const float* __restrict__ W2, const float* __restrict__ a2s,
                          const float* __restrict__ a2d,
                          const float* __restrict__ W3, const float* __restrict__ a3s,
                          const float* __restrict__ a3d) {
    int gid = blockIdx.x * blockDim.x + threadIdx.x;
    if (gid < 128 * 64) {
        int k = gid >> 6, col = gid & 63, h = col >> 1;
        float v = 0.f;
        if (col < 8) {
            const float* a = (col & 1) ? a1d : a1s;
            for (int u = 0; u < 128; u++) v += W1[k * 512 + h * 128 + u] * a[h * 128 + u];
        }
        g_ws1[k * 64 + col] = __float2half_rn(v);
        return;
    }
    gid -= 128 * 64;
    if (gid < 512 * 64) {
        int k = gid >> 6, col = gid & 63, h = col >> 1;
        float v = 0.f;
        if (col < 8) {
            const float* a = (col & 1) ? a2d : a2s;
            for (int u = 0; u < 128; u++) v += W2[k * 512 + h * 128 + u] * a[h * 128 + u];
        }
        g_ws2[k * 64 + col] = __float2half_rn(v);
        return;
    }
    gid -= 512 * 64;
    if (gid < 512 * 64) {
        int k = gid >> 6, col = gid & 63, h = col >> 1;
        float v = 0.f;
        if (col < 12) {
            const float* a = (col & 1) ? a3d : a3s;
            for (int u = 0; u < 121; u++) v += W3[k * 726 + h * 121 + u] * a[h * 121 + u];
        }
        g_ws3[k * 64 + col] = __float2half_rn(v);
    }
}
#define COMBINE_TOTAL (128 * 64 + 512 * 64 + 512 * 64)

// ------------------------------- CSR build -----------------------------------
__global__ void k_zero_cnt() {
    int i = blockIdx.x * blockDim.x + threadIdx.x;
    if (i <= N_NODES) g_cnt[i] = 0;
}
__global__ void k_count(const int* __restrict__ edges) {
    int e = blockIdx.x * blockDim.x + threadIdx.x;
    if (e < N_EDGES) atomicAdd(&g_cnt[edges[2 * e + 1]], 1);
}
__global__ void k_scan() {
    __shared__ int sh[1024];
    __shared__ int carry_s;
    int tid = threadIdx.x;
    if (tid == 0) { carry_s = 0; g_off[0] = 0; g_cur[0] = 0; }
    __syncthreads();
    for (int base = 0; base < N_NODES; base += 1024) {
        int i = base + tid;
        int v = (i < N_NODES) ? g_cnt[i] : 0;
        sh[tid] = v;
        __syncthreads();
        for (int d = 1; d < 1024; d <<= 1) {
            int t = (tid >= d) ? sh[tid - d] : 0;
            __syncthreads();
            sh[tid] += t;
            __syncthreads();
        }
        if (i < N_NODES) {
            int val = carry_s + sh[tid];
            g_off[i + 1] = val;
            if (i + 1 < N_NODES) g_cur[i + 1] = val;
        }
        __syncthreads();
        if (tid == 0) carry_s += sh[1023];
        __syncthreads();
    }
}
__global__ void k_scatter(const int* __restrict__ edges) {
    int e = blockIdx.x * blockDim.x + threadIdx.x;
    if (e < N_EDGES) {
        int dst = edges[2 * e + 1];
        int p = atomicAdd(&g_cur[dst], 1);
        g_csr[p] = edges[2 * e];
    }
}

// --------------- FP16 TC GEMM (R10-proven config, K templated) ----------------
#define BM 128
#define BN 64
#define BK 32
#define A_TILE_HALFS (BM * BK)
#define B_TILE_HALFS (BK * BN)

__device__ __forceinline__ void cph16(uint32_t s, const void* g, bool p) {
    asm volatile("cp.async.cg.shared.global [%0], [%1], 16, %2;" ::"r"(s), "l"(g), "r"(p ? 16 : 0));
}
__device__ __forceinline__ void cp_commit() { asm volatile("cp.async.commit_group;"); }
__device__ __forceinline__ void ldmA(uint32_t a[4], uint32_t addr) {
    asm volatile("ldmatrix.sync.aligned.m8n8.x4.shared.b16 {%0,%1,%2,%3}, [%4];"
                 : "=r"(a[0]), "=r"(a[1]), "=r"(a[2]), "=r"(a[3]) : "r"(addr));
}
__device__ __forceinline__ void ldmBT(uint32_t b[4], uint32_t addr) {
    asm volatile("ldmatrix.sync.aligned.m8n8.x4.trans.shared.b16 {%0,%1,%2,%3}, [%4];"
                 : "=r"(b[0]), "=r"(b[1]), "=r"(b[2]), "=r"(b[3]) : "r"(addr));
}
__device__ __forceinline__ void mma16816(float c[4], const uint32_t a[4], uint32_t b0, uint32_t b1) {
    asm volatile("mma.sync.aligned.m16n8k16.row.col.f32.f16.f16.f32 "
                 "{%0,%1,%2,%3}, {%4,%5,%6,%7}, {%8,%9}, {%0,%1,%2,%3};"
                 : "+f"(c[0]), "+f"(c[1]), "+f"(c[2]), "+f"(c[3])
                 : "r"(a[0]), "r"(a[1]), "r"(a[2]), "r"(a[3]), "r"(b0), "r"(b1));
}

template <bool HALF_OUT, int K>
__global__ __launch_bounds__(256) void k_gemm_h(const __half* __restrict__ A,
                                                const __half* __restrict__ B,
                                                void* __restrict__ Cout,
                                                int M, int N, int Np) {
    __shared__ __align__(16) __half As[2][A_TILE_HALFS];
    __shared__ __align__(16) __half Bs[2][B_TILE_HALFS];
    const int tid = threadIdx.x, lane = tid & 31, wid = tid >> 5;
    const int wm = wid & 3, wn = wid >> 2;
    const int g = lane >> 2, c = lane & 3;
    const int mBase = blockIdx.y * BM, nBase = blockIdx.x * BN;
    const uint32_t sA = (uint32_t)__cvta_generic_to_shared(&As[0][0]);
    const uint32_t sB = (uint32_t)__cvta_generic_to_shared(&Bs[0][0]);

    float acc[2][4][4];
    #pragma unroll
    for (int mt = 0; mt < 2; mt++)
        #pragma unroll
        for (int nt = 0; nt < 4; nt++)
            #pragma unroll
            for (int i = 0; i < 4; i++) acc[mt][nt][i] = 0.f;

    const int ar = tid >> 2, ac = tid & 3;
    const int br = tid >> 3, bc = tid & 7;
    const int asw1 = ac ^ ((ar >> 1) & 3);
    const int asw2 = ac ^ (((ar + 64) >> 1) & 3);
    const int bsw  = bc ^ (br & 7);

    auto loadTile = [&](int k0, int buf) {
        uint32_t aB = sA + (uint32_t)(buf * A_TILE_HALFS * 2);
        int gm0 = mBase + ar, gm1 = mBase + ar + 64;
        cph16(aB + (uint32_t)(ar * 64 + asw1 * 16),
              A + (size_t)gm0 * K + k0 + ac * 8, gm0 < M);
        cph16(aB + (uint32_t)((ar + 64) * 64 + asw2 * 16),
              A + (size_t)gm1 * K + k0 + ac * 8, gm1 < M);
        uint32_t bB = sB + (uint32_t)(buf * B_TILE_HALFS * 2);
        cph16(bB + (uint32_t)(br * 128 + bsw * 16),
              B + (size_t)(k0 + br) * Np + nBase + bc * 8, true);
    };

    uint32_t aoff[2][2], boff[2][2];
    #pragma unroll
    for (int mt = 0; mt < 2; mt++)
        #pragma unroll
        for (int kk = 0; kk < 2; kk++) {
            int row = wm * 32 + mt * 16 + (lane & 15);
            int ch = kk * 2 + (lane >> 4);
            int sw = ch ^ ((row >> 1) & 3);
            aoff[mt][kk] = (uint32_t)(row * 64 + sw * 16);
        }
    #pragma unroll
    for (int ng = 0; ng < 2; ng++)
        #pragma unroll
        for (int kk = 0; kk < 2; kk++) {
            int row = kk * 16 + (lane & 15);
            int ch = wn * 4 + ng * 2 + (lane >> 4);
            int sw = ch ^ (row & 7);
            boff[ng][kk] = (uint32_t)(row * 128 + sw * 16);
        }

    constexpr int ntiles = K / BK;
    loadTile(0, 0);
    cp_commit();

    #pragma unroll
    for (int t = 0; t < ntiles; t++) {
        int buf = t & 1;
        if (t + 1 < ntiles) {
            loadTile((t + 1) * BK, (t + 1) & 1);
            cp_commit();
            asm volatile("cp.async.wait_group 1;");
        } else {
            asm volatile("cp.async.wait_group 0;");
        }
        __syncthreads();

        uint32_t aB = sA + (uint32_t)(buf * A_TILE_HALFS * 2);
        uint32_t bB = sB + (uint32_t)(buf * B_TILE_HALFS * 2);
        #pragma unroll
        for (int kk = 0; kk < 2; kk++) {
            uint32_t a0[4], a1[4], b0[4], b1[4];
            ldmA(a0, aB + aoff[0][kk]);
            ldmA(a1, aB + aoff[1][kk]);
            ldmBT(b0, bB + boff[0][kk]);
            ldmBT(b1, bB + boff[1][kk]);
            mma16816(acc[0][0], a0, b0[0], b0[1]);
            mma16816(acc[0][1], a0, b0[2], b0[3]);
            mma16816(acc[0][2], a0, b1[0], b1[1]);
            mma16816(acc[0][3], a0, b1[2], b1[3]);
            mma16816(acc[1][0], a1, b0[0], b0[1]);
            mma16816(acc[1][1], a1, b0[2], b0[3]);
            mma16816(acc[1][2], a1, b1[0], b1[1]);
            mma16816(acc[1][3], a1, b1[2], b1[3]);
        }
        __syncthreads();
    }

    #pragma unroll
    for (int mt = 0; mt < 2; mt++) {
        int r0 = mBase + wm * 32 + mt * 16 + g;
        int r1 = r0 + 8;
        #pragma unroll
        for (int nt = 0; nt < 4; nt++) {
            int col = nBase + wn * 32 + nt * 8 + 2 * c;
            if (HALF_OUT) {
                __half2* C2 = (__half2*)Cout;
                if (r0 < M && col < N)
                    C2[((size_t)r0 * N + col) >> 1] = __floats2half2_rn(acc[mt][nt][0], acc[mt][nt][1]);
                if (r1 < M && col < N)
                    C2[((size_t)r1 * N + col) >> 1] = __floats2half2_rn(acc[mt][nt][2], acc[mt][nt][3]);
            } else {
                float* C = (float*)Cout;
                if (r0 < M) {
                    if (col < N)     C[(size_t)r0 * N + col]     = acc[mt][nt][0];
                    if (col + 1 < N) C[(size_t)r0 * N + col + 1] = acc[mt][nt][1];
                }
                if (r1 < M) {
                    if (col < N)     C[(size_t)r1 * N + col]     = acc[mt][nt][2];
                    if (col + 1 < N) C[(size_t)r1 * N + col + 1] = acc[mt][nt][3];
                }
            }
        }
    }
}

// --------------- softmax weights: all heads, one gather (R8-proven) ------------
#define WCAP 512
template <int H>
__global__ __launch_bounds__(128) void k_weights(const float* __restrict__ esd) {
    __shared__ int   sidx[WCAP];
    __shared__ float se[H][WCAP];
    __shared__ float red[4 * H];
    __shared__ float s_mh[H], s_inv[H];
    int n = blockIdx.x;
    int tid = threadIdx.x;
    int lane = tid & 31, wid = tid >> 5;
    int beg = g_off[n], deg = g_off[n + 1] - beg;
    if (deg == 0) return;
    const float4* e4 = (const float4*)esd;

    float edv[H];
    #pragma unroll
    for (int q = 0; q < H / 2; q++) {
        float4 d = e4[n * (H / 2) + q];
        edv[2 * q] = d.y; edv[2 * q + 1] = d.w;
    }

    if (deg <= WCAP) {
        float mx[H];
        #pragma unroll
        for (int hh = 0; hh < H; hh++) mx[hh] = -1e30f;
        for (int i = tid; i < deg; i += 128) {
            int s = g_csr[beg + i];
            sidx[i] = s;
            float ev[H];
            #pragma unroll
            for (int q = 0; q < H / 2; q++) {
                float4 v = e4[s * (H / 2) + q];
                ev[2 * q] = v.x; ev[2 * q + 1] = v.z;
            }
            #pragma unroll
            for (int hh = 0; hh < H; hh++) {
                float e = ev[hh] + edv[hh];
                e = (e > 0.f) ? e : 0.2f * e;
                se[hh][i] = e;
                mx[hh] = fmaxf(mx[hh], e);
            }
        }
        #pragma unroll
        for (int hh = 0; hh < H; hh++) {
            #pragma unroll
            for (int o = 16; o > 0; o >>= 1)
                mx[hh] = fmaxf(mx[hh], __shfl_xor_sync(0xffffffffu, mx[hh], o));
        }
        if (lane == 0)
            #pragma unroll
            for (int hh = 0; hh < H; hh++) red[wid * H + hh] = mx[hh];
        __syncthreads();
        if (tid < H)
            s_mh[tid] = fmaxf(fmaxf(red[tid], red[H + tid]),
                              fmaxf(red[2 * H + tid], red[3 * H + tid]));
        __syncthreads();
        float m[H], sum[H];
        #pragma unroll
        for (int hh = 0; hh < H; hh++) { m[hh] = s_mh[hh]; sum[hh] = 0.f; }
        for (int i = tid; i < deg; i += 128) {
            #pragma unroll
            for (int hh = 0; hh < H; hh++) {
                float p = expf(se[hh][i] - m[hh]);
                se[hh][i] = p;
                sum[hh] += p;
            }
        }
        #pragma unroll
        for (int hh = 0; hh < H; hh++) {
            #pragma unroll
            for (int o = 16; o > 0; o >>= 1)
                sum[hh] += __shfl_xor_sync(0xffffffffu, sum[hh], o);
        }
        if (lane == 0)
            #pragma unroll
            for (int hh = 0; hh < H; hh++) red[wid * H + hh] = sum[hh];
        __syncthreads();
        if (tid < H)
            s_inv[tid] = 1.0f / fmaxf(red[tid] + red[H + tid] + red[2 * H + tid] + red[3 * H + tid], 1e-9f);
        __syncthreads();
        float inv[H];
        #pragma unroll
        for (int hh = 0; hh < H; hh++) inv[hh] = s_inv[hh];
        for (int i = tid; i < deg; i += 128) {
            if (H == 4) {
                float4 w;
                w.x = se[0][i] * inv[0]; w.y = se[1][i] * inv[1];
                w.z = se[2][i] * inv[2]; w.w = se[3][i] * inv[3];
                *(float4*)(&g_w[(size_t)(beg + i) * 4]) = w;
            } else {
                #pragma unroll
                for (int q = 0; q < H / 2; q++) {
                    float2 w;
                    w.x = se[2 * q][i] * inv[2 * q];
                    w.y = se[2 * q + 1][i] * inv[2 * q + 1];
                    *(float2*)(&g_w[(size_t)(beg + i) * H + 2 * q]) = w;
                }
            }
        }
    } else {
        __shared__ float warpred[4];
        __shared__ float s_m1, s_i1;
        for (int hh = 0; hh < H; hh++) {
            float ev = edv[hh];
            float mxx = -1e30f;
            for (int i = tid; i < deg; i += 128) {
                float e = esd[g_csr[beg + i] * 2 * H + 2 * hh] + ev;
                e = (e > 0.f) ? e : 0.2f * e;
                mxx = fmaxf(mxx, e);
            }
            #pragma unroll
            for (int o = 16; o > 0; o >>= 1) mxx = fmaxf(mxx, __shfl_xor_sync(0xffffffffu, mxx, o));
            if (lane == 0) warpred[wid] = mxx;
            __syncthreads();
            if (tid == 0)
                s_m1 = fmaxf(fmaxf(warpred[0], warpred[1]), fmaxf(warpred[2], warpred[3]));
            __syncthreads();
            float m = s_m1;
            float sum = 0.f;
            for (int i = tid; i < deg; i += 128) {
                float e = esd[g_csr[beg + i] * 2 * H + 2 * hh] + ev;
                e = (e > 0.f) ? e : 0.2f * e;
                sum += expf(e - m);
            }
            #pragma unroll
            for (int o = 16; o > 0; o >>= 1) sum += __shfl_xor_sync(0xffffffffu, sum, o);
            if (lane == 0) warpred[wid] = sum;
            __syncthreads();
            if (tid == 0)
                s_i1 = 1.0f / fmaxf(warpred[0] + warpred[1] + warpred[2] + warpred[3], 1e-9f);
            __syncthreads();
            float inv = s_i1;
            for (int i = tid; i < deg; i += 128) {
                float e = esd[g_csr[beg + i] * 2 * H + 2 * hh] + ev;
                e = (e > 0.f) ? e : 0.2f * e;
                g_w[(size_t)(beg + i) * H + hh] = expf(e - m) * inv;
            }
            __syncthreads();
        }
    }
}

// ---------------- weighted aggregation, layers 1/2 (R8-proven) ----------------
__global__ __launch_bounds__(256) void k_agg512(const __half* __restrict__ h,
                                                const float* __restrict__ res,
                                                float* __restrict__ outf,
                                                __half* __restrict__ out16) {
    int n = blockIdx.x;
    int tid = threadIdx.x;
    int hh = tid >> 6;
    int beg = g_off[n], deg = g_off[n + 1] - beg;
    const __half2* h2 = (const __half2*)h;
    float ax = 0.f, ay = 0.f;
    int i = 0;
    for (; i + 4 <= deg; i += 4) {
        int s0 = g_csr[beg + i],     s1 = g_csr[beg + i + 1];
        int s2 = g_csr[beg + i + 2], s3 = g_csr[beg + i + 3];
        float w0 = g_w[(size_t)(beg + i) * 4 + hh];
        float w1 = g_w[(size_t)(beg + i + 1) * 4 + hh];
        float w2 = g_w[(size_t)(beg + i + 2) * 4 + hh];
        float w3 = g_w[(size_t)(beg + i + 3) * 4 + hh];
        float2 v0 = __half22float2(__ldg(h2 + (size_t)s0 * 256 + tid));
        float2 v1 = __half22float2(__ldg(h2 + (size_t)s1 * 256 + tid));
        float2 v2 = __half22float2(__ldg(h2 + (size_t)s2 * 256 + tid));
        float2 v3 = __half22float2(__ldg(h2 + (size_t)s3 * 256 + tid));
        ax += w0 * v0.x + w1 * v1.x + w2 * v2.x + w3 * v3.x;
        ay += w0 * v0.y + w1 * v1.y + w2 * v2.y + w3 * v3.y;
    }
    for (; i < deg; i++) {
        int s = g_csr[beg + i];
        float w = g_w[(size_t)(beg + i) * 4 + hh];
        float2 v = __half22float2(__ldg(h2 + (size_t)s * 256 + tid));
        ax += w * v.x;
        ay += w * v.y;
    }
    float2 r = ((const float2*)res)[(size_t)n * 256 + tid];
    float vx = ax + r.x, vy = ay + r.y;
    vx = (vx > 0.f) ? vx : (expf(vx) - 1.f);
    vy = (vy > 0.f) ? vy : (expf(vy) - 1.f);
    if (outf) ((float2*)outf)[(size_t)n * 256 + tid] = make_float2(vx, vy);
    ((__half2*)out16)[(size_t)n * 256 + tid] = __floats2half2_rn(vx, vy);
}

// ---------------- weighted aggregation, layer 3 (R8-proven) -------------------
__global__ __launch_bounds__(384) void k_agg726(const __half* __restrict__ h,
                                                const float* __restrict__ res,
                                                float* __restrict__ out) {
    __shared__ float sh[726];
    int n = blockIdx.x;
    int tid = threadIdx.x;
    int beg = g_off[n], deg = g_off[n + 1] - beg;
    const __half2* h2 = (const __half2*)h;
    if (tid < 363) {
        int hA = (2 * tid) / 121;
        int hB = (2 * tid + 1) / 121;
        float ax = 0.f, ay = 0.f;
        int i = 0;
        for (; i + 4 <= deg; i += 4) {
            int s0 = g_csr[beg + i],     s1 = g_csr[beg + i + 1];
            int s2 = g_csr[beg + i + 2], s3 = g_csr[beg + i + 3];
            const float* wb0 = &g_w[(size_t)(beg + i) * 6];
            const float* wb1 = &g_w[(size_t)(beg + i + 1) * 6];
            const float* wb2 = &g_w[(size_t)(beg + i + 2) * 6];
            const float* wb3 = &g_w[(size_t)(beg + i + 3) * 6];
            float2 v0 = __half22float2(__ldg(h2 + (size_t)s0 * 363 + tid));
            float2 v1 = __half22float2(__ldg(h2 + (size_t)s1 * 363 + tid));
            float2 v2 = __half22float2(__ldg(h2 + (size_t)s2 * 363 + tid));
            float2 v3 = __half22float2(__ldg(h2 + (size_t)s3 * 363 + tid));
            ax += wb0[hA] * v0.x + wb1[hA] * v1.x + wb2[hA] * v2.x + wb3[hA] * v3.x;
            ay += wb0[hB] * v0.y + wb1[hB] * v1.y + wb2[hB] * v2.y + wb3[hB] * v3.y;
        }
        for (; i < deg; i++) {
            int s = g_csr[beg + i];
            const float* wb = &g_w[(size_t)(beg + i) * 6];
            float2 v = __half22float2(__ldg(h2 + (size_t)s * 363 + tid));
            ax += wb[hA] * v.x;
            ay += wb[hB] * v.y;
        }
        sh[2 * tid]     = ax;
        sh[2 * tid + 1] = ay;
    }
    __syncthreads();
    if (tid < 121) {
        float s = 0.f;
        #pragma unroll
        for (int hh = 0; hh < 6; hh++) s += sh[tid + hh * 121];
        out[(size_t)n * 121 + tid] = s * (1.f / 6.f) + res[(size_t)n * 121 + tid];
    }
}

// ------------------------------- launcher ------------------------------------
template <bool HALF_OUT>
static void launch_gemm(const __half* A, const __half* B, void* C, int M, int N, int Np, int K) {
    dim3 grid(Np / BN, (M + BM - 1) / BM);
    if (K == 128)
        k_gemm_h<HALF_OUT, 128><<<grid, 256>>>(A, B, C, M, N, Np);
    else
        k_gemm_h<HALF_OUT, 512><<<grid, 256>>>(A, B, C, M, N, Np);
}

extern "C" void kernel_launch(void* const* d_in, const int* in_sizes, int n_in,
                              void* d_out, int out_size) {
    const float* x    = (const float*)d_in[0];
    const int*   edges= (const int*)d_in[1];
    const float* W1   = (const float*)d_in[2];
    const float* a1s  = (const float*)d_in[3];
    const float* a1d  = (const float*)d_in[4];
    const float* R1   = (const float*)d_in[5];
    const float* W2   = (const float*)d_in[6];
    const float* a2s  = (const float*)d_in[7];
    const float* a2d  = (const float*)d_in[8];
    const float* W3   = (const float*)d_in[9];
    const float* a3s  = (const float*)d_in[10];
    const float* a3d  = (const float*)d_in[11];
    const float* R3   = (const float*)d_in[12];
    float* out = (float*)d_out;

    __half *hh, *x16, *b16, *a216, *w16, *ws1, *ws2, *ws3;
    float *res, *xb, *esd;
    cudaGetSymbolAddress((void**)&hh,   g_hh);
    cudaGetSymbolAddress((void**)&res,  g_res);
    cudaGetSymbolAddress((void**)&xb,   g_xb);
    cudaGetSymbolAddress((void**)&x16,  g_x16);
    cudaGetSymbolAddress((void**)&b16,  g_b16);
    cudaGetSymbolAddress((void**)&a216, g_a216);
    cudaGetSymbolAddress((void**)&w16,  g_w16);
    cudaGetSymbolAddress((void**)&ws1,  g_ws1);
    cudaGetSymbolAddress((void**)&ws2,  g_ws2);
    cudaGetSymbolAddress((void**)&ws3,  g_ws3);
    cudaGetSymbolAddress((void**)&esd,  g_esd);

    k_cvt<<<(int)((CVT_TOTAL + 255) / 256), 256>>>(x, W1, R1, W2, W3, R3);
    k_zero_cnt<<<(N_NODES + 256) / 256, 256>>>();
    k_count<<<(N_EDGES + 255) / 256, 256>>>(edges);
    launch_gemm<true >(x16, w16 + W1_OFF, hh, N_NODES, 512, 512, 128);   // profiled slot
    k_combine<<<(COMBINE_TOTAL + 255) / 256, 256>>>(W1, a1s, a1d, W2, a2s, a2d, W3, a3s, a3d);
    k_scan<<<1, 1024>>>();
    k_scatter<<<(N_EDGES + 255) / 256, 256>>>(edges);

    // ---- layer 1: H=4, U=128, concat, residual x@R1, ELU
    launch_gemm<false>(x16, w16 + R1_OFF, res, N_NODES, 512, 512, 128);
    launch_gemm<false>(x16, ws1, esd, N_NODES, 8, 64, 128);
    k_weights<4><<<N_NODES, 128>>>(esd);
    k_agg512<<<N_NODES, 256>>>(hh, res, xb, b16);

    // ---- layer 2: H=4, U=128, concat, residual = x1, ELU
    launch_gemm<true >(b16, w16 + W2_OFF, hh, N_NODES, 512, 512, 512);
    launch_gemm<false>(b16, ws2, esd, N_NODES, 8, 64, 512);
    k_weights<4><<<N_NODES, 128>>>(esd);
    k_agg512<<<N_NODES, 256>>>(hh, xb, nullptr, a216);

    // ---- layer 3: H=6, U=121, avg merge, residual x2@R3, identity
    launch_gemm<true >(a216, w16 + W3_OFF, hh, N_NODES, 726, 768, 512);
    launch_gemm<false>(a216, w16 + R3_OFF, res, N_NODES, 121, 128, 512);
    launch_gemm<false>(a216, ws3, esd, N_NODES, 12, 64, 512);
    k_weights<6><<<N_NODES, 128>>>(esd);
    k_agg726<<<N_NODES, 384>>>(hh, res, out);
}

// round 13
// speedup vs baseline: 1.4468x; 1.0167x over previous
#include <cuda_runtime.h>
#include <cuda_fp16.h>
#include <math.h>
#include <stdint.h>

#define N_NODES 50000
#define N_EDGES 800000

// ---------------- scratch (device globals; no dynamic allocation) -------------
__device__ __half g_hh[(size_t)N_NODES * 726];
__device__ float  g_res[(size_t)N_NODES * 512];
__device__ float  g_xb [(size_t)N_NODES * 512];
__device__ __half g_x16 [(size_t)N_NODES * 128];
__device__ __half g_b16 [(size_t)N_NODES * 512];
__device__ __half g_a216[(size_t)N_NODES * 512];
__device__ float  g_esd[(size_t)N_NODES * 12];
__device__ __half g_bw1[128 * 1088];   // [W1 | R1 | ws1]
__device__ __half g_bw2[512 * 576];    // [W2 | ws2]
__device__ __half g_bw3[512 * 960];    // [W3pad | R3pad | ws3]
__device__ float  g_w[(size_t)N_EDGES * 6];
__device__ int   g_cnt[N_NODES + 1];
__device__ int   g_off[N_NODES + 1];
__device__ int   g_cur[N_NODES];
__device__ int   g_csr[N_EDGES];

// ------------------------- fp32 -> fp16 conversion + B arenas -----------------
__global__ void k_cvt(const float* __restrict__ x,  const float* __restrict__ W1,
                      const float* __restrict__ R1, const float* __restrict__ W2,
                      const float* __restrict__ W3, const float* __restrict__ R3) {
    size_t i = (size_t)blockIdx.x * blockDim.x + threadIdx.x;
    const size_t NX = (size_t)N_NODES * 128;
    if (i < NX) { g_x16[i] = __float2half_rn(x[i]); return; }
    size_t j = i - NX;
    if (j < 128 * 1088) {
        int k = (int)(j / 1088), col = (int)(j % 1088);
        float v = 0.f;
        if (col < 512) v = W1[k * 512 + col];
        else if (col < 1024) v = R1[k * 512 + (col - 512)];
        g_bw1[j] = __float2half_rn(v);   // ws region zero; k_combine fills it
        return;
    }
    j -= 128 * 1088;
    if (j < 512 * 576) {
        int k = (int)(j / 576), col = (int)(j % 576);
        float v = (col < 512) ? W2[k * 512 + col] : 0.f;
        g_bw2[j] = __float2half_rn(v);
        return;
    }
    j -= 512 * 576;
    if (j < 512 * 960) {
        int k = (int)(j / 960), col = (int)(j % 960);
        float v = 0.f;
        if (col < 726) v = W3[k * 726 + col];
        else if (col >= 768 && col < 889) v = R3[k * 121 + (col - 768)];
        g_bw3[j] = __float2half_rn(v);
    }
}
#define CVT_TOTAL ((size_t)N_NODES * 128 + 128 * 1088 + 512 * 576 + 512 * 960)

// --------------- compose attention vectors into arena ws columns --------------
__global__ void k_combine(const float* __restrict__ W1, const float* __restrict__ a1s,
                          const float* __restrict__ a1d,
                          const float* __restrict__ W2, const float* __restrict__ a2s,
                          const float* __restrict__ a2d,
                          const float* __restrict__ W3, const float* __restrict__ a3s,
                          const float* __restrict__ a3d) {
    int gid = blockIdx.x * blockDim.x + threadIdx.x;
    if (gid < 128 * 64) {
        int k = gid >> 6, col = gid & 63, h = col >> 1;
        float v = 0.f;
        if (col < 8) {
            const float* a = (col & 1) ? a1d : a1s;
            for (int u = 0; u < 128; u++) v += W1[k * 512 + h * 128 + u] * a[h * 128 + u];
        }
        g_bw1[k * 1088 + 1024 + col] = __float2half_rn(v);
        return;
    }
    gid -= 128 * 64;
    if (gid < 512 * 64) {
        int k = gid >> 6, col = gid & 63, h = col >> 1;
        float v = 0.f;
        if (col < 8) {
            const float* a = (col & 1) ? a2d : a2s;
            for (int u = 0; u < 128; u++) v += W2[k * 512 + h * 128 + u] * a[h * 128 + u];
        }
        g_bw2[k * 576 + 512 + col] = __float2half_rn(v);
        return;
    }
    gid -= 512 * 64;
    if (gid < 512 * 64) {
        int k = gid >> 6, col = gid & 63, h = col >> 1;
        float v = 0.f;
        if (col < 12) {
            const float* a = (col & 1) ? a3d : a3s;
            for (int u = 0; u < 121; u++) v += W3[k * 726 + h * 121 + u] * a[h * 121 + u];
        }
        g_bw3[k * 960 + 896 + col] = __float2half_rn(v);
    }
}
#define COMBINE_TOTAL (128 * 64 + 512 * 64 + 512 * 64)

// ------------------------------- CSR build -----------------------------------
__global__ void k_zero_cnt() {
    int i = blockIdx.x * blockDim.x + threadIdx.x;
    if (i <= N_NODES) g_cnt[i] = 0;
}
__global__ void k_count(const int* __restrict__ edges) {
    int e = blockIdx.x * blockDim.x + threadIdx.x;
    if (e < N_EDGES) atomicAdd(&g_cnt[edges[2 * e + 1]], 1);
}
__global__ void k_scan() {
    __shared__ int sh[1024];
    __shared__ int carry_s;
    int tid = threadIdx.x;
    if (tid == 0) { carry_s = 0; g_off[0] = 0; g_cur[0] = 0; }
    __syncthreads();
    for (int base = 0; base < N_NODES; base += 1024) {
        int i = base + tid;
        int v = (i < N_NODES) ? g_cnt[i] : 0;
        sh[tid] = v;
        __syncthreads();
        for (int d = 1; d < 1024; d <<= 1) {
            int t = (tid >= d) ? sh[tid - d] : 0;
            __syncthreads();
            sh[tid] += t;
            __syncthreads();
        }
        if (i < N_NODES) {
            int val = carry_s + sh[tid];
            g_off[i + 1] = val;
            if (i + 1 < N_NODES) g_cur[i + 1] = val;
        }
        __syncthreads();
        if (tid == 0) carry_s += sh[1023];
        __syncthreads();
    }
}
__global__ void k_scatter(const int* __restrict__ edges) {
    int e = blockIdx.x * blockDim.x + threadIdx.x;
    if (e < N_EDGES) {
        int dst = edges[2 * e + 1];
        int p = atomicAdd(&g_cur[dst], 1);
        g_csr[p] = edges[2 * e];
    }
}

// --------------- FP16 TC GEMM, merged-output epilogue -------------------------
#define BM 128
#define BN 64
#define BK 32
#define A_TILE_HALFS (BM * BK)
#define B_TILE_HALFS (BK * BN)

__device__ __forceinline__ void cph16(uint32_t s, const void* g, bool p) {
    asm volatile("cp.async.cg.shared.global [%0], [%1], 16, %2;" ::"r"(s), "l"(g), "r"(p ? 16 : 0));
}
__device__ __forceinline__ void cp_commit() { asm volatile("cp.async.commit_group;"); }
__device__ __forceinline__ void ldmA(uint32_t a[4], uint32_t addr) {
    asm volatile("ldmatrix.sync.aligned.m8n8.x4.shared.b16 {%0,%1,%2,%3}, [%4];"
                 : "=r"(a[0]), "=r"(a[1]), "=r"(a[2]), "=r"(a[3]) : "r"(addr));
}
__device__ __forceinline__ void ldmBT(uint32_t b[4], uint32_t addr) {
    asm volatile("ldmatrix.sync.aligned.m8n8.x4.trans.shared.b16 {%0,%1,%2,%3}, [%4];"
                 : "=r"(b[0]), "=r"(b[1]), "=r"(b[2]), "=r"(b[3]) : "r"(addr));
}
__device__ __forceinline__ void mma16816(float c[4], const uint32_t a[4], uint32_t b0, uint32_t b1) {
    asm volatile("mma.sync.aligned.m16n8k16.row.col.f32.f16.f16.f32 "
                 "{%0,%1,%2,%3}, {%4,%5,%6,%7}, {%8,%9}, {%0,%1,%2,%3};"
                 : "+f"(c[0]), "+f"(c[1]), "+f"(c[2]), "+f"(c[3])
                 : "r"(a[0]), "r"(a[1]), "r"(a[2]), "r"(a[3]), "r"(b0), "r"(b1));
}

// L=1: cols [0,512) hh(512), [512,1024) res(512), [1024,1032) esd(8)
// L=2: cols [0,512) hh(512), [512,520) esd(8)
// L=3: cols [0,726) hh(726), [768,889) res(121), [896,908) esd(12)
template <int L, int K>
__global__ __launch_bounds__(256) void k_gemm_h(const __half* __restrict__ A,
                                                const __half* __restrict__ B,
                                                __half* __restrict__ hhO,
                                                float* __restrict__ resO,
                                                float* __restrict__ esdO,
                                                int M, int Np) {
    __shared__ __align__(16) __half As[2][A_TILE_HALFS];
    __shared__ __align__(16) __half Bs[2][B_TILE_HALFS];
    const int tid = threadIdx.x, lane = tid & 31, wid = tid >> 5;
    const int wm = wid & 3, wn = wid >> 2;
    const int g = lane >> 2, c = lane & 3;
    const int mBase = blockIdx.y * BM, nBase = blockIdx.x * BN;
    const uint32_t sA = (uint32_t)__cvta_generic_to_shared(&As[0][0]);
    const uint32_t sB = (uint32_t)__cvta_generic_to_shared(&Bs[0][0]);

    float acc[2][4][4];
    #pragma unroll
    for (int mt = 0; mt < 2; mt++)
        #pragma unroll
        for (int nt = 0; nt < 4; nt++)
            #pragma unroll
            for (int i = 0; i < 4; i++) acc[mt][nt][i] = 0.f;

    const int ar = tid >> 2, ac = tid & 3;
    const int br = tid >> 3, bc = tid & 7;
    const int asw1 = ac ^ ((ar >> 1) & 3);
    const int asw2 = ac ^ (((ar + 64) >> 1) & 3);
    const int bsw  = bc ^ (br & 7);

    auto loadTile = [&](int k0, int buf) {
        uint32_t aB = sA + (uint32_t)(buf * A_TILE_HALFS * 2);
        int gm0 = mBase + ar, gm1 = mBase + ar + 64;
        cph16(aB + (uint32_t)(ar * 64 + asw1 * 16),
              A + (size_t)gm0 * K + k0 + ac * 8, gm0 < M);
        cph16(aB + (uint32_t)((ar + 64) * 64 + asw2 * 16),
              A + (size_t)gm1 * K + k0 + ac * 8, gm1 < M);
        uint32_t bB = sB + (uint32_t)(buf * B_TILE_HALFS * 2);
        cph16(bB + (uint32_t)(br * 128 + bsw * 16),
              B + (size_t)(k0 + br) * Np + nBase + bc * 8, true);
    };

    uint32_t aoff[2][2], boff[2][2];
    #pragma unroll
    for (int mt = 0; mt < 2; mt++)
        #pragma unroll
        for (int kk = 0; kk < 2; kk++) {
            int row = wm * 32 + mt * 16 + (lane & 15);
            int ch = kk * 2 + (lane >> 4);
            int sw = ch ^ ((row >> 1) & 3);
            aoff[mt][kk] = (uint32_t)(row * 64 + sw * 16);
        }
    #pragma unroll
    for (int ng = 0; ng < 2; ng++)
        #pragma unroll
        for (int kk = 0; kk < 2; kk++) {
            int row = kk * 16 + (lane & 15);
            int ch = wn * 4 + ng * 2 + (lane >> 4);
            int sw = ch ^ (row & 7);
            boff[ng][kk] = (uint32_t)(row * 128 + sw * 16);
        }

    constexpr int ntiles = K / BK;
    loadTile(0, 0);
    cp_commit();

    #pragma unroll
    for (int t = 0; t < ntiles; t++) {
        int buf = t & 1;
        if (t + 1 < ntiles) {
            loadTile((t + 1) * BK, (t + 1) & 1);
            cp_commit();
            asm volatile("cp.async.wait_group 1;");
        } else {
            asm volatile("cp.async.wait_group 0;");
        }
        __syncthreads();

        uint32_t aB = sA + (uint32_t)(buf * A_TILE_HALFS * 2);
        uint32_t bB = sB + (uint32_t)(buf * B_TILE_HALFS * 2);
        #pragma unroll
        for (int kk = 0; kk < 2; kk++) {
            uint32_t a0[4], a1[4], b0[4], b1[4];
            ldmA(a0, aB + aoff[0][kk]);
            ldmA(a1, aB + aoff[1][kk]);
            ldmBT(b0, bB + boff[0][kk]);
            ldmBT(b1, bB + boff[1][kk]);
            mma16816(acc[0][0], a0, b0[0], b0[1]);
            mma16816(acc[0][1], a0, b0[2], b0[3]);
            mma16816(acc[0][2], a0, b1[0], b1[1]);
            mma16816(acc[0][3], a0, b1[2], b1[3]);
            mma16816(acc[1][0], a1, b0[0], b0[1]);
            mma16816(acc[1][1], a1, b0[2], b0[3]);
            mma16816(acc[1][2], a1, b1[0], b1[1]);
            mma16816(acc[1][3], a1, b1[2], b1[3]);
        }
        __syncthreads();
    }

    // region-routed epilogue
    auto storeRow = [&](int r, int col, float va, float vb) {
        if (L == 1) {
            if (col < 512) {
                ((__half2*)hhO)[((size_t)r * 512 + col) >> 1] = __floats2half2_rn(va, vb);
            } else if (col < 1024) {
                resO[(size_t)r * 512 + (col - 512)]     = va;
                resO[(size_t)r * 512 + (col - 512) + 1] = vb;
            } else if (col < 1032) {
                esdO[(size_t)r * 8 + (col - 1024)]     = va;
                esdO[(size_t)r * 8 + (col - 1024) + 1] = vb;
            }
        } else if (L == 2) {
            if (col < 512) {
                ((__half2*)hhO)[((size_t)r * 512 + col) >> 1] = __floats2half2_rn(va, vb);
            } else if (col < 520) {
                esdO[(size_t)r * 8 + (col - 512)]     = va;
                esdO[(size_t)r * 8 + (col - 512) + 1] = vb;
            }
        } else {
            if (col < 726) {
                ((__half2*)hhO)[((size_t)r * 726 + col) >> 1] = __floats2half2_rn(va, vb);
            } else if (col >= 768 && col < 890) {
                int cc = col - 768;
                if (cc < 121)     resO[(size_t)r * 121 + cc]     = va;
                if (cc + 1 < 121) resO[(size_t)r * 121 + cc + 1] = vb;
            } else if (col >= 896 && col < 908) {
                esdO[(size_t)r * 12 + (col - 896)]     = va;
                esdO[(size_t)r * 12 + (col - 896) + 1] = vb;
            }
        }
    };
    #pragma unroll
    for (int mt = 0; mt < 2; mt++) {
        int r0 = mBase + wm * 32 + mt * 16 + g;
        int r1 = r0 + 8;
        #pragma unroll
        for (int nt = 0; nt < 4; nt++) {
            int col = nBase + wn * 32 + nt * 8 + 2 * c;
            if (r0 < M) storeRow(r0, col, acc[mt][nt][0], acc[mt][nt][1]);
            if (r1 < M) storeRow(r1, col, acc[mt][nt][2], acc[mt][nt][3]);
        }
    }
}

// --------------- softmax weights: all heads, one gather (R8-proven) ------------
#define WCAP 512
template <int H>
__global__ __launch_bounds__(128) void k_weights(const float* __restrict__ esd) {
    __shared__ int   sidx[WCAP];
    __shared__ float se[H][WCAP];
    __shared__ float red[4 * H];
    __shared__ float s_mh[H], s_inv[H];
    int n = blockIdx.x;
    int tid = threadIdx.x;
    int lane = tid & 31, wid = tid >> 5;
    int beg = g_off[n], deg = g_off[n + 1] - beg;
    if (deg == 0) return;
    const float4* e4 = (const float4*)esd;

    float edv[H];
    #pragma unroll
    for (int q = 0; q < H / 2; q++) {
        float4 d = e4[n * (H / 2) + q];
        edv[2 * q] = d.y; edv[2 * q + 1] = d.w;
    }

    if (deg <= WCAP) {
        float mx[H];
        #pragma unroll
        for (int hh = 0; hh < H; hh++) mx[hh] = -1e30f;
        for (int i = tid; i < deg; i += 128) {
            int s = g_csr[beg + i];
            sidx[i] = s;
            float ev[H];
            #pragma unroll
            for (int q = 0; q < H / 2; q++) {
                float4 v = e4[s * (H / 2) + q];
                ev[2 * q] = v.x; ev[2 * q + 1] = v.z;
            }
            #pragma unroll
            for (int hh = 0; hh < H; hh++) {
                float e = ev[hh] + edv[hh];
                e = (e > 0.f) ? e : 0.2f * e;
                se[hh][i] = e;
                mx[hh] = fmaxf(mx[hh], e);
            }
        }
        #pragma unroll
        for (int hh = 0; hh < H; hh++) {
            #pragma unroll
            for (int o = 16; o > 0; o >>= 1)
                mx[hh] = fmaxf(mx[hh], __shfl_xor_sync(0xffffffffu, mx[hh], o));
        }
        if (lane == 0)
            #pragma unroll
            for (int hh = 0; hh < H; hh++) red[wid * H + hh] = mx[hh];
        __syncthreads();
        if (tid < H)
            s_mh[tid] = fmaxf(fmaxf(red[tid], red[H + tid]),
                              fmaxf(red[2 * H + tid], red[3 * H + tid]));
        __syncthreads();
        float m[H], sum[H];
        #pragma unroll
        for (int hh = 0; hh < H; hh++) { m[hh] = s_mh[hh]; sum[hh] = 0.f; }
        for (int i = tid; i < deg; i += 128) {
            #pragma unroll
            for (int hh = 0; hh < H; hh++) {
                float p = expf(se[hh][i] - m[hh]);
                se[hh][i] = p;
                sum[hh] += p;
            }
        }
        #pragma unroll
        for (int hh = 0; hh < H; hh++) {
            #pragma unroll
            for (int o = 16; o > 0; o >>= 1)
                sum[hh] += __shfl_xor_sync(0xffffffffu, sum[hh], o);
        }
        if (lane == 0)
            #pragma unroll
            for (int hh = 0; hh < H; hh++) red[wid * H + hh] = sum[hh];
        __syncthreads();
        if (tid < H)
            s_inv[tid] = 1.0f / fmaxf(red[tid] + red[H + tid] + red[2 * H + tid] + red[3 * H + tid], 1e-9f);
        __syncthreads();
        float inv[H];
        #pragma unroll
        for (int hh = 0; hh < H; hh++) inv[hh] = s_inv[hh];
        for (int i = tid; i < deg; i += 128) {
            if (H == 4) {
                float4 w;
                w.x = se[0][i] * inv[0]; w.y = se[1][i] * inv[1];
                w.z = se[2][i] * inv[2]; w.w = se[3][i] * inv[3];
                *(float4*)(&g_w[(size_t)(beg + i) * 4]) = w;
            } else {
                #pragma unroll
                for (int q = 0; q < H / 2; q++) {
                    float2 w;
                    w.x = se[2 * q][i] * inv[2 * q];
                    w.y = se[2 * q + 1][i] * inv[2 * q + 1];
                    *(float2*)(&g_w[(size_t)(beg + i) * H + 2 * q]) = w;
                }
            }
        }
    } else {
        __shared__ float warpred[4];
        __shared__ float s_m1, s_i1;
        for (int hh = 0; hh < H; hh++) {
            float ev = edv[hh];
            float mxx = -1e30f;
            for (int i = tid; i < deg; i += 128) {
                float e = esd[g_csr[beg + i] * 2 * H + 2 * hh] + ev;
                e = (e > 0.f) ? e : 0.2f * e;
                mxx = fmaxf(mxx, e);
            }
            #pragma unroll
            for (int o = 16; o > 0; o >>= 1) mxx = fmaxf(mxx, __shfl_xor_sync(0xffffffffu, mxx, o));
            if (lane == 0) warpred[wid] = mxx;
            __syncthreads();
            if (tid == 0)
                s_m1 = fmaxf(fmaxf(warpred[0], warpred[1]), fmaxf(warpred[2], warpred[3]));
            __syncthreads();
            float m = s_m1;
            float sum = 0.f;
            for (int i = tid; i < deg; i += 128) {
                float e = esd[g_csr[beg + i] * 2 * H + 2 * hh] + ev;
                e = (e > 0.f) ? e : 0.2f * e;
                sum += expf(e - m);
            }
            #pragma unroll
            for (int o = 16; o > 0; o >>= 1) sum += __shfl_xor_sync(0xffffffffu, sum, o);
            if (lane == 0) warpred[wid] = sum;
            __syncthreads();
            if (tid == 0)
                s_i1 = 1.0f / fmaxf(warpred[0] + warpred[1] + warpred[2] + warpred[3], 1e-9f);
            __syncthreads();
            float inv = s_i1;
            for (int i = tid; i < deg; i += 128) {
                float e = esd[g_csr[beg + i] * 2 * H + 2 * hh] + ev;
                e = (e > 0.f) ? e : 0.2f * e;
                g_w[(size_t)(beg + i) * H + hh] = expf(e - m) * inv;
            }
            __syncthreads();
        }
    }
}

// ---------------- weighted aggregation, layers 1/2 (R8-proven) ----------------
__global__ __launch_bounds__(256) void k_agg512(const __half* __restrict__ h,
                                                const float* __restrict__ res,
                                                float* __restrict__ outf,
                                                __half* __restrict__ out16) {
    int n = blockIdx.x;
    int tid = threadIdx.x;
    int hh = tid >> 6;
    int beg = g_off[n], deg = g_off[n + 1] - beg;
    const __half2* h2 = (const __half2*)h;
    float ax = 0.f, ay = 0.f;
    int i = 0;
    for (; i + 4 <= deg; i += 4) {
        int s0 = g_csr[beg + i],     s1 = g_csr[beg + i + 1];
        int s2 = g_csr[beg + i + 2], s3 = g_csr[beg + i + 3];
        float w0 = g_w[(size_t)(beg + i) * 4 + hh];
        float w1 = g_w[(size_t)(beg + i + 1) * 4 + hh];
        float w2 = g_w[(size_t)(beg + i + 2) * 4 + hh];
        float w3 = g_w[(size_t)(beg + i + 3) * 4 + hh];
        float2 v0 = __half22float2(__ldg(h2 + (size_t)s0 * 256 + tid));
        float2 v1 = __half22float2(__ldg(h2 + (size_t)s1 * 256 + tid));
        float2 v2 = __half22float2(__ldg(h2 + (size_t)s2 * 256 + tid));
        float2 v3 = __half22float2(__ldg(h2 + (size_t)s3 * 256 + tid));
        ax += w0 * v0.x + w1 * v1.x + w2 * v2.x + w3 * v3.x;
        ay += w0 * v0.y + w1 * v1.y + w2 * v2.y + w3 * v3.y;
    }
    for (; i < deg; i++) {
        int s = g_csr[beg + i];
        float w = g_w[(size_t)(beg + i) * 4 + hh];
        float2 v = __half22float2(__ldg(h2 + (size_t)s * 256 + tid));
        ax += w * v.x;
        ay += w * v.y;
    }
    float2 r = ((const float2*)res)[(size_t)n * 256 + tid];
    float vx = ax + r.x, vy = ay + r.y;
    vx = (vx > 0.f) ? vx : (expf(vx) - 1.f);
    vy = (vy > 0.f) ? vy : (expf(vy) - 1.f);
    if (outf) ((float2*)outf)[(size_t)n * 256 + tid] = make_float2(vx, vy);
    ((__half2*)out16)[(size_t)n * 256 + tid] = __floats2half2_rn(vx, vy);
}

// ---------------- weighted aggregation, layer 3 (R8-proven) -------------------
__global__ __launch_bounds__(384) void k_agg726(const __half* __restrict__ h,
                                                const float* __restrict__ res,
                                                float* __restrict__ out) {
    __shared__ float sh[726];
    int n = blockIdx.x;
    int tid = threadIdx.x;
    int beg = g_off[n], deg = g_off[n + 1] - beg;
    const __half2* h2 = (const __half2*)h;
    if (tid < 363) {
        int hA = (2 * tid) / 121;
        int hB = (2 * tid + 1) / 121;
        float ax = 0.f, ay = 0.f;
        int i = 0;
        for (; i + 4 <= deg; i += 4) {
            int s0 = g_csr[beg + i],     s1 = g_csr[beg + i + 1];
            int s2 = g_csr[beg + i + 2], s3 = g_csr[beg + i + 3];
            const float* wb0 = &g_w[(size_t)(beg + i) * 6];
            const float* wb1 = &g_w[(size_t)(beg + i + 1) * 6];
            const float* wb2 = &g_w[(size_t)(beg + i + 2) * 6];
            const float* wb3 = &g_w[(size_t)(beg + i + 3) * 6];
            float2 v0 = __half22float2(__ldg(h2 + (size_t)s0 * 363 + tid));
            float2 v1 = __half22float2(__ldg(h2 + (size_t)s1 * 363 + tid));
            float2 v2 = __half22float2(__ldg(h2 + (size_t)s2 * 363 + tid));
            float2 v3 = __half22float2(__ldg(h2 + (size_t)s3 * 363 + tid));
            ax += wb0[hA] * v0.x + wb1[hA] * v1.x + wb2[hA] * v2.x + wb3[hA] * v3.x;
            ay += wb0[hB] * v0.y + wb1[hB] * v1.y + wb2[hB] * v2.y + wb3[hB] * v3.y;
        }
        for (; i < deg; i++) {
            int s = g_csr[beg + i];
            const float* wb = &g_w[(size_t)(beg + i) * 6];
            float2 v = __half22float2(__ldg(h2 + (size_t)s * 363 + tid));
            ax += wb[hA] * v.x;
            ay += wb[hB] * v.y;
        }
        sh[2 * tid]     = ax;
        sh[2 * tid + 1] = ay;
    }
    __syncthreads();
    if (tid < 121) {
        float s = 0.f;
        #pragma unroll
        for (int hh = 0; hh < 6; hh++) s += sh[tid + hh * 121];
        out[(size_t)n * 121 + tid] = s * (1.f / 6.f) + res[(size_t)n * 121 + tid];
    }
}

// ------------------------------- launcher ------------------------------------
extern "C" void kernel_launch(void* const* d_in, const int* in_sizes, int n_in,
                              void* d_out, int out_size) {
    const float* x    = (const float*)d_in[0];
    const int*   edges= (const int*)d_in[1];
    const float* W1   = (const float*)d_in[2];
    const float* a1s  = (const float*)d_in[3];
    const float* a1d  = (const float*)d_in[4];
    const float* R1   = (const float*)d_in[5];
    const float* W2   = (const float*)d_in[6];
    const float* a2s  = (const float*)d_in[7];
    const float* a2d  = (const float*)d_in[8];
    const float* W3   = (const float*)d_in[9];
    const float* a3s  = (const float*)d_in[10];
    const float* a3d  = (const float*)d_in[11];
    const float* R3   = (const float*)d_in[12];
    float* out = (float*)d_out;

    __half *hh, *x16, *b16, *a216, *bw1, *bw2, *bw3;
    float *res, *xb, *esd;
    cudaGetSymbolAddress((void**)&hh,   g_hh);
    cudaGetSymbolAddress((void**)&res,  g_res);
    cudaGetSymbolAddress((void**)&xb,   g_xb);
    cudaGetSymbolAddress((void**)&x16,  g_x16);
    cudaGetSymbolAddress((void**)&b16,  g_b16);
    cudaGetSymbolAddress((void**)&a216, g_a216);
    cudaGetSymbolAddress((void**)&bw1,  g_bw1);
    cudaGetSymbolAddress((void**)&bw2,  g_bw2);
    cudaGetSymbolAddress((void**)&bw3,  g_bw3);
    cudaGetSymbolAddress((void**)&esd,  g_esd);

    const int gy = (N_NODES + BM - 1) / BM;   // 391

    k_cvt<<<(int)((CVT_TOTAL + 255) / 256), 256>>>(x, W1, R1, W2, W3, R3);
    k_combine<<<(COMBINE_TOTAL + 255) / 256, 256>>>(W1, a1s, a1d, W2, a2s, a2d, W3, a3s, a3d);
    k_zero_cnt<<<(N_NODES + 256) / 256, 256>>>();
    // ---- layer 1 merged GEMM: [W1|R1|ws1], Np=1088  (profiled slot, index 3)
    k_gemm_h<1, 128><<<dim3(1088 / BN, gy), 256>>>(x16, bw1, hh, res, esd, N_NODES, 1088);
    k_count<<<(N_EDGES + 255) / 256, 256>>>(edges);
    k_scan<<<1, 1024>>>();
    k_scatter<<<(N_EDGES + 255) / 256, 256>>>(edges);

    k_weights<4><<<N_NODES, 128>>>(esd);
    k_agg512<<<N_NODES, 256>>>(hh, res, xb, b16);

    // ---- layer 2 merged GEMM: [W2|ws2], Np=576
    k_gemm_h<2, 512><<<dim3(576 / BN, gy), 256>>>(b16, bw2, hh, nullptr, esd, N_NODES, 576);
    k_weights<4><<<N_NODES, 128>>>(esd);
    k_agg512<<<N_NODES, 256>>>(hh, xb, nullptr, a216);

    // ---- layer 3 merged GEMM: [W3|R3|ws3], Np=960
    k_gemm_h<3, 512><<<dim3(960 / BN, gy), 256>>>(a216, bw3, hh, res, esd, N_NODES, 960);
    k_weights<6><<<N_NODES, 128>>>(esd);
    k_agg726<<<N_NODES, 384>>>(hh, res, out);
}

// round 14
// speedup vs baseline: 1.4870x; 1.0277x over previous
#include <cuda_runtime.h>
#include <cuda_fp16.h>
#include <math.h>
#include <stdint.h>

#define N_NODES 50000
#define N_EDGES 800000

// ---------------- scratch (device globals; no dynamic allocation) -------------
__device__ __half g_hh[(size_t)N_NODES * 726];
__device__ float  g_res[(size_t)N_NODES * 512];
__device__ float  g_xb [(size_t)N_NODES * 512];
__device__ __half g_x16 [(size_t)N_NODES * 128];
__device__ __half g_b16 [(size_t)N_NODES * 512];
__device__ __half g_a216[(size_t)N_NODES * 512];
__device__ float  g_esd[(size_t)N_NODES * 12];
__device__ __half g_bw1[128 * 1152];   // [W1 | R1 | ws1 | pad]
__device__ __half g_bw2[512 * 640];    // [W2 | ws2 | pad]
__device__ __half g_bw3[512 * 1024];   // [W3pad | R3pad | ws3 | pad]
__device__ float  g_w[(size_t)N_EDGES * 6];
__device__ int   g_cnt[N_NODES + 1];
__device__ int   g_off[N_NODES + 1];
__device__ int   g_cur[N_NODES];
__device__ int   g_csr[N_EDGES];

// ------------------------- fp32 -> fp16 conversion + B arenas -----------------
__global__ void k_cvt(const float* __restrict__ x,  const float* __restrict__ W1,
                      const float* __restrict__ R1, const float* __restrict__ W2,
                      const float* __restrict__ W3, const float* __restrict__ R3) {
    size_t i = (size_t)blockIdx.x * blockDim.x + threadIdx.x;
    const size_t NX = (size_t)N_NODES * 128;
    if (i < NX) { g_x16[i] = __float2half_rn(x[i]); return; }
    size_t j = i - NX;
    if (j < 128 * 1152) {
        int k = (int)(j / 1152), col = (int)(j % 1152);
        float v = 0.f;
        if (col < 512) v = W1[k * 512 + col];
        else if (col < 1024) v = R1[k * 512 + (col - 512)];
        g_bw1[j] = __float2half_rn(v);   // ws + pad zero; k_combine fills ws
        return;
    }
    j -= 128 * 1152;
    if (j < 512 * 640) {
        int k = (int)(j / 640), col = (int)(j % 640);
        float v = (col < 512) ? W2[k * 512 + col] : 0.f;
        g_bw2[j] = __float2half_rn(v);
        return;
    }
    j -= 512 * 640;
    if (j < 512 * 1024) {
        int k = (int)(j >> 10), col = (int)(j & 1023);
        float v = 0.f;
        if (col < 726) v = W3[k * 726 + col];
        else if (col >= 768 && col < 889) v = R3[k * 121 + (col - 768)];
        g_bw3[j] = __float2half_rn(v);
    }
}
#define CVT_TOTAL ((size_t)N_NODES * 128 + 128 * 1152 + 512 * 640 + 512 * 1024)

// --------------- compose attention vectors into arena ws columns --------------
__global__ void k_combine(const float* __restrict__ W1, const float* __restrict__ a1s,
                          const float* __restrict__ a1d,
                          const float* __restrict__ W2, const float* __restrict__ a2s,
                          const float* __restrict__ a2d,
                          const float* __restrict__ W3, const float* __restrict__ a3s,
                          const float* __restrict__ a3d) {
    int gid = blockIdx.x * blockDim.x + threadIdx.x;
    if (gid < 128 * 64) {
        int k = gid >> 6, col = gid & 63, h = col >> 1;
        float v = 0.f;
        if (col < 8) {
            const float* a = (col & 1) ? a1d : a1s;
            for (int u = 0; u < 128; u++) v += W1[k * 512 + h * 128 + u] * a[h * 128 + u];
        }
        g_bw1[k * 1152 + 1024 + col] = __float2half_rn(v);
        return;
    }
    gid -= 128 * 64;
    if (gid < 512 * 64) {
        int k = gid >> 6, col = gid & 63, h = col >> 1;
        float v = 0.f;
        if (col < 8) {
            const float* a = (col & 1) ? a2d : a2s;
            for (int u = 0; u < 128; u++) v += W2[k * 512 + h * 128 + u] * a[h * 128 + u];
        }
        g_bw2[k * 640 + 512 + col] = __float2half_rn(v);
        return;
    }
    gid -= 512 * 64;
    if (gid < 512 * 64) {
        int k = gid >> 6, col = gid & 63, h = col >> 1;
        float v = 0.f;
        if (col < 12) {
            const float* a = (col & 1) ? a3d : a3s;
            for (int u = 0; u < 121; u++) v += W3[k * 726 + h * 121 + u] * a[h * 121 + u];
        }
        g_bw3[k * 1024 + 896 + col] = __float2half_rn(v);
    }
}
#define COMBINE_TOTAL (128 * 64 + 512 * 64 + 512 * 64)

// ------------------------------- CSR build -----------------------------------
__global__ void k_zero_cnt() {
    int i = blockIdx.x * blockDim.x + threadIdx.x;
    if (i <= N_NODES) g_cnt[i] = 0;
}
__global__ void k_count(const int* __restrict__ edges) {
    int e = blockIdx.x * blockDim.x + threadIdx.x;
    if (e < N_EDGES) atomicAdd(&g_cnt[edges[2 * e + 1]], 1);
}
__global__ void k_scan() {
    __shared__ int sh[1024];
    __shared__ int carry_s;
    int tid = threadIdx.x;
    if (tid == 0) { carry_s = 0; g_off[0] = 0; g_cur[0] = 0; }
    __syncthreads();
    for (int base = 0; base < N_NODES; base += 1024) {
        int i = base + tid;
        int v = (i < N_NODES) ? g_cnt[i] : 0;
        sh[tid] = v;
        __syncthreads();
        for (int d = 1; d < 1024; d <<= 1) {
            int t = (tid >= d) ? sh[tid - d] : 0;
            __syncthreads();
            sh[tid] += t;
            __syncthreads();
        }
        if (i < N_NODES) {
            int val = carry_s + sh[tid];
            g_off[i + 1] = val;
            if (i + 1 < N_NODES) g_cur[i + 1] = val;
        }
        __syncthreads();
        if (tid == 0) carry_s += sh[1023];
        __syncthreads();
    }
}
__global__ void k_scatter(const int* __restrict__ edges) {
    int e = blockIdx.x * blockDim.x + threadIdx.x;
    if (e < N_EDGES) {
        int dst = edges[2 * e + 1];
        int p = atomicAdd(&g_cur[dst], 1);
        g_csr[p] = edges[2 * e];
    }
}

// --------------- FP16 TC GEMM, BN=128 (warp tile 32x64), merged epilogue ------
#define BM 128
#define BN 128
#define BK 32
#define A_TILE_HALFS (BM * BK)          // 4096
#define B_SUB_HALFS (BK * 64)           // 2048 per 64-wide subtile
#define B_TILE_HALFS (2 * B_SUB_HALFS)  // 4096

__device__ __forceinline__ void cph16(uint32_t s, const void* g, bool p) {
    asm volatile("cp.async.cg.shared.global [%0], [%1], 16, %2;" ::"r"(s), "l"(g), "r"(p ? 16 : 0));
}
__device__ __forceinline__ void cp_commit() { asm volatile("cp.async.commit_group;"); }
__device__ __forceinline__ void ldmA(uint32_t a[4], uint32_t addr) {
    asm volatile("ldmatrix.sync.aligned.m8n8.x4.shared.b16 {%0,%1,%2,%3}, [%4];"
                 : "=r"(a[0]), "=r"(a[1]), "=r"(a[2]), "=r"(a[3]) : "r"(addr));
}
__device__ __forceinline__ void ldmBT(uint32_t b[4], uint32_t addr) {
    asm volatile("ldmatrix.sync.aligned.m8n8.x4.trans.shared.b16 {%0,%1,%2,%3}, [%4];"
                 : "=r"(b[0]), "=r"(b[1]), "=r"(b[2]), "=r"(b[3]) : "r"(addr));
}
__device__ __forceinline__ void mma16816(float c[4], const uint32_t a[4], uint32_t b0, uint32_t b1) {
    asm volatile("mma.sync.aligned.m16n8k16.row.col.f32.f16.f16.f32 "
                 "{%0,%1,%2,%3}, {%4,%5,%6,%7}, {%8,%9}, {%0,%1,%2,%3};"
                 : "+f"(c[0]), "+f"(c[1]), "+f"(c[2]), "+f"(c[3])
                 : "r"(a[0]), "r"(a[1]), "r"(a[2]), "r"(a[3]), "r"(b0), "r"(b1));
}

// L=1: cols [0,512) hh(512), [512,1024) res, [1024,1032) esd   (Np=1152)
// L=2: cols [0,512) hh(512), [512,520) esd                      (Np=640)
// L=3: cols [0,726) hh(726), [768,889) res(121), [896,908) esd  (Np=1024)
template <int L, int K>
__global__ __launch_bounds__(256) void k_gemm_h(const __half* __restrict__ A,
                                                const __half* __restrict__ B,
                                                __half* __restrict__ hhO,
                                                float* __restrict__ resO,
                                                float* __restrict__ esdO,
                                                int M, int Np) {
    __shared__ __align__(16) __half As[2][A_TILE_HALFS];
    __shared__ __align__(16) __half Bs[2][B_TILE_HALFS];
    const int tid = threadIdx.x, lane = tid & 31, wid = tid >> 5;
    const int wm = wid & 3, wn = wid >> 2;           // warp tile: 32 (M) x 64 (N)
    const int g = lane >> 2, c = lane & 3;
    const int mBase = blockIdx.y * BM, nBase = blockIdx.x * BN;
    const uint32_t sA = (uint32_t)__cvta_generic_to_shared(&As[0][0]);
    const uint32_t sB = (uint32_t)__cvta_generic_to_shared(&Bs[0][0]);

    float acc[2][8][4];
    #pragma unroll
    for (int mt = 0; mt < 2; mt++)
        #pragma unroll
        for (int nt = 0; nt < 8; nt++)
            #pragma unroll
            for (int i = 0; i < 4; i++) acc[mt][nt][i] = 0.f;

    const int ar = tid >> 2, ac = tid & 3;
    const int br = tid >> 3, bc = tid & 7;
    const int asw1 = ac ^ ((ar >> 1) & 3);
    const int asw2 = ac ^ (((ar + 64) >> 1) & 3);
    const int bsw  = bc ^ (br & 7);

    auto loadTile = [&](int k0, int buf) {
        uint32_t aB = sA + (uint32_t)(buf * A_TILE_HALFS * 2);
        int gm0 = mBase + ar, gm1 = mBase + ar + 64;
        cph16(aB + (uint32_t)(ar * 64 + asw1 * 16),
              A + (size_t)gm0 * K + k0 + ac * 8, gm0 < M);
        cph16(aB + (uint32_t)((ar + 64) * 64 + asw2 * 16),
              A + (size_t)gm1 * K + k0 + ac * 8, gm1 < M);
        uint32_t bB = sB + (uint32_t)(buf * B_TILE_HALFS * 2);
        #pragma unroll
        for (int sub = 0; sub < 2; sub++) {
            cph16(bB + (uint32_t)(sub * B_SUB_HALFS * 2 + br * 128 + bsw * 16),
                  B + (size_t)(k0 + br) * Np + nBase + sub * 64 + bc * 8, true);
        }
    };

    // ldmatrix offsets: A as before; B within this warp's subtile (wn)
    uint32_t aoff[2][2], boff[4][2];
    #pragma unroll
    for (int mt = 0; mt < 2; mt++)
        #pragma unroll
        for (int kk = 0; kk < 2; kk++) {
            int row = wm * 32 + mt * 16 + (lane & 15);
            int ch = kk * 2 + (lane >> 4);
            int sw = ch ^ ((row >> 1) & 3);
            aoff[mt][kk] = (uint32_t)(row * 64 + sw * 16);
        }
    #pragma unroll
    for (int ng = 0; ng < 4; ng++)
        #pragma unroll
        for (int kk = 0; kk < 2; kk++) {
            int row = kk * 16 + (lane & 15);
            int ch = ng * 2 + (lane >> 4);
            int sw = ch ^ (row & 7);
            boff[ng][kk] = (uint32_t)(wn * B_SUB_HALFS * 2 + row * 128 + sw * 16);
        }

    constexpr int ntiles = K / BK;
    loadTile(0, 0);
    cp_commit();

    #pragma unroll
    for (int t = 0; t < ntiles; t++) {
        int buf = t & 1;
        if (t + 1 < ntiles) {
            loadTile((t + 1) * BK, (t + 1) & 1);
            cp_commit();
            asm volatile("cp.async.wait_group 1;");
        } else {
            asm volatile("cp.async.wait_group 0;");
        }
        __syncthreads();

        uint32_t aB = sA + (uint32_t)(buf * A_TILE_HALFS * 2);
        uint32_t bB = sB + (uint32_t)(buf * B_TILE_HALFS * 2);
        #pragma unroll
        for (int kk = 0; kk < 2; kk++) {
            uint32_t a0[4], a1[4], bf[4][4];
            ldmA(a0, aB + aoff[0][kk]);
            ldmA(a1, aB + aoff[1][kk]);
            #pragma unroll
            for (int ng = 0; ng < 4; ng++) ldmBT(bf[ng], bB + boff[ng][kk]);
            #pragma unroll
            for (int ng = 0; ng < 4; ng++) {
                mma16816(acc[0][2 * ng],     a0, bf[ng][0], bf[ng][1]);
                mma16816(acc[0][2 * ng + 1], a0, bf[ng][2], bf[ng][3]);
                mma16816(acc[1][2 * ng],     a1, bf[ng][0], bf[ng][1]);
                mma16816(acc[1][2 * ng + 1], a1, bf[ng][2], bf[ng][3]);
            }
        }
        __syncthreads();
    }

    // region-routed epilogue
    auto storeRow = [&](int r, int col, float va, float vb) {
        if (L == 1) {
            if (col < 512) {
                ((__half2*)hhO)[((size_t)r * 512 + col) >> 1] = __floats2half2_rn(va, vb);
            } else if (col < 1024) {
                resO[(size_t)r * 512 + (col - 512)]     = va;
                resO[(size_t)r * 512 + (col - 512) + 1] = vb;
            } else if (col < 1032) {
                esdO[(size_t)r * 8 + (col - 1024)]     = va;
                esdO[(size_t)r * 8 + (col - 1024) + 1] = vb;
            }
        } else if (L == 2) {
            if (col < 512) {
                ((__half2*)hhO)[((size_t)r * 512 + col) >> 1] = __floats2half2_rn(va, vb);
            } else if (col < 520) {
                esdO[(size_t)r * 8 + (col - 512)]     = va;
                esdO[(size_t)r * 8 + (col - 512) + 1] = vb;
            }
        } else {
            if (col < 726) {
                ((__half2*)hhO)[((size_t)r * 726 + col) >> 1] = __floats2half2_rn(va, vb);
            } else if (col >= 768 && col < 890) {
                int cc = col - 768;
                if (cc < 121)     resO[(size_t)r * 121 + cc]     = va;
                if (cc + 1 < 121) resO[(size_t)r * 121 + cc + 1] = vb;
            } else if (col >= 896 && col < 908) {
                esdO[(size_t)r * 12 + (col - 896)]     = va;
                esdO[(size_t)r * 12 + (col - 896) + 1] = vb;
            }
        }
    };
    #pragma unroll
    for (int mt = 0; mt < 2; mt++) {
        int r0 = mBase + wm * 32 + mt * 16 + g;
        int r1 = r0 + 8;
        #pragma unroll
        for (int nt = 0; nt < 8; nt++) {
            int col = nBase + wn * 64 + nt * 8 + 2 * c;
            if (r0 < M) storeRow(r0, col, acc[mt][nt][0], acc[mt][nt][1]);
            if (r1 < M) storeRow(r1, col, acc[mt][nt][2], acc[mt][nt][3]);
        }
    }
}

// --------------- softmax weights: all heads, one gather (R8-proven) ------------
#define WCAP 512
template <int H>
__global__ __launch_bounds__(128) void k_weights(const float* __restrict__ esd) {
    __shared__ int   sidx[WCAP];
    __shared__ float se[H][WCAP];
    __shared__ float red[4 * H];
    __shared__ float s_mh[H], s_inv[H];
    int n = blockIdx.x;
    int tid = threadIdx.x;
    int lane = tid & 31, wid = tid >> 5;
    int beg = g_off[n], deg = g_off[n + 1] - beg;
    if (deg == 0) return;
    const float4* e4 = (const float4*)esd;

    float edv[H];
    #pragma unroll
    for (int q = 0; q < H / 2; q++) {
        float4 d = e4[n * (H / 2) + q];
        edv[2 * q] = d.y; edv[2 * q + 1] = d.w;
    }

    if (deg <= WCAP) {
        float mx[H];
        #pragma unroll
        for (int hh = 0; hh < H; hh++) mx[hh] = -1e30f;
        for (int i = tid; i < deg; i += 128) {
            int s = g_csr[beg + i];
            sidx[i] = s;
            float ev[H];
            #pragma unroll
            for (int q = 0; q < H / 2; q++) {
                float4 v = e4[s * (H / 2) + q];
                ev[2 * q] = v.x; ev[2 * q + 1] = v.z;
            }
            #pragma unroll
            for (int hh = 0; hh < H; hh++) {
                float e = ev[hh] + edv[hh];
                e = (e > 0.f) ? e : 0.2f * e;
                se[hh][i] = e;
                mx[hh] = fmaxf(mx[hh], e);
            }
        }
        #pragma unroll
        for (int hh = 0; hh < H; hh++) {
            #pragma unroll
            for (int o = 16; o > 0; o >>= 1)
                mx[hh] = fmaxf(mx[hh], __shfl_xor_sync(0xffffffffu, mx[hh], o));
        }
        if (lane == 0)
            #pragma unroll
            for (int hh = 0; hh < H; hh++) red[wid * H + hh] = mx[hh];
        __syncthreads();
        if (tid < H)
            s_mh[tid] = fmaxf(fmaxf(red[tid], red[H + tid]),
                              fmaxf(red[2 * H + tid], red[3 * H + tid]));
        __syncthreads();
        float m[H], sum[H];
        #pragma unroll
        for (int hh = 0; hh < H; hh++) { m[hh] = s_mh[hh]; sum[hh] = 0.f; }
        for (int i = tid; i < deg; i += 128) {
            #pragma unroll
            for (int hh = 0; hh < H; hh++) {
                float p = expf(se[hh][i] - m[hh]);
                se[hh][i] = p;
                sum[hh] += p;
            }
        }
        #pragma unroll
        for (int hh = 0; hh < H; hh++) {
            #pragma unroll
            for (int o = 16; o > 0; o >>= 1)
                sum[hh] += __shfl_xor_sync(0xffffffffu, sum[hh], o);
        }
        if (lane == 0)
            #pragma unroll
            for (int hh = 0; hh < H; hh++) red[wid * H + hh] = sum[hh];
        __syncthreads();
        if (tid < H)
            s_inv[tid] = 1.0f / fmaxf(red[tid] + red[H + tid] + red[2 * H + tid] + red[3 * H + tid], 1e-9f);
        __syncthreads();
        float inv[H];
        #pragma unroll
        for (int hh = 0; hh < H; hh++) inv[hh] = s_inv[hh];
        for (int i = tid; i < deg; i += 128) {
            if (H == 4) {
                float4 w;
                w.x = se[0][i] * inv[0]; w.y = se[1][i] * inv[1];
                w.z = se[2][i] * inv[2]; w.w = se[3][i] * inv[3];
                *(float4*)(&g_w[(size_t)(beg + i) * 4]) = w;
            } else {
                #pragma unroll
                for (int q = 0; q < H / 2; q++) {
                    float2 w;
                    w.x = se[2 * q][i] * inv[2 * q];
                    w.y = se[2 * q + 1][i] * inv[2 * q + 1];
                    *(float2*)(&g_w[(size_t)(beg + i) * H + 2 * q]) = w;
                }
            }
        }
    } else {
        __shared__ float warpred[4];
        __shared__ float s_m1, s_i1;
        for (int hh = 0; hh < H; hh++) {
            float ev = edv[hh];
            float mxx = -1e30f;
            for (int i = tid; i < deg; i += 128) {
                float e = esd[g_csr[beg + i] * 2 * H + 2 * hh] + ev;
                e = (e > 0.f) ? e : 0.2f * e;
                mxx = fmaxf(mxx, e);
            }
            #pragma unroll
            for (int o = 16; o > 0; o >>= 1) mxx = fmaxf(mxx, __shfl_xor_sync(0xffffffffu, mxx, o));
            if (lane == 0) warpred[wid] = mxx;
            __syncthreads();
            if (tid == 0)
                s_m1 = fmaxf(fmaxf(warpred[0], warpred[1]), fmaxf(warpred[2], warpred[3]));
            __syncthreads();
            float m = s_m1;
            float sum = 0.f;
            for (int i = tid; i < deg; i += 128) {
                float e = esd[g_csr[beg + i] * 2 * H + 2 * hh] + ev;
                e = (e > 0.f) ? e : 0.2f * e;
                sum += expf(e - m);
            }
            #pragma unroll
            for (int o = 16; o > 0; o >>= 1) sum += __shfl_xor_sync(0xffffffffu, sum, o);
            if (lane == 0) warpred[wid] = sum;
            __syncthreads();
            if (tid == 0)
                s_i1 = 1.0f / fmaxf(warpred[0] + warpred[1] + warpred[2] + warpred[3], 1e-9f);
            __syncthreads();
            float inv = s_i1;
            for (int i = tid; i < deg; i += 128) {
                float e = esd[g_csr[beg + i] * 2 * H + 2 * hh] + ev;
                e = (e > 0.f) ? e : 0.2f * e;
                g_w[(size_t)(beg + i) * H + hh] = expf(e - m) * inv;
            }
            __syncthreads();
        }
    }
}

// ---------------- weighted aggregation, layers 1/2 (R8-proven) ----------------
__global__ __launch_bounds__(256) void k_agg512(const __half* __restrict__ h,
                                                const float* __restrict__ res,
                                                float* __restrict__ outf,
                                                __half* __restrict__ out16) {
    int n = blockIdx.x;
    int tid = threadIdx.x;
    int hh = tid >> 6;
    int beg = g_off[n], deg = g_off[n + 1] - beg;
    const __half2* h2 = (const __half2*)h;
    float ax = 0.f, ay = 0.f;
    int i = 0;
    for (; i + 4 <= deg; i += 4) {
        int s0 = g_csr[beg + i],     s1 = g_csr[beg + i + 1];
        int s2 = g_csr[beg + i + 2], s3 = g_csr[beg + i + 3];
        float w0 = g_w[(size_t)(beg + i) * 4 + hh];
        float w1 = g_w[(size_t)(beg + i + 1) * 4 + hh];
        float w2 = g_w[(size_t)(beg + i + 2) * 4 + hh];
        float w3 = g_w[(size_t)(beg + i + 3) * 4 + hh];
        float2 v0 = __half22float2(__ldg(h2 + (size_t)s0 * 256 + tid));
        float2 v1 = __half22float2(__ldg(h2 + (size_t)s1 * 256 + tid));
        float2 v2 = __half22float2(__ldg(h2 + (size_t)s2 * 256 + tid));
        float2 v3 = __half22float2(__ldg(h2 + (size_t)s3 * 256 + tid));
        ax += w0 * v0.x + w1 * v1.x + w2 * v2.x + w3 * v3.x;
        ay += w0 * v0.y + w1 * v1.y + w2 * v2.y + w3 * v3.y;
    }
    for (; i < deg; i++) {
        int s = g_csr[beg + i];
        float w = g_w[(size_t)(beg + i) * 4 + hh];
        float2 v = __half22float2(__ldg(h2 + (size_t)s * 256 + tid));
        ax += w * v.x;
        ay += w * v.y;
    }
    float2 r = ((const float2*)res)[(size_t)n * 256 + tid];
    float vx = ax + r.x, vy = ay + r.y;
    vx = (vx > 0.f) ? vx : (expf(vx) - 1.f);
    vy = (vy > 0.f) ? vy : (expf(vy) - 1.f);
    if (outf) ((float2*)outf)[(size_t)n * 256 + tid] = make_float2(vx, vy);
    ((__half2*)out16)[(size_t)n * 256 + tid] = __floats2half2_rn(vx, vy);
}

// ---------------- weighted aggregation, layer 3 (R8-proven) -------------------
__global__ __launch_bounds__(384) void k_agg726(const __half* __restrict__ h,
                                                const float* __restrict__ res,
                                                float* __restrict__ out) {
    __shared__ float sh[726];
    int n = blockIdx.x;
    int tid = threadIdx.x;
    int beg = g_off[n], deg = g_off[n + 1] - beg;
    const __half2* h2 = (const __half2*)h;
    if (tid < 363) {
        int hA = (2 * tid) / 121;
        int hB = (2 * tid + 1) / 121;
        float ax = 0.f, ay = 0.f;
        int i = 0;
        for (; i + 4 <= deg; i += 4) {
            int s0 = g_csr[beg + i],     s1 = g_csr[beg + i + 1];
            int s2 = g_csr[beg + i + 2], s3 = g_csr[beg + i + 3];
            const float* wb0 = &g_w[(size_t)(beg + i) * 6];
            const float* wb1 = &g_w[(size_t)(beg + i + 1) * 6];
            const float* wb2 = &g_w[(size_t)(beg + i + 2) * 6];
            const float* wb3 = &g_w[(size_t)(beg + i + 3) * 6];
            float2 v0 = __half22float2(__ldg(h2 + (size_t)s0 * 363 + tid));
            float2 v1 = __half22float2(__ldg(h2 + (size_t)s1 * 363 + tid));
            float2 v2 = __half22float2(__ldg(h2 + (size_t)s2 * 363 + tid));
            float2 v3 = __half22float2(__ldg(h2 + (size_t)s3 * 363 + tid));
            ax += wb0[hA] * v0.x + wb1[hA] * v1.x + wb2[hA] * v2.x + wb3[hA] * v3.x;
            ay += wb0[hB] * v0.y + wb1[hB] * v1.y + wb2[hB] * v2.y + wb3[hB] * v3.y;
        }
        for (; i < deg; i++) {
            int s = g_csr[beg + i];
            const float* wb = &g_w[(size_t)(beg + i) * 6];
            float2 v = __half22float2(__ldg(h2 + (size_t)s * 363 + tid));
            ax += wb[hA] * v.x;
            ay += wb[hB] * v.y;
        }
        sh[2 * tid]     = ax;
        sh[2 * tid + 1] = ay;
    }
    __syncthreads();
    if (tid < 121) {
        float s = 0.f;
        #pragma unroll
        for (int hh = 0; hh < 6; hh++) s += sh[tid + hh * 121];
        out[(size_t)n * 121 + tid] = s * (1.f / 6.f) + res[(size_t)n * 121 + tid];
    }
}

// ------------------------------- launcher ------------------------------------
extern "C" void kernel_launch(void* const* d_in, const int* in_sizes, int n_in,
                              void* d_out, int out_size) {
    const float* x    = (const float*)d_in[0];
    const int*   edges= (const int*)d_in[1];
    const float* W1   = (const float*)d_in[2];
    const float* a1s  = (const float*)d_in[3];
    const float* a1d  = (const float*)d_in[4];
    const float* R1   = (const float*)d_in[5];
    const float* W2   = (const float*)d_in[6];
    const float* a2s  = (const float*)d_in[7];
    const float* a2d  = (const float*)d_in[8];
    const float* W3   = (const float*)d_in[9];
    const float* a3s  = (const float*)d_in[10];
    const float* a3d  = (const float*)d_in[11];
    const float* R3   = (const float*)d_in[12];
    float* out = (float*)d_out;

    __half *hh, *x16, *b16, *a216, *bw1, *bw2, *bw3;
    float *res, *xb, *esd;
    cudaGetSymbolAddress((void**)&hh,   g_hh);
    cudaGetSymbolAddress((void**)&res,  g_res);
    cudaGetSymbolAddress((void**)&xb,   g_xb);
    cudaGetSymbolAddress((void**)&x16,  g_x16);
    cudaGetSymbolAddress((void**)&b16,  g_b16);
    cudaGetSymbolAddress((void**)&a216, g_a216);
    cudaGetSymbolAddress((void**)&bw1,  g_bw1);
    cudaGetSymbolAddress((void**)&bw2,  g_bw2);
    cudaGetSymbolAddress((void**)&bw3,  g_bw3);
    cudaGetSymbolAddress((void**)&esd,  g_esd);

    const int gy = (N_NODES + BM - 1) / BM;   // 391

    k_cvt<<<(int)((CVT_TOTAL + 255) / 256), 256>>>(x, W1, R1, W2, W3, R3);
    k_combine<<<(COMBINE_TOTAL + 255) / 256, 256>>>(W1, a1s, a1d, W2, a2s, a2d, W3, a3s, a3d);
    k_zero_cnt<<<(N_NODES + 256) / 256, 256>>>();
    // ---- layer 1 merged GEMM: [W1|R1|ws1], Np=1152  (profiled slot, index 3)
    k_gemm_h<1, 128><<<dim3(1152 / BN, gy), 256>>>(x16, bw1, hh, res, esd, N_NODES, 1152);
    k_count<<<(N_EDGES + 255) / 256, 256>>>(edges);
    k_scan<<<1, 1024>>>();
    k_scatter<<<(N_EDGES + 255) / 256, 256>>>(edges);

    k_weights<4><<<N_NODES, 128>>>(esd);
    k_agg512<<<N_NODES, 256>>>(hh, res, xb, b16);

    // ---- layer 2 merged GEMM: [W2|ws2], Np=640
    k_gemm_h<2, 512><<<dim3(640 / BN, gy), 256>>>(b16, bw2, hh, nullptr, esd, N_NODES, 640);
    k_weights<4><<<N_NODES, 128>>>(esd);
    k_agg512<<<N_NODES, 256>>>(hh, xb, nullptr, a216);

    // ---- layer 3 merged GEMM: [W3|R3|ws3], Np=1024
    k_gemm_h<3, 512><<<dim3(1024 / BN, gy), 256>>>(a216, bw3, hh, res, esd, N_NODES, 1024);
    k_weights<6><<<N_NODES, 128>>>(esd);
    k_agg726<<<N_NODES, 384>>>(hh, res, out);
}

// round 15
// speedup vs baseline: 1.5278x; 1.0275x over previous
#include <cuda_runtime.h>
#include <cuda_fp16.h>
#include <math.h>
#include <stdint.h>

#define N_NODES 50000
#define N_EDGES 800000

// ---------------- scratch (device globals; no dynamic allocation) -------------
__device__ __half g_hh[(size_t)N_NODES * 726];
__device__ __half g_res16[(size_t)N_NODES * 512];  // layer-1 residual, fp16
__device__ float  g_res3[(size_t)N_NODES * 128];   // layer-3 residual, fp32 (121 used)
__device__ __half g_x16 [(size_t)N_NODES * 128];
__device__ __half g_b16 [(size_t)N_NODES * 512];   // x1 fp16 (GEMM A + layer-2 residual)
__device__ __half g_a216[(size_t)N_NODES * 512];
__device__ float  g_esd[(size_t)N_NODES * 12];
__device__ __half g_bw1[128 * 1152];   // [W1 | R1 | ws1 | pad]
__device__ __half g_bw2[512 * 640];    // [W2 | ws2 | pad]
__device__ __half g_bw3[512 * 1024];   // [W3pad | R3pad | ws3 | pad]
__device__ float  g_w[(size_t)N_EDGES * 6];
__device__ int   g_cnt[N_NODES + 1];
__device__ int   g_off[N_NODES + 1];
__device__ int   g_cur[N_NODES];
__device__ int   g_csr[N_EDGES];

// ------------------------- fp32 -> fp16 conversion + B arenas -----------------
__global__ void k_cvt(const float* __restrict__ x,  const float* __restrict__ W1,
                      const float* __restrict__ R1, const float* __restrict__ W2,
                      const float* __restrict__ W3, const float* __restrict__ R3) {
    size_t i = (size_t)blockIdx.x * blockDim.x + threadIdx.x;
    const size_t NX = (size_t)N_NODES * 128;
    if (i < NX) { g_x16[i] = __float2half_rn(x[i]); return; }
    size_t j = i - NX;
    if (j < 128 * 1152) {
        int k = (int)(j / 1152), col = (int)(j % 1152);
        float v = 0.f;
        if (col < 512) v = W1[k * 512 + col];
        else if (col < 1024) v = R1[k * 512 + (col - 512)];
        g_bw1[j] = __float2half_rn(v);
        return;
    }
    j -= 128 * 1152;
    if (j < 512 * 640) {
        int k = (int)(j / 640), col = (int)(j % 640);
        float v = (col < 512) ? W2[k * 512 + col] : 0.f;
        g_bw2[j] = __float2half_rn(v);
        return;
    }
    j -= 512 * 640;
    if (j < 512 * 1024) {
        int k = (int)(j >> 10), col = (int)(j & 1023);
        float v = 0.f;
        if (col < 726) v = W3[k * 726 + col];
        else if (col >= 768 && col < 889) v = R3[k * 121 + (col - 768)];
        g_bw3[j] = __float2half_rn(v);
    }
}
#define CVT_TOTAL ((size_t)N_NODES * 128 + 128 * 1152 + 512 * 640 + 512 * 1024)

// --------------- compose attention vectors into arena ws columns --------------
__global__ void k_combine(const float* __restrict__ W1, const float* __restrict__ a1s,
                          const float* __restrict__ a1d,
                          const float* __restrict__ W2, const float* __restrict__ a2s,
                          const float* __restrict__ a2d,
                          const float* __restrict__ W3, const float* __restrict__ a3s,
                          const float* __restrict__ a3d) {
    int gid = blockIdx.x * blockDim.x + threadIdx.x;
    if (gid < 128 * 64) {
        int k = gid >> 6, col = gid & 63, h = col >> 1;
        float v = 0.f;
        if (col < 8) {
            const float* a = (col & 1) ? a1d : a1s;
            for (int u = 0; u < 128; u++) v += W1[k * 512 + h * 128 + u] * a[h * 128 + u];
        }
        g_bw1[k * 1152 + 1024 + col] = __float2half_rn(v);
        return;
    }
    gid -= 128 * 64;
    if (gid < 512 * 64) {
        int k = gid >> 6, col = gid & 63, h = col >> 1;
        float v = 0.f;
        if (col < 8) {
            const float* a = (col & 1) ? a2d : a2s;
            for (int u = 0; u < 128; u++) v += W2[k * 512 + h * 128 + u] * a[h * 128 + u];
        }
        g_bw2[k * 640 + 512 + col] = __float2half_rn(v);
        return;
    }
    gid -= 512 * 64;
    if (gid < 512 * 64) {
        int k = gid >> 6, col = gid & 63, h = col >> 1;
        float v = 0.f;
        if (col < 12) {
            const float* a = (col & 1) ? a3d : a3s;
            for (int u = 0; u < 121; u++) v += W3[k * 726 + h * 121 + u] * a[h * 121 + u];
        }
        g_bw3[k * 1024 + 896 + col] = __float2half_rn(v);
    }
}
#define COMBINE_TOTAL (128 * 64 + 512 * 64 + 512 * 64)

// ------------------------------- CSR build -----------------------------------
__global__ void k_zero_cnt() {
    int i = blockIdx.x * blockDim.x + threadIdx.x;
    if (i <= N_NODES) g_cnt[i] = 0;
}
__global__ void k_count(const int* __restrict__ edges) {
    int e = blockIdx.x * blockDim.x + threadIdx.x;
    if (e < N_EDGES) atomicAdd(&g_cnt[edges[2 * e + 1]], 1);
}
__global__ void k_scan() {
    __shared__ int sh[1024];
    __shared__ int carry_s;
    int tid = threadIdx.x;
    if (tid == 0) { carry_s = 0; g_off[0] = 0; g_cur[0] = 0; }
    __syncthreads();
    for (int base = 0; base < N_NODES; base += 1024) {
        int i = base + tid;
        int v = (i < N_NODES) ? g_cnt[i] : 0;
        sh[tid] = v;
        __syncthreads();
        for (int d = 1; d < 1024; d <<= 1) {
            int t = (tid >= d) ? sh[tid - d] : 0;
            __syncthreads();
            sh[tid] += t;
            __syncthreads();
        }
        if (i < N_NODES) {
            int val = carry_s + sh[tid];
            g_off[i + 1] = val;
            if (i + 1 < N_NODES) g_cur[i + 1] = val;
        }
        __syncthreads();
        if (tid == 0) carry_s += sh[1023];
        __syncthreads();
    }
}
__global__ void k_scatter(const int* __restrict__ edges) {
    int e = blockIdx.x * blockDim.x + threadIdx.x;
    if (e < N_EDGES) {
        int dst = edges[2 * e + 1];
        int p = atomicAdd(&g_cur[dst], 1);
        g_csr[p] = edges[2 * e];
    }
}

// --------------- FP16 TC GEMM, BN=128 (warp tile 32x64), merged epilogue ------
#define BM 128
#define BN 128
#define BK 32
#define A_TILE_HALFS (BM * BK)
#define B_SUB_HALFS (BK * 64)
#define B_TILE_HALFS (2 * B_SUB_HALFS)

__device__ __forceinline__ void cph16(uint32_t s, const void* g, bool p) {
    asm volatile("cp.async.cg.shared.global [%0], [%1], 16, %2;" ::"r"(s), "l"(g), "r"(p ? 16 : 0));
}
__device__ __forceinline__ void cp_commit() { asm volatile("cp.async.commit_group;"); }
__device__ __forceinline__ void ldmA(uint32_t a[4], uint32_t addr) {
    asm volatile("ldmatrix.sync.aligned.m8n8.x4.shared.b16 {%0,%1,%2,%3}, [%4];"
                 : "=r"(a[0]), "=r"(a[1]), "=r"(a[2]), "=r"(a[3]) : "r"(addr));
}
__device__ __forceinline__ void ldmBT(uint32_t b[4], uint32_t addr) {
    asm volatile("ldmatrix.sync.aligned.m8n8.x4.trans.shared.b16 {%0,%1,%2,%3}, [%4];"
                 : "=r"(b[0]), "=r"(b[1]), "=r"(b[2]), "=r"(b[3]) : "r"(addr));
}
__device__ __forceinline__ void mma16816(float c[4], const uint32_t a[4], uint32_t b0, uint32_t b1) {
    asm volatile("mma.sync.aligned.m16n8k16.row.col.f32.f16.f16.f32 "
                 "{%0,%1,%2,%3}, {%4,%5,%6,%7}, {%8,%9}, {%0,%1,%2,%3};"
                 : "+f"(c[0]), "+f"(c[1]), "+f"(c[2]), "+f"(c[3])
                 : "r"(a[0]), "r"(a[1]), "r"(a[2]), "r"(a[3]), "r"(b0), "r"(b1));
}

// L=1: [0,512) hh fp16, [512,1024) res16 fp16, [1024,1032) esd fp32  (Np=1152)
// L=2: [0,512) hh fp16, [512,520) esd fp32                            (Np=640)
// L=3: [0,726) hh fp16, [768,889) res3 fp32, [896,908) esd fp32       (Np=1024)
template <int L, int K>
__global__ __launch_bounds__(256) void k_gemm_h(const __half* __restrict__ A,
                                                const __half* __restrict__ B,
                                                __half* __restrict__ hhO,
                                                void* __restrict__ resO,
                                                float* __restrict__ esdO,
                                                int M, int Np) {
    __shared__ __align__(16) __half As[2][A_TILE_HALFS];
    __shared__ __align__(16) __half Bs[2][B_TILE_HALFS];
    const int tid = threadIdx.x, lane = tid & 31, wid = tid >> 5;
    const int wm = wid & 3, wn = wid >> 2;
    const int g = lane >> 2, c = lane & 3;
    const int mBase = blockIdx.y * BM, nBase = blockIdx.x * BN;
    const uint32_t sA = (uint32_t)__cvta_generic_to_shared(&As[0][0]);
    const uint32_t sB = (uint32_t)__cvta_generic_to_shared(&Bs[0][0]);

    float acc[2][8][4];
    #pragma unroll
    for (int mt = 0; mt < 2; mt++)
        #pragma unroll
        for (int nt = 0; nt < 8; nt++)
            #pragma unroll
            for (int i = 0; i < 4; i++) acc[mt][nt][i] = 0.f;

    const int ar = tid >> 2, ac = tid & 3;
    const int br = tid >> 3, bc = tid & 7;
    const int asw1 = ac ^ ((ar >> 1) & 3);
    const int asw2 = ac ^ (((ar + 64) >> 1) & 3);
    const int bsw  = bc ^ (br & 7);

    auto loadTile = [&](int k0, int buf) {
        uint32_t aB = sA + (uint32_t)(buf * A_TILE_HALFS * 2);
        int gm0 = mBase + ar, gm1 = mBase + ar + 64;
        cph16(aB + (uint32_t)(ar * 64 + asw1 * 16),
              A + (size_t)gm0 * K + k0 + ac * 8, gm0 < M);
        cph16(aB + (uint32_t)((ar + 64) * 64 + asw2 * 16),
              A + (size_t)gm1 * K + k0 + ac * 8, gm1 < M);
        uint32_t bB = sB + (uint32_t)(buf * B_TILE_HALFS * 2);
        #pragma unroll
        for (int sub = 0; sub < 2; sub++) {
            cph16(bB + (uint32_t)(sub * B_SUB_HALFS * 2 + br * 128 + bsw * 16),
                  B + (size_t)(k0 + br) * Np + nBase + sub * 64 + bc * 8, true);
        }
    };

    uint32_t aoff[2][2], boff[4][2];
    #pragma unroll
    for (int mt = 0; mt < 2; mt++)
        #pragma unroll
        for (int kk = 0; kk < 2; kk++) {
            int row = wm * 32 + mt * 16 + (lane & 15);
            int ch = kk * 2 + (lane >> 4);
            int sw = ch ^ ((row >> 1) & 3);
            aoff[mt][kk] = (uint32_t)(row * 64 + sw * 16);
        }
    #pragma unroll
    for (int ng = 0; ng < 4; ng++)
        #pragma unroll
        for (int kk = 0; kk < 2; kk++) {
            int row = kk * 16 + (lane & 15);
            int ch = ng * 2 + (lane >> 4);
            int sw = ch ^ (row & 7);
            boff[ng][kk] = (uint32_t)(wn * B_SUB_HALFS * 2 + row * 128 + sw * 16);
        }

    constexpr int ntiles = K / BK;
    loadTile(0, 0);
    cp_commit();

    #pragma unroll
    for (int t = 0; t < ntiles; t++) {
        int buf = t & 1;
        if (t + 1 < ntiles) {
            loadTile((t + 1) * BK, (t + 1) & 1);
            cp_commit();
            asm volatile("cp.async.wait_group 1;");
        } else {
            asm volatile("cp.async.wait_group 0;");
        }
        __syncthreads();

        uint32_t aB = sA + (uint32_t)(buf * A_TILE_HALFS * 2);
        uint32_t bB = sB + (uint32_t)(buf * B_TILE_HALFS * 2);
        #pragma unroll
        for (int kk = 0; kk < 2; kk++) {
            uint32_t a0[4], a1[4], bf[4][4];
            ldmA(a0, aB + aoff[0][kk]);
            ldmA(a1, aB + aoff[1][kk]);
            #pragma unroll
            for (int ng = 0; ng < 4; ng++) ldmBT(bf[ng], bB + boff[ng][kk]);
            #pragma unroll
            for (int ng = 0; ng < 4; ng++) {
                mma16816(acc[0][2 * ng],     a0, bf[ng][0], bf[ng][1]);
                mma16816(acc[0][2 * ng + 1], a0, bf[ng][2], bf[ng][3]);
                mma16816(acc[1][2 * ng],     a1, bf[ng][0], bf[ng][1]);
                mma16816(acc[1][2 * ng + 1], a1, bf[ng][2], bf[ng][3]);
            }
        }
        __syncthreads();
    }

    // region-routed epilogue
    auto storeRow = [&](int r, int col, float va, float vb) {
        if (L == 1) {
            if (col < 512) {
                ((__half2*)hhO)[((size_t)r * 512 + col) >> 1] = __floats2half2_rn(va, vb);
            } else if (col < 1024) {
                ((__half2*)resO)[((size_t)r * 512 + (col - 512)) >> 1] = __floats2half2_rn(va, vb);
            } else if (col < 1032) {
                esdO[(size_t)r * 8 + (col - 1024)]     = va;
                esdO[(size_t)r * 8 + (col - 1024) + 1] = vb;
            }
        } else if (L == 2) {
            if (col < 512) {
                ((__half2*)hhO)[((size_t)r * 512 + col) >> 1] = __floats2half2_rn(va, vb);
            } else if (col < 520) {
                esdO[(size_t)r * 8 + (col - 512)]     = va;
                esdO[(size_t)r * 8 + (col - 512) + 1] = vb;
            }
        } else {
            if (col < 726) {
                ((__half2*)hhO)[((size_t)r * 726 + col) >> 1] = __floats2half2_rn(va, vb);
            } else if (col >= 768 && col < 890) {
                int cc = col - 768;
                float* rf = (float*)resO;
                if (cc < 121)     rf[(size_t)r * 121 + cc]     = va;
                if (cc + 1 < 121) rf[(size_t)r * 121 + cc + 1] = vb;
            } else if (col >= 896 && col < 908) {
                esdO[(size_t)r * 12 + (col - 896)]     = va;
                esdO[(size_t)r * 12 + (col - 896) + 1] = vb;
            }
        }
    };
    #pragma unroll
    for (int mt = 0; mt < 2; mt++) {
        int r0 = mBase + wm * 32 + mt * 16 + g;
        int r1 = r0 + 8;
        #pragma unroll
        for (int nt = 0; nt < 8; nt++) {
            int col = nBase + wn * 64 + nt * 8 + 2 * c;
            if (r0 < M) storeRow(r0, col, acc[mt][nt][0], acc[mt][nt][1]);
            if (r1 < M) storeRow(r1, col, acc[mt][nt][2], acc[mt][nt][3]);
        }
    }
}

// --------------- softmax weights: all heads, one gather (R8-proven) ------------
#define WCAP 512
template <int H>
__global__ __launch_bounds__(128) void k_weights(const float* __restrict__ esd) {
    __shared__ int   sidx[WCAP];
    __shared__ float se[H][WCAP];
    __shared__ float red[4 * H];
    __shared__ float s_mh[H], s_inv[H];
    int n = blockIdx.x;
    int tid = threadIdx.x;
    int lane = tid & 31, wid = tid >> 5;
    int beg = g_off[n], deg = g_off[n + 1] - beg;
    if (deg == 0) return;
    const float4* e4 = (const float4*)esd;

    float edv[H];
    #pragma unroll
    for (int q = 0; q < H / 2; q++) {
        float4 d = e4[n * (H / 2) + q];
        edv[2 * q] = d.y; edv[2 * q + 1] = d.w;
    }

    if (deg <= WCAP) {
        float mx[H];
        #pragma unroll
        for (int hh = 0; hh < H; hh++) mx[hh] = -1e30f;
        for (int i = tid; i < deg; i += 128) {
            int s = g_csr[beg + i];
            sidx[i] = s;
            float ev[H];
            #pragma unroll
            for (int q = 0; q < H / 2; q++) {
                float4 v = e4[s * (H / 2) + q];
                ev[2 * q] = v.x; ev[2 * q + 1] = v.z;
            }
            #pragma unroll
            for (int hh = 0; hh < H; hh++) {
                float e = ev[hh] + edv[hh];
                e = (e > 0.f) ? e : 0.2f * e;
                se[hh][i] = e;
                mx[hh] = fmaxf(mx[hh], e);
            }
        }
        #pragma unroll
        for (int hh = 0; hh < H; hh++) {
            #pragma unroll
            for (int o = 16; o > 0; o >>= 1)
                mx[hh] = fmaxf(mx[hh], __shfl_xor_sync(0xffffffffu, mx[hh], o));
        }
        if (lane == 0)
            #pragma unroll
            for (int hh = 0; hh < H; hh++) red[wid * H + hh] = mx[hh];
        __syncthreads();
        if (tid < H)
            s_mh[tid] = fmaxf(fmaxf(red[tid], red[H + tid]),
                              fmaxf(red[2 * H + tid], red[3 * H + tid]));
        __syncthreads();
        float m[H], sum[H];
        #pragma unroll
        for (int hh = 0; hh < H; hh++) { m[hh] = s_mh[hh]; sum[hh] = 0.f; }
        for (int i = tid; i < deg; i += 128) {
            #pragma unroll
            for (int hh = 0; hh < H; hh++) {
                float p = expf(se[hh][i] - m[hh]);
                se[hh][i] = p;
                sum[hh] += p;
            }
        }
        #pragma unroll
        for (int hh = 0; hh < H; hh++) {
            #pragma unroll
            for (int o = 16; o > 0; o >>= 1)
                sum[hh] += __shfl_xor_sync(0xffffffffu, sum[hh], o);
        }
        if (lane == 0)
            #pragma unroll
            for (int hh = 0; hh < H; hh++) red[wid * H + hh] = sum[hh];
        __syncthreads();
        if (tid < H)
            s_inv[tid] = 1.0f / fmaxf(red[tid] + red[H + tid] + red[2 * H + tid] + red[3 * H + tid], 1e-9f);
        __syncthreads();
        float inv[H];
        #pragma unroll
        for (int hh = 0; hh < H; hh++) inv[hh] = s_inv[hh];
        for (int i = tid; i < deg; i += 128) {
            if (H == 4) {
                float4 w;
                w.x = se[0][i] * inv[0]; w.y = se[1][i] * inv[1];
                w.z = se[2][i] * inv[2]; w.w = se[3][i] * inv[3];
                *(float4*)(&g_w[(size_t)(beg + i) * 4]) = w;
            } else {
                #pragma unroll
                for (int q = 0; q < H / 2; q++) {
                    float2 w;
                    w.x = se[2 * q][i] * inv[2 * q];
                    w.y = se[2 * q + 1][i] * inv[2 * q + 1];
                    *(float2*)(&g_w[(size_t)(beg + i) * H + 2 * q]) = w;
                }
            }
        }
    } else {
        __shared__ float warpred[4];
        __shared__ float s_m1, s_i1;
        for (int hh = 0; hh < H; hh++) {
            float ev = edv[hh];
            float mxx = -1e30f;
            for (int i = tid; i < deg; i += 128) {
                float e = esd[g_csr[beg + i] * 2 * H + 2 * hh] + ev;
                e = (e > 0.f) ? e : 0.2f * e;
                mxx = fmaxf(mxx, e);
            }
            #pragma unroll
            for (int o = 16; o > 0; o >>= 1) mxx = fmaxf(mxx, __shfl_xor_sync(0xffffffffu, mxx, o));
            if (lane == 0) warpred[wid] = mxx;
            __syncthreads();
            if (tid == 0)
                s_m1 = fmaxf(fmaxf(warpred[0], warpred[1]), fmaxf(warpred[2], warpred[3]));
            __syncthreads();
            float m = s_m1;
            float sum = 0.f;
            for (int i = tid; i < deg; i += 128) {
                float e = esd[g_csr[beg + i] * 2 * H + 2 * hh] + ev;
                e = (e > 0.f) ? e : 0.2f * e;
                sum += expf(e - m);
            }
            #pragma unroll
            for (int o = 16; o > 0; o >>= 1) sum += __shfl_xor_sync(0xffffffffu, sum, o);
            if (lane == 0) warpred[wid] = sum;
            __syncthreads();
            if (tid == 0)
                s_i1 = 1.0f / fmaxf(warpred[0] + warpred[1] + warpred[2] + warpred[3], 1e-9f);
            __syncthreads();
            float inv = s_i1;
            for (int i = tid; i < deg; i += 128) {
                float e = esd[g_csr[beg + i] * 2 * H + 2 * hh] + ev;
                e = (e > 0.f) ? e : 0.2f * e;
                g_w[(size_t)(beg + i) * H + hh] = expf(e - m) * inv;
            }
            __syncthreads();
        }
    }
}

// ---------------- weighted aggregation, layers 1/2 (fp16 residual) ------------
__global__ __launch_bounds__(256) void k_agg512(const __half* __restrict__ h,
                                                const __half* __restrict__ res,
                                                __half* __restrict__ out16) {
    int n = blockIdx.x;
    int tid = threadIdx.x;
    int hh = tid >> 6;
    int beg = g_off[n], deg = g_off[n + 1] - beg;
    const __half2* h2 = (const __half2*)h;
    float ax = 0.f, ay = 0.f;
    int i = 0;
    for (; i + 4 <= deg; i += 4) {
        int s0 = g_csr[beg + i],     s1 = g_csr[beg + i + 1];
        int s2 = g_csr[beg + i + 2], s3 = g_csr[beg + i + 3];
        float w0 = g_w[(size_t)(beg + i) * 4 + hh];
        float w1 = g_w[(size_t)(beg + i + 1) * 4 + hh];
        float w2 = g_w[(size_t)(beg + i + 2) * 4 + hh];
        float w3 = g_w[(size_t)(beg + i + 3) * 4 + hh];
        float2 v0 = __half22float2(__ldg(h2 + (size_t)s0 * 256 + tid));
        float2 v1 = __half22float2(__ldg(h2 + (size_t)s1 * 256 + tid));
        float2 v2 = __half22float2(__ldg(h2 + (size_t)s2 * 256 + tid));
        float2 v3 = __half22float2(__ldg(h2 + (size_t)s3 * 256 + tid));
        ax += w0 * v0.x + w1 * v1.x + w2 * v2.x + w3 * v3.x;
        ay += w0 * v0.y + w1 * v1.y + w2 * v2.y + w3 * v3.y;
    }
    for (; i < deg; i++) {
        int s = g_csr[beg + i];
        float w = g_w[(size_t)(beg + i) * 4 + hh];
        float2 v = __half22float2(__ldg(h2 + (size_t)s * 256 + tid));
        ax += w * v.x;
        ay += w * v.y;
    }
    float2 r = __half22float2(((const __half2*)res)[(size_t)n * 256 + tid]);
    float vx = ax + r.x, vy = ay + r.y;
    vx = (vx > 0.f) ? vx : (expf(vx) - 1.f);
    vy = (vy > 0.f) ? vy : (expf(vy) - 1.f);
    ((__half2*)out16)[(size_t)n * 256 + tid] = __floats2half2_rn(vx, vy);
}

// ---------------- weighted aggregation, layer 3 (fp32 res, final out) ---------
__global__ __launch_bounds__(384) void k_agg726(const __half* __restrict__ h,
                                                const float* __restrict__ res,
                                                float* __restrict__ out) {
    __shared__ float sh[726];
    int n = blockIdx.x;
    int tid = threadIdx.x;
    int beg = g_off[n], deg = g_off[n + 1] - beg;
    const __half2* h2 = (const __half2*)h;
    if (tid < 363) {
        int hA = (2 * tid) / 121;
        int hB = (2 * tid + 1) / 121;
        float ax = 0.f, ay = 0.f;
        int i = 0;
        for (; i + 4 <= deg; i += 4) {
            int s0 = g_csr[beg + i],     s1 = g_csr[beg + i + 1];
            int s2 = g_csr[beg + i + 2], s3 = g_csr[beg + i + 3];
            const float* wb0 = &g_w[(size_t)(beg + i) * 6];
            const float* wb1 = &g_w[(size_t)(beg + i + 1) * 6];
            const float* wb2 = &g_w[(size_t)(beg + i + 2) * 6];
            const float* wb3 = &g_w[(size_t)(beg + i + 3) * 6];
            float2 v0 = __half22float2(__ldg(h2 + (size_t)s0 * 363 + tid));
            float2 v1 = __half22float2(__ldg(h2 + (size_t)s1 * 363 + tid));
            float2 v2 = __half22float2(__ldg(h2 + (size_t)s2 * 363 + tid));
            float2 v3 = __half22float2(__ldg(h2 + (size_t)s3 * 363 + tid));
            ax += wb0[hA] * v0.x + wb1[hA] * v1.x + wb2[hA] * v2.x + wb3[hA] * v3.x;
            ay += wb0[hB] * v0.y + wb1[hB] * v1.y + wb2[hB] * v2.y + wb3[hB] * v3.y;
        }
        for (; i < deg; i++) {
            int s = g_csr[beg + i];
            const float* wb = &g_w[(size_t)(beg + i) * 6];
            float2 v = __half22float2(__ldg(h2 + (size_t)s * 363 + tid));
            ax += wb[hA] * v.x;
            ay += wb[hB] * v.y;
        }
        sh[2 * tid]     = ax;
        sh[2 * tid + 1] = ay;
    }
    __syncthreads();
    if (tid < 121) {
        float s = 0.f;
        #pragma unroll
        for (int hh = 0; hh < 6; hh++) s += sh[tid + hh * 121];
        out[(size_t)n * 121 + tid] = s * (1.f / 6.f) + res[(size_t)n * 121 + tid];
    }
}

// ------------------------------- launcher ------------------------------------
extern "C" void kernel_launch(void* const* d_in, const int* in_sizes, int n_in,
                              void* d_out, int out_size) {
    const float* x    = (const float*)d_in[0];
    const int*   edges= (const int*)d_in[1];
    const float* W1   = (const float*)d_in[2];
    const float* a1s  = (const float*)d_in[3];
    const float* a1d  = (const float*)d_in[4];
    const float* R1   = (const float*)d_in[5];
    const float* W2   = (const float*)d_in[6];
    const float* a2s  = (const float*)d_in[7];
    const float* a2d  = (const float*)d_in[8];
    const float* W3   = (const float*)d_in[9];
    const float* a3s  = (const float*)d_in[10];
    const float* a3d  = (const float*)d_in[11];
    const float* R3   = (const float*)d_in[12];
    float* out = (float*)d_out;

    __half *hh, *x16, *b16, *a216, *bw1, *bw2, *bw3, *res16;
    float *res3, *esd;
    cudaGetSymbolAddress((void**)&hh,    g_hh);
    cudaGetSymbolAddress((void**)&res16, g_res16);
    cudaGetSymbolAddress((void**)&res3,  g_res3);
    cudaGetSymbolAddress((void**)&x16,   g_x16);
    cudaGetSymbolAddress((void**)&b16,   g_b16);
    cudaGetSymbolAddress((void**)&a216,  g_a216);
    cudaGetSymbolAddress((void**)&bw1,   g_bw1);
    cudaGetSymbolAddress((void**)&bw2,   g_bw2);
    cudaGetSymbolAddress((void**)&bw3,   g_bw3);
    cudaGetSymbolAddress((void**)&esd,   g_esd);

    const int gy = (N_NODES + BM - 1) / BM;   // 391

    k_cvt<<<(int)((CVT_TOTAL + 255) / 256), 256>>>(x, W1, R1, W2, W3, R3);
    k_combine<<<(COMBINE_TOTAL + 255) / 256, 256>>>(W1, a1s, a1d, W2, a2s, a2d, W3, a3s, a3d);
    k_zero_cnt<<<(N_NODES + 256) / 256, 256>>>();
    // ---- layer 1 merged GEMM: [W1|R1|ws1], Np=1152  (profiled slot, index 3)
    k_gemm_h<1, 128><<<dim3(1152 / BN, gy), 256>>>(x16, bw1, hh, res16, esd, N_NODES, 1152);
    k_count<<<(N_EDGES + 255) / 256, 256>>>(edges);
    k_scan<<<1, 1024>>>();
    k_scatter<<<(N_EDGES + 255) / 256, 256>>>(edges);

    k_weights<4><<<N_NODES, 128>>>(esd);
    k_agg512<<<N_NODES, 256>>>(hh, res16, b16);

    // ---- layer 2 merged GEMM: [W2|ws2], Np=640; residual read from b16
    k_gemm_h<2, 512><<<dim3(640 / BN, gy), 256>>>(b16, bw2, hh, nullptr, esd, N_NODES, 640);
    k_weights<4><<<N_NODES, 128>>>(esd);
    k_agg512<<<N_NODES, 256>>>(hh, b16, a216);

    // ---- layer 3 merged GEMM: [W3|R3|ws3], Np=1024
    k_gemm_h<3, 512><<<dim3(1024 / BN, gy), 256>>>(a216, bw3, hh, res3, esd, N_NODES, 1024);
    k_weights<6><<<N_NODES, 128>>>(esd);
    k_agg726<<<N_NODES, 384>>>(hh, res3, out);
}

// round 16
// speedup vs baseline: 1.5279x; 1.0000x over previous
#include <cuda_runtime.h>
#include <cuda_fp16.h>
#include <math.h>
#include <stdint.h>

#define N_NODES 50000
#define N_EDGES 800000

// ---------------- scratch (device globals; no dynamic allocation) -------------
__device__ __half g_hh[(size_t)N_NODES * 726];
__device__ __half g_res16[(size_t)N_NODES * 512];  // layer-1 residual, fp16
__device__ float  g_res3[(size_t)N_NODES * 128];   // layer-3 residual, fp32 (121 used)
__device__ __half g_x16 [(size_t)N_NODES * 128];
__device__ __half g_b16 [(size_t)N_NODES * 512];   // x1 fp16 (GEMM A + layer-2 residual)
__device__ __half g_a216[(size_t)N_NODES * 512];
__device__ float  g_esd[(size_t)N_NODES * 12];
__device__ __half g_bw1[128 * 1152];   // [W1 | R1 | ws1 | pad]
__device__ __half g_bw2[512 * 640];    // [W2 | ws2 | pad]
__device__ __half g_bw3[512 * 1024];   // [W3pad | R3pad | ws3 | pad]
__device__ float  g_w[(size_t)N_EDGES * 6];
__device__ int   g_cnt[N_NODES + 1];
__device__ int   g_off[N_NODES + 1];
__device__ int   g_cur[N_NODES];
__device__ int   g_csr[N_EDGES];

// ------------------------- fp32 -> fp16 conversion + B arenas -----------------
__global__ void k_cvt(const float* __restrict__ x,  const float* __restrict__ W1,
                      const float* __restrict__ R1, const float* __restrict__ W2,
                      const float* __restrict__ W3, const float* __restrict__ R3) {
    size_t i = (size_t)blockIdx.x * blockDim.x + threadIdx.x;
    const size_t NX = (size_t)N_NODES * 128;
    if (i < NX) { g_x16[i] = __float2half_rn(x[i]); return; }
    size_t j = i - NX;
    if (j < 128 * 1152) {
        int k = (int)(j / 1152), col = (int)(j % 1152);
        float v = 0.f;
        if (col < 512) v = W1[k * 512 + col];
        else if (col < 1024) v = R1[k * 512 + (col - 512)];
        g_bw1[j] = __float2half_rn(v);
        return;
    }
    j -= 128 * 1152;
    if (j < 512 * 640) {
        int k = (int)(j / 640), col = (int)(j % 640);
        float v = (col < 512) ? W2[k * 512 + col] : 0.f;
        g_bw2[j] = __float2half_rn(v);
        return;
    }
    j -= 512 * 640;
    if (j < 512 * 1024) {
        int k = (int)(j >> 10), col = (int)(j & 1023);
        float v = 0.f;
        if (col < 726) v = W3[k * 726 + col];
        else if (col >= 768 && col < 889) v = R3[k * 121 + (col - 768)];
        g_bw3[j] = __float2half_rn(v);
    }
}
#define CVT_TOTAL ((size_t)N_NODES * 128 + 128 * 1152 + 512 * 640 + 512 * 1024)

// --------------- compose attention vectors into arena ws columns --------------
__global__ void k_combine(const float* __restrict__ W1, const float* __restrict__ a1s,
                          const float* __restrict__ a1d,
                          const float* __restrict__ W2, const float* __restrict__ a2s,
                          const float* __restrict__ a2d,
                          const float* __restrict__ W3, const float* __restrict__ a3s,
                          const float* __restrict__ a3d) {
    int gid = blockIdx.x * blockDim.x + threadIdx.x;
    if (gid < 128 * 64) {
        int k = gid >> 6, col = gid & 63, h = col >> 1;
        float v = 0.f;
        if (col < 8) {
            const float* a = (col & 1) ? a1d : a1s;
            for (int u = 0; u < 128; u++) v += W1[k * 512 + h * 128 + u] * a[h * 128 + u];
        }
        g_bw1[k * 1152 + 1024 + col] = __float2half_rn(v);
        return;
    }
    gid -= 128 * 64;
    if (gid < 512 * 64) {
        int k = gid >> 6, col = gid & 63, h = col >> 1;
        float v = 0.f;
        if (col < 8) {
            const float* a = (col & 1) ? a2d : a2s;
            for (int u = 0; u < 128; u++) v += W2[k * 512 + h * 128 + u] * a[h * 128 + u];
        }
        g_bw2[k * 640 + 512 + col] = __float2half_rn(v);
        return;
    }
    gid -= 512 * 64;
    if (gid < 512 * 64) {
        int k = gid >> 6, col = gid & 63, h = col >> 1;
        float v = 0.f;
        if (col < 12) {
            const float* a = (col & 1) ? a3d : a3s;
            for (int u = 0; u < 121; u++) v += W3[k * 726 + h * 121 + u] * a[h * 121 + u];
        }
        g_bw3[k * 1024 + 896 + col] = __float2half_rn(v);
    }
}
#define COMBINE_TOTAL (128 * 64 + 512 * 64 + 512 * 64)

// ------------------------------- CSR build -----------------------------------
__global__ void k_zero_cnt() {
    int i = blockIdx.x * blockDim.x + threadIdx.x;
    if (i <= N_NODES) g_cnt[i] = 0;
}
__global__ void k_count(const int* __restrict__ edges) {
    int e = blockIdx.x * blockDim.x + threadIdx.x;
    if (e < N_EDGES) atomicAdd(&g_cnt[edges[2 * e + 1]], 1);
}
__global__ void k_scan() {
    __shared__ int sh[1024];
    __shared__ int carry_s;
    int tid = threadIdx.x;
    if (tid == 0) { carry_s = 0; g_off[0] = 0; g_cur[0] = 0; }
    __syncthreads();
    for (int base = 0; base < N_NODES; base += 1024) {
        int i = base + tid;
        int v = (i < N_NODES) ? g_cnt[i] : 0;
        sh[tid] = v;
        __syncthreads();
        for (int d = 1; d < 1024; d <<= 1) {
            int t = (tid >= d) ? sh[tid - d] : 0;
            __syncthreads();
            sh[tid] += t;
            __syncthreads();
        }
        if (i < N_NODES) {
            int val = carry_s + sh[tid];
            g_off[i + 1] = val;
            if (i + 1 < N_NODES) g_cur[i + 1] = val;
        }
        __syncthreads();
        if (tid == 0) carry_s += sh[1023];
        __syncthreads();
    }
}
__global__ void k_scatter(const int* __restrict__ edges) {
    int e = blockIdx.x * blockDim.x + threadIdx.x;
    if (e < N_EDGES) {
        int dst = edges[2 * e + 1];
        int p = atomicAdd(&g_cur[dst], 1);
        g_csr[p] = edges[2 * e];
    }
}

// ------- FP16 TC GEMM, BN=128, 3-stage cp.async pipeline, one sync/tile -------
#define BM 128
#define BN 128
#define BK 32
#define NSTAGE 3
#define A_TILE_HALFS (BM * BK)
#define B_SUB_HALFS (BK * 64)
#define B_TILE_HALFS (2 * B_SUB_HALFS)

__device__ __forceinline__ void cph16(uint32_t s, const void* g, bool p) {
    asm volatile("cp.async.cg.shared.global [%0], [%1], 16, %2;" ::"r"(s), "l"(g), "r"(p ? 16 : 0));
}
__device__ __forceinline__ void cp_commit() { asm volatile("cp.async.commit_group;"); }
__device__ __forceinline__ void ldmA(uint32_t a[4], uint32_t addr) {
    asm volatile("ldmatrix.sync.aligned.m8n8.x4.shared.b16 {%0,%1,%2,%3}, [%4];"
                 : "=r"(a[0]), "=r"(a[1]), "=r"(a[2]), "=r"(a[3]) : "r"(addr));
}
__device__ __forceinline__ void ldmBT(uint32_t b[4], uint32_t addr) {
    asm volatile("ldmatrix.sync.aligned.m8n8.x4.trans.shared.b16 {%0,%1,%2,%3}, [%4];"
                 : "=r"(b[0]), "=r"(b[1]), "=r"(b[2]), "=r"(b[3]) : "r"(addr));
}
__device__ __forceinline__ void mma16816(float c[4], const uint32_t a[4], uint32_t b0, uint32_t b1) {
    asm volatile("mma.sync.aligned.m16n8k16.row.col.f32.f16.f16.f32 "
                 "{%0,%1,%2,%3}, {%4,%5,%6,%7}, {%8,%9}, {%0,%1,%2,%3};"
                 : "+f"(c[0]), "+f"(c[1]), "+f"(c[2]), "+f"(c[3])
                 : "r"(a[0]), "r"(a[1]), "r"(a[2]), "r"(a[3]), "r"(b0), "r"(b1));
}

// L=1: [0,512) hh fp16, [512,1024) res16 fp16, [1024,1032) esd fp32  (Np=1152)
// L=2: [0,512) hh fp16, [512,520) esd fp32                            (Np=640)
// L=3: [0,726) hh fp16, [768,889) res3 fp32, [896,908) esd fp32       (Np=1024)
template <int L, int K>
__global__ __launch_bounds__(256) void k_gemm_h(const __half* __restrict__ A,
                                                const __half* __restrict__ B,
                                                __half* __restrict__ hhO,
                                                void* __restrict__ resO,
                                                float* __restrict__ esdO,
                                                int M, int Np) {
    __shared__ __align__(16) __half As[NSTAGE][A_TILE_HALFS];
    __shared__ __align__(16) __half Bs[NSTAGE][B_TILE_HALFS];
    const int tid = threadIdx.x, lane = tid & 31, wid = tid >> 5;
    const int wm = wid & 3, wn = wid >> 2;
    const int g = lane >> 2, c = lane & 3;
    const int mBase = blockIdx.y * BM, nBase = blockIdx.x * BN;
    const uint32_t sA = (uint32_t)__cvta_generic_to_shared(&As[0][0]);
    const uint32_t sB = (uint32_t)__cvta_generic_to_shared(&Bs[0][0]);

    float acc[2][8][4];
    #pragma unroll
    for (int mt = 0; mt < 2; mt++)
        #pragma unroll
        for (int nt = 0; nt < 8; nt++)
            #pragma unroll
            for (int i = 0; i < 4; i++) acc[mt][nt][i] = 0.f;

    const int ar = tid >> 2, ac = tid & 3;
    const int br = tid >> 3, bc = tid & 7;
    const int asw1 = ac ^ ((ar >> 1) & 3);
    const int asw2 = ac ^ (((ar + 64) >> 1) & 3);
    const int bsw  = bc ^ (br & 7);

    auto loadTile = [&](int k0, int buf) {
        uint32_t aB = sA + (uint32_t)(buf * A_TILE_HALFS * 2);
        int gm0 = mBase + ar, gm1 = mBase + ar + 64;
        cph16(aB + (uint32_t)(ar * 64 + asw1 * 16),
              A + (size_t)gm0 * K + k0 + ac * 8, gm0 < M);
        cph16(aB + (uint32_t)((ar + 64) * 64 + asw2 * 16),
              A + (size_t)gm1 * K + k0 + ac * 8, gm1 < M);
        uint32_t bB = sB + (uint32_t)(buf * B_TILE_HALFS * 2);
        #pragma unroll
        for (int sub = 0; sub < 2; sub++) {
            cph16(bB + (uint32_t)(sub * B_SUB_HALFS * 2 + br * 128 + bsw * 16),
                  B + (size_t)(k0 + br) * Np + nBase + sub * 64 + bc * 8, true);
        }
    };

    uint32_t aoff[2][2], boff[4][2];
    #pragma unroll
    for (int mt = 0; mt < 2; mt++)
        #pragma unroll
        for (int kk = 0; kk < 2; kk++) {
            int row = wm * 32 + mt * 16 + (lane & 15);
            int ch = kk * 2 + (lane >> 4);
            int sw = ch ^ ((row >> 1) & 3);
            aoff[mt][kk] = (uint32_t)(row * 64 + sw * 16);
        }
    #pragma unroll
    for (int ng = 0; ng < 4; ng++)
        #pragma unroll
        for (int kk = 0; kk < 2; kk++) {
            int row = kk * 16 + (lane & 15);
            int ch = ng * 2 + (lane >> 4);
            int sw = ch ^ (row & 7);
            boff[ng][kk] = (uint32_t)(wn * B_SUB_HALFS * 2 + row * 128 + sw * 16);
        }

    constexpr int ntiles = K / BK;
    // prologue: 2 tiles in flight
    loadTile(0, 0);
    cp_commit();
    if (ntiles > 1) { loadTile(BK, 1); cp_commit(); }

    #pragma unroll
    for (int t = 0; t < ntiles; t++) {
        if (t + 1 < ntiles) asm volatile("cp.async.wait_group 1;");
        else                asm volatile("cp.async.wait_group 0;");
        __syncthreads();   // tile t visible to all; all warps done with tile t-1

        const int buf = t % NSTAGE;
        uint32_t aB = sA + (uint32_t)(buf * A_TILE_HALFS * 2);
        uint32_t bB = sB + (uint32_t)(buf * B_TILE_HALFS * 2);
        #pragma unroll
        for (int kk = 0; kk < 2; kk++) {
            uint32_t a0[4], a1[4], bf[4][4];
            ldmA(a0, aB + aoff[0][kk]);
            ldmA(a1, aB + aoff[1][kk]);
            #pragma unroll
            for (int ng = 0; ng < 4; ng++) ldmBT(bf[ng], bB + boff[ng][kk]);
            #pragma unroll
            for (int ng = 0; ng < 4; ng++) {
                mma16816(acc[0][2 * ng],     a0, bf[ng][0], bf[ng][1]);
                mma16816(acc[0][2 * ng + 1], a0, bf[ng][2], bf[ng][3]);
                mma16816(acc[1][2 * ng],     a1, bf[ng][0], bf[ng][1]);
                mma16816(acc[1][2 * ng + 1], a1, bf[ng][2], bf[ng][3]);
            }
        }
        // refill stage (t+2) -> buffer (t+2)%3, which held tile t-1 (consumed)
        if (t + 2 < ntiles) { loadTile((t + 2) * BK, (t + 2) % NSTAGE); cp_commit(); }
    }

    // region-routed epilogue
    auto storeRow = [&](int r, int col, float va, float vb) {
        if (L == 1) {
            if (col < 512) {
                ((__half2*)hhO)[((size_t)r * 512 + col) >> 1] = __floats2half2_rn(va, vb);
            } else if (col < 1024) {
                ((__half2*)resO)[((size_t)r * 512 + (col - 512)) >> 1] = __floats2half2_rn(va, vb);
            } else if (col < 1032) {
                esdO[(size_t)r * 8 + (col - 1024)]     = va;
                esdO[(size_t)r * 8 + (col - 1024) + 1] = vb;
            }
        } else if (L == 2) {
            if (col < 512) {
                ((__half2*)hhO)[((size_t)r * 512 + col) >> 1] = __floats2half2_rn(va, vb);
            } else if (col < 520) {
                esdO[(size_t)r * 8 + (col - 512)]     = va;
                esdO[(size_t)r * 8 + (col - 512) + 1] = vb;
            }
        } else {
            if (col < 726) {
                ((__half2*)hhO)[((size_t)r * 726 + col) >> 1] = __floats2half2_rn(va, vb);
            } else if (col >= 768 && col < 890) {
                int cc = col - 768;
                float* rf = (float*)resO;
                if (cc < 121)     rf[(size_t)r * 121 + cc]     = va;
                if (cc + 1 < 121) rf[(size_t)r * 121 + cc + 1] = vb;
            } else if (col >= 896 && col < 908) {
                esdO[(size_t)r * 12 + (col - 896)]     = va;
                esdO[(size_t)r * 12 + (col - 896) + 1] = vb;
            }
        }
    };
    #pragma unroll
    for (int mt = 0; mt < 2; mt++) {
        int r0 = mBase + wm * 32 + mt * 16 + g;
        int r1 = r0 + 8;
        #pragma unroll
        for (int nt = 0; nt < 8; nt++) {
            int col = nBase + wn * 64 + nt * 8 + 2 * c;
            if (r0 < M) storeRow(r0, col, acc[mt][nt][0], acc[mt][nt][1]);
            if (r1 < M) storeRow(r1, col, acc[mt][nt][2], acc[mt][nt][3]);
        }
    }
}

// --------------- softmax weights: all heads, one gather (R8-proven) ------------
#define WCAP 512
template <int H>
__global__ __launch_bounds__(128) void k_weights(const float* __restrict__ esd) {
    __shared__ int   sidx[WCAP];
    __shared__ float se[H][WCAP];
    __shared__ float red[4 * H];
    __shared__ float s_mh[H], s_inv[H];
    int n = blockIdx.x;
    int tid = threadIdx.x;
    int lane = tid & 31, wid = tid >> 5;
    int beg = g_off[n], deg = g_off[n + 1] - beg;
    if (deg == 0) return;
    const float4* e4 = (const float4*)esd;

    float edv[H];
    #pragma unroll
    for (int q = 0; q < H / 2; q++) {
        float4 d = e4[n * (H / 2) + q];
        edv[2 * q] = d.y; edv[2 * q + 1] = d.w;
    }

    if (deg <= WCAP) {
        float mx[H];
        #pragma unroll
        for (int hh = 0; hh < H; hh++) mx[hh] = -1e30f;
        for (int i = tid; i < deg; i += 128) {
            int s = g_csr[beg + i];
            sidx[i] = s;
            float ev[H];
            #pragma unroll
            for (int q = 0; q < H / 2; q++) {
                float4 v = e4[s * (H / 2) + q];
                ev[2 * q] = v.x; ev[2 * q + 1] = v.z;
            }
            #pragma unroll
            for (int hh = 0; hh < H; hh++) {
                float e = ev[hh] + edv[hh];
                e = (e > 0.f) ? e : 0.2f * e;
                se[hh][i] = e;
                mx[hh] = fmaxf(mx[hh], e);
            }
        }
        #pragma unroll
        for (int hh = 0; hh < H; hh++) {
            #pragma unroll
            for (int o = 16; o > 0; o >>= 1)
                mx[hh] = fmaxf(mx[hh], __shfl_xor_sync(0xffffffffu, mx[hh], o));
        }
        if (lane == 0)
            #pragma unroll
            for (int hh = 0; hh < H; hh++) red[wid * H + hh] = mx[hh];
        __syncthreads();
        if (tid < H)
            s_mh[tid] = fmaxf(fmaxf(red[tid], red[H + tid]),
                              fmaxf(red[2 * H + tid], red[3 * H + tid]));
        __syncthreads();
        float m[H], sum[H];
        #pragma unroll
        for (int hh = 0; hh < H; hh++) { m[hh] = s_mh[hh]; sum[hh] = 0.f; }
        for (int i = tid; i < deg; i += 128) {
            #pragma unroll
            for (int hh = 0; hh < H; hh++) {
                float p = expf(se[hh][i] - m[hh]);
                se[hh][i] = p;
                sum[hh] += p;
            }
        }
        #pragma unroll
        for (int hh = 0; hh < H; hh++) {
            #pragma unroll
            for (int o = 16; o > 0; o >>= 1)
                sum[hh] += __shfl_xor_sync(0xffffffffu, sum[hh], o);
        }
        if (lane == 0)
            #pragma unroll
            for (int hh = 0; hh < H; hh++) red[wid * H + hh] = sum[hh];
        __syncthreads();
        if (tid < H)
            s_inv[tid] = 1.0f / fmaxf(red[tid] + red[H + tid] + red[2 * H + tid] + red[3 * H + tid], 1e-9f);
        __syncthreads();
        float inv[H];
        #pragma unroll
        for (int hh = 0; hh < H; hh++) inv[hh] = s_inv[hh];
        for (int i = tid; i < deg; i += 128) {
            if (H == 4) {
                float4 w;
                w.x = se[0][i] * inv[0]; w.y = se[1][i] * inv[1];
                w.z = se[2][i] * inv[2]; w.w = se[3][i] * inv[3];
                *(float4*)(&g_w[(size_t)(beg + i) * 4]) = w;
            } else {
                #pragma unroll
                for (int q = 0; q < H / 2; q++) {
                    float2 w;
                    w.x = se[2 * q][i] * inv[2 * q];
                    w.y = se[2 * q + 1][i] * inv[2 * q + 1];
                    *(float2*)(&g_w[(size_t)(beg + i) * H + 2 * q]) = w;
                }
            }
        }
    } else {
        __shared__ float warpred[4];
        __shared__ float s_m1, s_i1;
        for (int hh = 0; hh < H; hh++) {
            float ev = edv[hh];
            float mxx = -1e30f;
            for (int i = tid; i < deg; i += 128) {
                float e = esd[g_csr[beg + i] * 2 * H + 2 * hh] + ev;
                e = (e > 0.f) ? e : 0.2f * e;
                mxx = fmaxf(mxx, e);
            }
            #pragma unroll
            for (int o = 16; o > 0; o >>= 1) mxx = fmaxf(mxx, __shfl_xor_sync(0xffffffffu, mxx, o));
            if (lane == 0) warpred[wid] = mxx;
            __syncthreads();
            if (tid == 0)
                s_m1 = fmaxf(fmaxf(warpred[0], warpred[1]), fmaxf(warpred[2], warpred[3]));
            __syncthreads();
            float m = s_m1;
            float sum = 0.f;
            for (int i = tid; i < deg; i += 128) {
                float e = esd[g_csr[beg + i] * 2 * H + 2 * hh] + ev;
                e = (e > 0.f) ? e : 0.2f * e;
                sum += expf(e - m);
            }
            #pragma unroll
            for (int o = 16; o > 0; o >>= 1) sum += __shfl_xor_sync(0xffffffffu, sum, o);
            if (lane == 0) warpred[wid] = sum;
            __syncthreads();
            if (tid == 0)
                s_i1 = 1.0f / fmaxf(warpred[0] + warpred[1] + warpred[2] + warpred[3], 1e-9f);
            __syncthreads();
            float inv = s_i1;
            for (int i = tid; i < deg; i += 128) {
                float e = esd[g_csr[beg + i] * 2 * H + 2 * hh] + ev;
                e = (e > 0.f) ? e : 0.2f * e;
                g_w[(size_t)(beg + i) * H + hh] = expf(e - m) * inv;
            }
            __syncthreads();
        }
    }
}

// ---------------- weighted aggregation, layers 1/2 (fp16 residual) ------------
__global__ __launch_bounds__(256) void k_agg512(const __half* __restrict__ h,
                                                const __half* __restrict__ res,
                                                __half* __restrict__ out16) {
    int n = blockIdx.x;
    int tid = threadIdx.x;
    int hh = tid >> 6;
    int beg = g_off[n], deg = g_off[n + 1] - beg;
    const __half2* h2 = (const __half2*)h;
    float ax = 0.f, ay = 0.f;
    int i = 0;
    for (; i + 4 <= deg; i += 4) {
        int s0 = g_csr[beg + i],     s1 = g_csr[beg + i + 1];
        int s2 = g_csr[beg + i + 2], s3 = g_csr[beg + i + 3];
        float w0 = g_w[(size_t)(beg + i) * 4 + hh];
        float w1 = g_w[(size_t)(beg + i + 1) * 4 + hh];
        float w2 = g_w[(size_t)(beg + i + 2) * 4 + hh];
        float w3 = g_w[(size_t)(beg + i + 3) * 4 + hh];
        float2 v0 = __half22float2(__ldg(h2 + (size_t)s0 * 256 + tid));
        float2 v1 = __half22float2(__ldg(h2 + (size_t)s1 * 256 + tid));
        float2 v2 = __half22float2(__ldg(h2 + (size_t)s2 * 256 + tid));
        float2 v3 = __half22float2(__ldg(h2 + (size_t)s3 * 256 + tid));
        ax += w0 * v0.x + w1 * v1.x + w2 * v2.x + w3 * v3.x;
        ay += w0 * v0.y + w1 * v1.y + w2 * v2.y + w3 * v3.y;
    }
    for (; i < deg; i++) {
        int s = g_csr[beg + i];
        float w = g_w[(size_t)(beg + i) * 4 + hh];
        float2 v = __half22float2(__ldg(h2 + (size_t)s * 256 + tid));
        ax += w * v.x;
        ay += w * v.y;
    }
    float2 r = __half22float2(((const __half2*)res)[(size_t)n * 256 + tid]);
    float vx = ax + r.x, vy = ay + r.y;
    vx = (vx > 0.f) ? vx : (expf(vx) - 1.f);
    vy = (vy > 0.f) ? vy : (expf(vy) - 1.f);
    ((__half2*)out16)[(size_t)n * 256 + tid] = __floats2half2_rn(vx, vy);
}

// ---------------- weighted aggregation, layer 3 (fp32 res, final out) ---------
__global__ __launch_bounds__(384) void k_agg726(const __half* __restrict__ h,
                                                const float* __restrict__ res,
                                                float* __restrict__ out) {
    __shared__ float sh[726];
    int n = blockIdx.x;
    int tid = threadIdx.x;
    int beg = g_off[n], deg = g_off[n + 1] - beg;
    const __half2* h2 = (const __half2*)h;
    if (tid < 363) {
        int hA = (2 * tid) / 121;
        int hB = (2 * tid + 1) / 121;
        float ax = 0.f, ay = 0.f;
        int i = 0;
        for (; i + 4 <= deg; i += 4) {
            int s0 = g_csr[beg + i],     s1 = g_csr[beg + i + 1];
            int s2 = g_csr[beg + i + 2], s3 = g_csr[beg + i + 3];
            const float* wb0 = &g_w[(size_t)(beg + i) * 6];
            const float* wb1 = &g_w[(size_t)(beg + i + 1) * 6];
            const float* wb2 = &g_w[(size_t)(beg + i + 2) * 6];
            const float* wb3 = &g_w[(size_t)(beg + i + 3) * 6];
            float2 v0 = __half22float2(__ldg(h2 + (size_t)s0 * 363 + tid));
            float2 v1 = __half22float2(__ldg(h2 + (size_t)s1 * 363 + tid));
            float2 v2 = __half22float2(__ldg(h2 + (size_t)s2 * 363 + tid));
            float2 v3 = __half22float2(__ldg(h2 + (size_t)s3 * 363 + tid));
            ax += wb0[hA] * v0.x + wb1[hA] * v1.x + wb2[hA] * v2.x + wb3[hA] * v3.x;
            ay += wb0[hB] * v0.y + wb1[hB] * v1.y + wb2[hB] * v2.y + wb3[hB] * v3.y;
        }
        for (; i < deg; i++) {
            int s = g_csr[beg + i];
            const float* wb = &g_w[(size_t)(beg + i) * 6];
            float2 v = __half22float2(__ldg(h2 + (size_t)s * 363 + tid));
            ax += wb[hA] * v.x;
            ay += wb[hB] * v.y;
        }
        sh[2 * tid]     = ax;
        sh[2 * tid + 1] = ay;
    }
    __syncthreads();
    if (tid < 121) {
        float s = 0.f;
        #pragma unroll
        for (int hh = 0; hh < 6; hh++) s += sh[tid + hh * 121];
        out[(size_t)n * 121 + tid] = s * (1.f / 6.f) + res[(size_t)n * 121 + tid];
    }
}

// ------------------------------- launcher ------------------------------------
extern "C" void kernel_launch(void* const* d_in, const int* in_sizes, int n_in,
                              void* d_out, int out_size) {
    const float* x    = (const float*)d_in[0];
    const int*   edges= (const int*)d_in[1];
    const float* W1   = (const float*)d_in[2];
    const float* a1s  = (const float*)d_in[3];
    const float* a1d  = (const float*)d_in[4];
    const float* R1   = (const float*)d_in[5];
    const float* W2   = (const float*)d_in[6];
    const float* a2s  = (const float*)d_in[7];
    const float* a2d  = (const float*)d_in[8];
    const float* W3   = (const float*)d_in[9];
    const float* a3s  = (const float*)d_in[10];
    const float* a3d  = (const float*)d_in[11];
    const float* R3   = (const float*)d_in[12];
    float* out = (float*)d_out;

    __half *hh, *x16, *b16, *a216, *bw1, *bw2, *bw3, *res16;
    float *res3, *esd;
    cudaGetSymbolAddress((void**)&hh,    g_hh);
    cudaGetSymbolAddress((void**)&res16, g_res16);
    cudaGetSymbolAddress((void**)&res3,  g_res3);
    cudaGetSymbolAddress((void**)&x16,   g_x16);
    cudaGetSymbolAddress((void**)&b16,   g_b16);
    cudaGetSymbolAddress((void**)&a216,  g_a216);
    cudaGetSymbolAddress((void**)&bw1,   g_bw1);
    cudaGetSymbolAddress((void**)&bw2,   g_bw2);
    cudaGetSymbolAddress((void**)&bw3,   g_bw3);
    cudaGetSymbolAddress((void**)&esd,   g_esd);

    const int gy = (N_NODES + BM - 1) / BM;   // 391

    k_cvt<<<(int)((CVT_TOTAL + 255) / 256), 256>>>(x, W1, R1, W2, W3, R3);
    k_combine<<<(COMBINE_TOTAL + 255) / 256, 256>>>(W1, a1s, a1d, W2, a2s, a2d, W3, a3s, a3d);
    k_zero_cnt<<<(N_NODES + 256) / 256, 256>>>();
    // ---- layer 1 merged GEMM: [W1|R1|ws1], Np=1152  (profiled slot, index 3)
    k_gemm_h<1, 128><<<dim3(1152 / BN, gy), 256>>>(x16, bw1, hh, res16, esd, N_NODES, 1152);
    k_count<<<(N_EDGES + 255) / 256, 256>>>(edges);
    k_scan<<<1, 1024>>>();
    k_scatter<<<(N_EDGES + 255) / 256, 256>>>(edges);

    k_weights<4><<<N_NODES, 128>>>(esd);
    k_agg512<<<N_NODES, 256>>>(hh, res16, b16);

    // ---- layer 2 merged GEMM: [W2|ws2], Np=640; residual read from b16
    k_gemm_h<2, 512><<<dim3(640 / BN, gy), 256>>>(b16, bw2, hh, nullptr, esd, N_NODES, 640);
    k_weights<4><<<N_NODES, 128>>>(esd);
    k_agg512<<<N_NODES, 256>>>(hh, b16, a216);

    // ---- layer 3 merged GEMM: [W3|R3|ws3], Np=1024
    k_gemm_h<3, 512><<<dim3(1024 / BN, gy), 256>>>(a216, bw3, hh, res3, esd, N_NODES, 1024);
    k_weights<6><<<N_NODES, 128>>>(esd);
    k_agg726<<<N_NODES, 384>>>(hh, res3, out);
}

// round 17
// speedup vs baseline: 1.7047x; 1.1157x over previous
#include <cuda_runtime.h>
#include <cuda_fp16.h>
#include <math.h>
#include <stdint.h>

#define N_NODES 50000
#define N_EDGES 800000

// ---------------- scratch (device globals; no dynamic allocation) -------------
__device__ __half g_hh[(size_t)N_NODES * 726];
__device__ __half g_res16[(size_t)N_NODES * 512];  // layer-1 residual, fp16
__device__ float  g_res3[(size_t)N_NODES * 128];   // layer-3 residual, fp32 (121 used)
__device__ __half g_x16 [(size_t)N_NODES * 128];
__device__ __half g_b16 [(size_t)N_NODES * 512];   // x1 fp16 (GEMM A + layer-2 residual)
__device__ __half g_a216[(size_t)N_NODES * 512];
__device__ float  g_esd[(size_t)N_NODES * 12];
__device__ __half g_bw1[128 * 1152];   // [W1 | R1 | ws1 | pad]
__device__ __half g_bw2[512 * 640];    // [W2 | ws2 | pad]
__device__ __half g_bw3[512 * 1024];   // [W3pad | R3pad | ws3 | pad]
__device__ float  g_w[(size_t)N_EDGES * 6];
__device__ int   g_cnt[N_NODES + 1];
__device__ int   g_off[N_NODES + 1];
__device__ int   g_cur[N_NODES];
__device__ int   g_csr[N_EDGES];

// ---------- fp32 -> fp16 conversion + B arenas (combine folded in) ------------
__global__ void k_cvt(const float* __restrict__ x,  const float* __restrict__ W1,
                      const float* __restrict__ R1, const float* __restrict__ W2,
                      const float* __restrict__ W3, const float* __restrict__ R3,
                      const float* __restrict__ a1s, const float* __restrict__ a1d,
                      const float* __restrict__ a2s, const float* __restrict__ a2d,
                      const float* __restrict__ a3s, const float* __restrict__ a3d) {
    size_t i = (size_t)blockIdx.x * blockDim.x + threadIdx.x;
    const size_t NX = (size_t)N_NODES * 128;
    if (i < NX) { g_x16[i] = __float2half_rn(x[i]); return; }
    size_t j = i - NX;
    if (j < 128 * 1152) {
        int k = (int)(j / 1152), col = (int)(j % 1152);
        float v = 0.f;
        if (col < 512) v = W1[k * 512 + col];
        else if (col < 1024) v = R1[k * 512 + (col - 512)];
        else if (col < 1032) {                      // ws1 columns (composed)
            int cc = col - 1024, h = cc >> 1;
            const float* a = (cc & 1) ? a1d : a1s;
            for (int u = 0; u < 128; u++) v += W1[k * 512 + h * 128 + u] * a[h * 128 + u];
        }
        g_bw1[j] = __float2half_rn(v);
        return;
    }
    j -= 128 * 1152;
    if (j < 512 * 640) {
        int k = (int)(j / 640), col = (int)(j % 640);
        float v = 0.f;
        if (col < 512) v = W2[k * 512 + col];
        else if (col < 520) {                       // ws2 columns
            int cc = col - 512, h = cc >> 1;
            const float* a = (cc & 1) ? a2d : a2s;
            for (int u = 0; u < 128; u++) v += W2[k * 512 + h * 128 + u] * a[h * 128 + u];
        }
        g_bw2[j] = __float2half_rn(v);
        return;
    }
    j -= 512 * 640;
    if (j < 512 * 1024) {
        int k = (int)(j >> 10), col = (int)(j & 1023);
        float v = 0.f;
        if (col < 726) v = W3[k * 726 + col];
        else if (col >= 768 && col < 889) v = R3[k * 121 + (col - 768)];
        else if (col >= 896 && col < 908) {         // ws3 columns
            int cc = col - 896, h = cc >> 1;
            const float* a = (cc & 1) ? a3d : a3s;
            for (int u = 0; u < 121; u++) v += W3[k * 726 + h * 121 + u] * a[h * 121 + u];
        }
        g_bw3[j] = __float2half_rn(v);
    }
}
#define CVT_TOTAL ((size_t)N_NODES * 128 + 128 * 1152 + 512 * 640 + 512 * 1024)

// ------------------------------- CSR build -----------------------------------
__global__ void k_zero_cnt() {
    int i = blockIdx.x * blockDim.x + threadIdx.x;
    if (i <= N_NODES) g_cnt[i] = 0;
}
__global__ void k_count(const int* __restrict__ edges) {
    int e = blockIdx.x * blockDim.x + threadIdx.x;
    if (e < N_EDGES) atomicAdd(&g_cnt[edges[2 * e + 1]], 1);
}
__global__ void k_scan() {
    __shared__ int sh[1024];
    __shared__ int carry_s;
    int tid = threadIdx.x;
    if (tid == 0) { carry_s = 0; g_off[0] = 0; g_cur[0] = 0; }
    __syncthreads();
    for (int base = 0; base < N_NODES; base += 1024) {
        int i = base + tid;
        int v = (i < N_NODES) ? g_cnt[i] : 0;
        sh[tid] = v;
        __syncthreads();
        for (int d = 1; d < 1024; d <<= 1) {
            int t = (tid >= d) ? sh[tid - d] : 0;
            __syncthreads();
            sh[tid] += t;
            __syncthreads();
        }
        if (i < N_NODES) {
            int val = carry_s + sh[tid];
            g_off[i + 1] = val;
            if (i + 1 < N_NODES) g_cur[i + 1] = val;
        }
        __syncthreads();
        if (tid == 0) carry_s += sh[1023];
        __syncthreads();
    }
}
__global__ void k_scatter(const int* __restrict__ edges) {
    int e = blockIdx.x * blockDim.x + threadIdx.x;
    if (e < N_EDGES) {
        int dst = edges[2 * e + 1];
        int p = atomicAdd(&g_cur[dst], 1);
        g_csr[p] = edges[2 * e];
    }
}

// ------- FP16 TC GEMM, BN=128, 3-stage cp.async pipeline (R16) ----------------
#define BM 128
#define BN 128
#define BK 32
#define NSTAGE 3
#define A_TILE_HALFS (BM * BK)
#define B_SUB_HALFS (BK * 64)
#define B_TILE_HALFS (2 * B_SUB_HALFS)

__device__ __forceinline__ void cph16(uint32_t s, const void* g, bool p) {
    asm volatile("cp.async.cg.shared.global [%0], [%1], 16, %2;" ::"r"(s), "l"(g), "r"(p ? 16 : 0));
}
__device__ __forceinline__ void cp_commit() { asm volatile("cp.async.commit_group;"); }
__device__ __forceinline__ void ldmA(uint32_t a[4], uint32_t addr) {
    asm volatile("ldmatrix.sync.aligned.m8n8.x4.shared.b16 {%0,%1,%2,%3}, [%4];"
                 : "=r"(a[0]), "=r"(a[1]), "=r"(a[2]), "=r"(a[3]) : "r"(addr));
}
__device__ __forceinline__ void ldmBT(uint32_t b[4], uint32_t addr) {
    asm volatile("ldmatrix.sync.aligned.m8n8.x4.trans.shared.b16 {%0,%1,%2,%3}, [%4];"
                 : "=r"(b[0]), "=r"(b[1]), "=r"(b[2]), "=r"(b[3]) : "r"(addr));
}
__device__ __forceinline__ void mma16816(float c[4], const uint32_t a[4], uint32_t b0, uint32_t b1) {
    asm volatile("mma.sync.aligned.m16n8k16.row.col.f32.f16.f16.f32 "
                 "{%0,%1,%2,%3}, {%4,%5,%6,%7}, {%8,%9}, {%0,%1,%2,%3};"
                 : "+f"(c[0]), "+f"(c[1]), "+f"(c[2]), "+f"(c[3])
                 : "r"(a[0]), "r"(a[1]), "r"(a[2]), "r"(a[3]), "r"(b0), "r"(b1));
}

template <int L, int K>
__global__ __launch_bounds__(256) void k_gemm_h(const __half* __restrict__ A,
                                                const __half* __restrict__ B,
                                                __half* __restrict__ hhO,
                                                void* __restrict__ resO,
                                                float* __restrict__ esdO,
                                                int M, int Np) {
    __shared__ __align__(16) __half As[NSTAGE][A_TILE_HALFS];
    __shared__ __align__(16) __half Bs[NSTAGE][B_TILE_HALFS];
    const int tid = threadIdx.x, lane = tid & 31, wid = tid >> 5;
    const int wm = wid & 3, wn = wid >> 2;
    const int g = lane >> 2, c = lane & 3;
    const int mBase = blockIdx.y * BM, nBase = blockIdx.x * BN;
    const uint32_t sA = (uint32_t)__cvta_generic_to_shared(&As[0][0]);
    const uint32_t sB = (uint32_t)__cvta_generic_to_shared(&Bs[0][0]);

    float acc[2][8][4];
    #pragma unroll
    for (int mt = 0; mt < 2; mt++)
        #pragma unroll
        for (int nt = 0; nt < 8; nt++)
            #pragma unroll
            for (int i = 0; i < 4; i++) acc[mt][nt][i] = 0.f;

    const int ar = tid >> 2, ac = tid & 3;
    const int br = tid >> 3, bc = tid & 7;
    const int asw1 = ac ^ ((ar >> 1) & 3);
    const int asw2 = ac ^ (((ar + 64) >> 1) & 3);
    const int bsw  = bc ^ (br & 7);

    auto loadTile = [&](int k0, int buf) {
        uint32_t aB = sA + (uint32_t)(buf * A_TILE_HALFS * 2);
        int gm0 = mBase + ar, gm1 = mBase + ar + 64;
        cph16(aB + (uint32_t)(ar * 64 + asw1 * 16),
              A + (size_t)gm0 * K + k0 + ac * 8, gm0 < M);
        cph16(aB + (uint32_t)((ar + 64) * 64 + asw2 * 16),
              A + (size_t)gm1 * K + k0 + ac * 8, gm1 < M);
        uint32_t bB = sB + (uint32_t)(buf * B_TILE_HALFS * 2);
        #pragma unroll
        for (int sub = 0; sub < 2; sub++) {
            cph16(bB + (uint32_t)(sub * B_SUB_HALFS * 2 + br * 128 + bsw * 16),
                  B + (size_t)(k0 + br) * Np + nBase + sub * 64 + bc * 8, true);
        }
    };

    uint32_t aoff[2][2], boff[4][2];
    #pragma unroll
    for (int mt = 0; mt < 2; mt++)
        #pragma unroll
        for (int kk = 0; kk < 2; kk++) {
            int row = wm * 32 + mt * 16 + (lane & 15);
            int ch = kk * 2 + (lane >> 4);
            int sw = ch ^ ((row >> 1) & 3);
            aoff[mt][kk] = (uint32_t)(row * 64 + sw * 16);
        }
    #pragma unroll
    for (int ng = 0; ng < 4; ng++)
        #pragma unroll
        for (int kk = 0; kk < 2; kk++) {
            int row = kk * 16 + (lane & 15);
            int ch = ng * 2 + (lane >> 4);
            int sw = ch ^ (row & 7);
            boff[ng][kk] = (uint32_t)(wn * B_SUB_HALFS * 2 + row * 128 + sw * 16);
        }

    constexpr int ntiles = K / BK;
    loadTile(0, 0);
    cp_commit();
    if (ntiles > 1) { loadTile(BK, 1); cp_commit(); }

    #pragma unroll
    for (int t = 0; t < ntiles; t++) {
        if (t + 1 < ntiles) asm volatile("cp.async.wait_group 1;");
        else                asm volatile("cp.async.wait_group 0;");
        __syncthreads();

        const int buf = t % NSTAGE;
        uint32_t aB = sA + (uint32_t)(buf * A_TILE_HALFS * 2);
        uint32_t bB = sB + (uint32_t)(buf * B_TILE_HALFS * 2);
        #pragma unroll
        for (int kk = 0; kk < 2; kk++) {
            uint32_t a0[4], a1[4], bf[4][4];
            ldmA(a0, aB + aoff[0][kk]);
            ldmA(a1, aB + aoff[1][kk]);
            #pragma unroll
            for (int ng = 0; ng < 4; ng++) ldmBT(bf[ng], bB + boff[ng][kk]);
            #pragma unroll
            for (int ng = 0; ng < 4; ng++) {
                mma16816(acc[0][2 * ng],     a0, bf[ng][0], bf[ng][1]);
                mma16816(acc[0][2 * ng + 1], a0, bf[ng][2], bf[ng][3]);
                mma16816(acc[1][2 * ng],     a1, bf[ng][0], bf[ng][1]);
                mma16816(acc[1][2 * ng + 1], a1, bf[ng][2], bf[ng][3]);
            }
        }
        if (t + 2 < ntiles) { loadTile((t + 2) * BK, (t + 2) % NSTAGE); cp_commit(); }
    }

    auto storeRow = [&](int r, int col, float va, float vb) {
        if (L == 1) {
            if (col < 512) {
                ((__half2*)hhO)[((size_t)r * 512 + col) >> 1] = __floats2half2_rn(va, vb);
            } else if (col < 1024) {
                ((__half2*)resO)[((size_t)r * 512 + (col - 512)) >> 1] = __floats2half2_rn(va, vb);
            } else if (col < 1032) {
                esdO[(size_t)r * 8 + (col - 1024)]     = va;
                esdO[(size_t)r * 8 + (col - 1024) + 1] = vb;
            }
        } else if (L == 2) {
            if (col < 512) {
                ((__half2*)hhO)[((size_t)r * 512 + col) >> 1] = __floats2half2_rn(va, vb);
            } else if (col < 520) {
                esdO[(size_t)r * 8 + (col - 512)]     = va;
                esdO[(size_t)r * 8 + (col - 512) + 1] = vb;
            }
        } else {
            if (col < 726) {
                ((__half2*)hhO)[((size_t)r * 726 + col) >> 1] = __floats2half2_rn(va, vb);
            } else if (col >= 768 && col < 890) {
                int cc = col - 768;
                float* rf = (float*)resO;
                if (cc < 121)     rf[(size_t)r * 121 + cc]     = va;
                if (cc + 1 < 121) rf[(size_t)r * 121 + cc + 1] = vb;
            } else if (col >= 896 && col < 908) {
                esdO[(size_t)r * 12 + (col - 896)]     = va;
                esdO[(size_t)r * 12 + (col - 896) + 1] = vb;
            }
        }
    };
    #pragma unroll
    for (int mt = 0; mt < 2; mt++) {
        int r0 = mBase + wm * 32 + mt * 16 + g;
        int r1 = r0 + 8;
        #pragma unroll
        for (int nt = 0; nt < 8; nt++) {
            int col = nBase + wn * 64 + nt * 8 + 2 * c;
            if (r0 < M) storeRow(r0, col, acc[mt][nt][0], acc[mt][nt][1]);
            if (r1 < M) storeRow(r1, col, acc[mt][nt][2], acc[mt][nt][3]);
        }
    }
}

// --------------- softmax weights: WARP per node, no block barriers ------------
__device__ __forceinline__ float wmax(float v) {
    #pragma unroll
    for (int o = 16; o > 0; o >>= 1) v = fmaxf(v, __shfl_xor_sync(0xffffffffu, v, o));
    return v;
}
__device__ __forceinline__ float wsum(float v) {
    #pragma unroll
    for (int o = 16; o > 0; o >>= 1) v += __shfl_xor_sync(0xffffffffu, v, o);
    return v;
}

template <int H>
__global__ __launch_bounds__(128) void k_weights(const float* __restrict__ esd) {
    int n = blockIdx.x * 4 + (threadIdx.x >> 5);
    if (n >= N_NODES) return;
    int lane = threadIdx.x & 31;
    int beg = g_off[n], deg = g_off[n + 1] - beg;
    if (deg == 0) return;
    const float4* e4 = (const float4*)esd;

    float edv[H];
    #pragma unroll
    for (int q = 0; q < H / 2; q++) {
        float4 d = e4[n * (H / 2) + q];
        edv[2 * q] = d.y; edv[2 * q + 1] = d.w;
    }

    if (deg <= 32) {
        // one edge per lane: single gather, single exp
        int s = (lane < deg) ? g_csr[beg + lane] : 0;
        float e[H];
        if (lane < deg) {
            #pragma unroll
            for (int q = 0; q < H / 2; q++) {
                float4 v = e4[s * (H / 2) + q];
                float e0 = v.x + edv[2 * q];
                float e1 = v.z + edv[2 * q + 1];
                e[2 * q]     = (e0 > 0.f) ? e0 : 0.2f * e0;
                e[2 * q + 1] = (e1 > 0.f) ? e1 : 0.2f * e1;
            }
        } else {
            #pragma unroll
            for (int hh = 0; hh < H; hh++) e[hh] = -1e30f;
        }
        float p[H], inv[H];
        #pragma unroll
        for (int hh = 0; hh < H; hh++) {
            float m = wmax(e[hh]);
            p[hh] = (lane < deg) ? expf(e[hh] - m) : 0.f;
            inv[hh] = 1.0f / fmaxf(wsum(p[hh]), 1e-9f);
        }
        if (lane < deg) {
            if (H == 4) {
                float4 w;
                w.x = p[0] * inv[0]; w.y = p[1] * inv[1];
                w.z = p[2] * inv[2]; w.w = p[3] * inv[3];
                *(float4*)(&g_w[(size_t)(beg + lane) * 4]) = w;
            } else {
                #pragma unroll
                for (int q = 0; q < H / 2; q++) {
                    float2 w;
                    w.x = p[2 * q] * inv[2 * q];
                    w.y = p[2 * q + 1] * inv[2 * q + 1];
                    *(float2*)(&g_w[(size_t)(beg + lane) * H + 2 * q]) = w;
                }
            }
        }
    } else {
        // rare: strided 3-pass with recompute
        float mx[H];
        #pragma unroll
        for (int hh = 0; hh < H; hh++) mx[hh] = -1e30f;
        for (int i = lane; i < deg; i += 32) {
            int s = g_csr[beg + i];
            #pragma unroll
            for (int q = 0; q < H / 2; q++) {
                float4 v = e4[s * (H / 2) + q];
                float e0 = v.x + edv[2 * q];
                float e1 = v.z + edv[2 * q + 1];
                e0 = (e0 > 0.f) ? e0 : 0.2f * e0;
                e1 = (e1 > 0.f) ? e1 : 0.2f * e1;
                mx[2 * q] = fmaxf(mx[2 * q], e0);
                mx[2 * q + 1] = fmaxf(mx[2 * q + 1], e1);
            }
        }
        float m[H], sum[H];
        #pragma unroll
        for (int hh = 0; hh < H; hh++) { m[hh] = wmax(mx[hh]); sum[hh] = 0.f; }
        for (int i = lane; i < deg; i += 32) {
            int s = g_csr[beg + i];
            #pragma unroll
            for (int q = 0; q < H / 2; q++) {
                float4 v = e4[s * (H / 2) + q];
                float e0 = v.x + edv[2 * q];
                float e1 = v.z + edv[2 * q + 1];
                e0 = (e0 > 0.f) ? e0 : 0.2f * e0;
                e1 = (e1 > 0.f) ? e1 : 0.2f * e1;
                sum[2 * q] += expf(e0 - m[2 * q]);
                sum[2 * q + 1] += expf(e1 - m[2 * q + 1]);
            }
        }
        float inv[H];
        #pragma unroll
        for (int hh = 0; hh < H; hh++) inv[hh] = 1.0f / fmaxf(wsum(sum[hh]), 1e-9f);
        for (int i = lane; i < deg; i += 32) {
            int s = g_csr[beg + i];
            #pragma unroll
            for (int q = 0; q < H / 2; q++) {
                float4 v = e4[s * (H / 2) + q];
                float e0 = v.x + edv[2 * q];
                float e1 = v.z + edv[2 * q + 1];
                e0 = (e0 > 0.f) ? e0 : 0.2f * e0;
                e1 = (e1 > 0.f) ? e1 : 0.2f * e1;
                float2 w;
                w.x = expf(e0 - m[2 * q]) * inv[2 * q];
                w.y = expf(e1 - m[2 * q + 1]) * inv[2 * q + 1];
                *(float2*)(&g_w[(size_t)(beg + i) * H + 2 * q]) = w;
            }
        }
    }
}

// ---------------- weighted aggregation, layers 1/2 (fp16 residual) ------------
__global__ __launch_bounds__(256) void k_agg512(const __half* __restrict__ h,
                                                const __half* __restrict__ res,
                                                __half* __restrict__ out16) {
    int n = blockIdx.x;
    int tid = threadIdx.x;
    int hh = tid >> 6;
    int beg = g_off[n], deg = g_off[n + 1] - beg;
    const __half2* h2 = (const __half2*)h;
    float ax = 0.f, ay = 0.f;
    int i = 0;
    for (; i + 4 <= deg; i += 4) {
        int s0 = g_csr[beg + i],     s1 = g_csr[beg + i + 1];
        int s2 = g_csr[beg + i + 2], s3 = g_csr[beg + i + 3];
        float w0 = g_w[(size_t)(beg + i) * 4 + hh];
        float w1 = g_w[(size_t)(beg + i + 1) * 4 + hh];
        float w2 = g_w[(size_t)(beg + i + 2) * 4 + hh];
        float w3 = g_w[(size_t)(beg + i + 3) * 4 + hh];
        float2 v0 = __half22float2(__ldg(h2 + (size_t)s0 * 256 + tid));
        float2 v1 = __half22float2(__ldg(h2 + (size_t)s1 * 256 + tid));
        float2 v2 = __half22float2(__ldg(h2 + (size_t)s2 * 256 + tid));
        float2 v3 = __half22float2(__ldg(h2 + (size_t)s3 * 256 + tid));
        ax += w0 * v0.x + w1 * v1.x + w2 * v2.x + w3 * v3.x;
        ay += w0 * v0.y + w1 * v1.y + w2 * v2.y + w3 * v3.y;
    }
    for (; i < deg; i++) {
        int s = g_csr[beg + i];
        float w = g_w[(size_t)(beg + i) * 4 + hh];
        float2 v = __half22float2(__ldg(h2 + (size_t)s * 256 + tid));
        ax += w * v.x;
        ay += w * v.y;
    }
    float2 r = __half22float2(((const __half2*)res)[(size_t)n * 256 + tid]);
    float vx = ax + r.x, vy = ay + r.y;
    vx = (vx > 0.f) ? vx : (expf(vx) - 1.f);
    vy = (vy > 0.f) ? vy : (expf(vy) - 1.f);
    ((__half2*)out16)[(size_t)n * 256 + tid] = __floats2half2_rn(vx, vy);
}

// ---------------- weighted aggregation, layer 3 (fp32 res, final out) ---------
__global__ __launch_bounds__(384) void k_agg726(const __half* __restrict__ h,
                                                const float* __restrict__ res,
                                                float* __restrict__ out) {
    __shared__ float sh[726];
    int n = blockIdx.x;
    int tid = threadIdx.x;
    int beg = g_off[n], deg = g_off[n + 1] - beg;
    const __half2* h2 = (const __half2*)h;
    if (tid < 363) {
        int hA = (2 * tid) / 121;
        int hB = (2 * tid + 1) / 121;
        float ax = 0.f, ay = 0.f;
        int i = 0;
        for (; i + 4 <= deg; i += 4) {
            int s0 = g_csr[beg + i],     s1 = g_csr[beg + i + 1];
            int s2 = g_csr[beg + i + 2], s3 = g_csr[beg + i + 3];
            const float* wb0 = &g_w[(size_t)(beg + i) * 6];
            const float* wb1 = &g_w[(size_t)(beg + i + 1) * 6];
            const float* wb2 = &g_w[(size_t)(beg + i + 2) * 6];
            const float* wb3 = &g_w[(size_t)(beg + i + 3) * 6];
            float2 v0 = __half22float2(__ldg(h2 + (size_t)s0 * 363 + tid));
            float2 v1 = __half22float2(__ldg(h2 + (size_t)s1 * 363 + tid));
            float2 v2 = __half22float2(__ldg(h2 + (size_t)s2 * 363 + tid));
            float2 v3 = __half22float2(__ldg(h2 + (size_t)s3 * 363 + tid));
            ax += wb0[hA] * v0.x + wb1[hA] * v1.x + wb2[hA] * v2.x + wb3[hA] * v3.x;
            ay += wb0[hB] * v0.y + wb1[hB] * v1.y + wb2[hB] * v2.y + wb3[hB] * v3.y;
        }
        for (; i < deg; i++) {
            int s = g_csr[beg + i];
            const float* wb = &g_w[(size_t)(beg + i) * 6];
            float2 v = __half22float2(__ldg(h2 + (size_t)s * 363 + tid));
            ax += wb[hA] * v.x;
            ay += wb[hB] * v.y;
        }
        sh[2 * tid]     = ax;
        sh[2 * tid + 1] = ay;
    }
    __syncthreads();
    if (tid < 121) {
        float s = 0.f;
        #pragma unroll
        for (int hh = 0; hh < 6; hh++) s += sh[tid + hh * 121];
        out[(size_t)n * 121 + tid] = s * (1.f / 6.f) + res[(size_t)n * 121 + tid];
    }
}

// ------------------------------- launcher ------------------------------------
extern "C" void kernel_launch(void* const* d_in, const int* in_sizes, int n_in,
                              void* d_out, int out_size) {
    const float* x    = (const float*)d_in[0];
    const int*   edges= (const int*)d_in[1];
    const float* W1   = (const float*)d_in[2];
    const float* a1s  = (const float*)d_in[3];
    const float* a1d  = (const float*)d_in[4];
    const float* R1   = (const float*)d_in[5];
    const float* W2   = (const float*)d_in[6];
    const float* a2s  = (const float*)d_in[7];
    const float* a2d  = (const float*)d_in[8];
    const float* W3   = (const float*)d_in[9];
    const float* a3s  = (const float*)d_in[10];
    const float* a3d  = (const float*)d_in[11];
    const float* R3   = (const float*)d_in[12];
    float* out = (float*)d_out;

    __half *hh, *x16, *b16, *a216, *bw1, *bw2, *bw3, *res16;
    float *res3, *esd;
    cudaGetSymbolAddress((void**)&hh,    g_hh);
    cudaGetSymbolAddress((void**)&res16, g_res16);
    cudaGetSymbolAddress((void**)&res3,  g_res3);
    cudaGetSymbolAddress((void**)&x16,   g_x16);
    cudaGetSymbolAddress((void**)&b16,   g_b16);
    cudaGetSymbolAddress((void**)&a216,  g_a216);
    cudaGetSymbolAddress((void**)&bw1,   g_bw1);
    cudaGetSymbolAddress((void**)&bw2,   g_bw2);
    cudaGetSymbolAddress((void**)&bw3,   g_bw3);
    cudaGetSymbolAddress((void**)&esd,   g_esd);

    const int gy = (N_NODES + BM - 1) / BM;   // 391

    k_cvt<<<(int)((CVT_TOTAL + 255) / 256), 256>>>(x, W1, R1, W2, W3, R3,
                                                   a1s, a1d, a2s, a2d, a3s, a3d);
    k_zero_cnt<<<(N_NODES + 256) / 256, 256>>>();
    k_count<<<(N_EDGES + 255) / 256, 256>>>(edges);
    // ---- layer 1 merged GEMM: [W1|R1|ws1], Np=1152  (profiled slot, index 3)
    k_gemm_h<1, 128><<<dim3(1152 / BN, gy), 256>>>(x16, bw1, hh, res16, esd, N_NODES, 1152);
    k_scan<<<1, 1024>>>();
    k_scatter<<<(N_EDGES + 255) / 256, 256>>>(edges);

    k_weights<4><<<(N_NODES + 3) / 4, 128>>>(esd);
    k_agg512<<<N_NODES, 256>>>(hh, res16, b16);

    // ---- layer 2 merged GEMM: [W2|ws2], Np=640; residual read from b16
    k_gemm_h<2, 512><<<dim3(640 / BN, gy), 256>>>(b16, bw2, hh, nullptr, esd, N_NODES, 640);
    k_weights<4><<<(N_NODES + 3) / 4, 128>>>(esd);
    k_agg512<<<N_NODES, 256>>>(hh, b16, a216);

    // ---- layer 3 merged GEMM: [W3|R3|ws3], Np=1024
    k_gemm_h<3, 512><<<dim3(1024 / BN, gy), 256>>>(a216, bw3, hh, res3, esd, N_NODES, 1024);
    k_weights<6><<<(N_NODES + 3) / 4, 128>>>(esd);
    k_agg726<<<N_NODES, 384>>>(hh, res3, out);
}